// round 8
// baseline (speedup 1.0000x reference)
#include <cuda_runtime.h>
#include <cuda_bf16.h>
#include <math.h>
#include <stdint.h>
#include <string.h>

#define BATCH 2
#define SEQ 2048
#define DMODEL 2048
#define NH 16
#define NKV 4
#define HD 128
#define BS (BATCH*SEQ)
#define KVD (NKV*HD)
#define NQKV (DMODEL + 2*KVD)     // 3072
#define LOG2E 1.4426950408889634f

// ---------------- scratch (__device__ globals; no allocs allowed) ----------
__device__ float g_qkv[(size_t)BS*NQKV];
__device__ float g_cos[SEQ*64];
__device__ float g_sin[SEQ*64];

__device__ __nv_bfloat16 g_xhi[(size_t)BS*DMODEL];
__device__ __nv_bfloat16 g_xlo[(size_t)BS*DMODEL];
__device__ __nv_bfloat16 g_yhi[(size_t)BS*DMODEL];
__device__ __nv_bfloat16 g_ylo[(size_t)BS*DMODEL];
__device__ __nv_bfloat16 g_qhi[(size_t)BS*DMODEL];
__device__ __nv_bfloat16 g_qlo[(size_t)BS*DMODEL];
__device__ __nv_bfloat16 g_khi[(size_t)BS*KVD];
__device__ __nv_bfloat16 g_klo[(size_t)BS*KVD];
__device__ __nv_bfloat16 g_vhi[(size_t)BS*KVD];
__device__ __nv_bfloat16 g_vlo[(size_t)BS*KVD];
__device__ __nv_bfloat16 g_wchi[(size_t)NQKV*DMODEL];   // [Wq;Wk;Wv]
__device__ __nv_bfloat16 g_wclo[(size_t)NQKV*DMODEL];
__device__ __nv_bfloat16 g_wphi[(size_t)DMODEL*DMODEL];
__device__ __nv_bfloat16 g_wplo[(size_t)DMODEL*DMODEL];

// ---------------- mma.sync helpers -----------------------------------------
__device__ __forceinline__ uint32_t smem_u32(const void* p) {
    uint32_t a;
    asm("{ .reg .u64 t; cvta.to.shared.u64 t, %1; cvt.u32.u64 %0, t; }" : "=r"(a) : "l"(p));
    return a;
}
__device__ __forceinline__ void ldsm_x4(uint32_t* r, uint32_t addr) {
    asm volatile("ldmatrix.sync.aligned.m8n8.x4.shared.b16 {%0,%1,%2,%3}, [%4];"
                 : "=r"(r[0]), "=r"(r[1]), "=r"(r[2]), "=r"(r[3]) : "r"(addr));
}
__device__ __forceinline__ void ldsm_x4_t(uint32_t* r, uint32_t addr) {
    asm volatile("ldmatrix.sync.aligned.m8n8.x4.trans.shared.b16 {%0,%1,%2,%3}, [%4];"
                 : "=r"(r[0]), "=r"(r[1]), "=r"(r[2]), "=r"(r[3]) : "r"(addr));
}
__device__ __forceinline__ void mma_bf16(float* d, const uint32_t* a, const uint32_t* b) {
    asm volatile("mma.sync.aligned.m16n8k16.row.col.f32.bf16.bf16.f32 "
                 "{%0,%1,%2,%3}, {%4,%5,%6,%7}, {%8,%9}, {%0,%1,%2,%3};"
                 : "+f"(d[0]), "+f"(d[1]), "+f"(d[2]), "+f"(d[3])
                 : "r"(a[0]), "r"(a[1]), "r"(a[2]), "r"(a[3]), "r"(b[0]), "r"(b[1]));
}
__device__ __forceinline__ uint32_t pack_bf16x2(float v0, float v1) {
    uint32_t r;
    asm("cvt.rn.bf16x2.f32 %0, %1, %2;" : "=r"(r) : "f"(v1), "f"(v0));
    return r;
}
#define CP_ASYNC16(s, g) \
    asm volatile("cp.async.cg.shared.global [%0], [%1], 16;" :: "r"(s), "l"(g))

// ---------------- fp32 -> bf16 hi/lo split ---------------------------------
__device__ __forceinline__ void split4(float4 v, __nv_bfloat162* hi, __nv_bfloat162* lo, size_t o2) {
    __nv_bfloat16 h0 = __float2bfloat16(v.x), h1 = __float2bfloat16(v.y);
    __nv_bfloat16 h2 = __float2bfloat16(v.z), h3 = __float2bfloat16(v.w);
    hi[o2 + 0] = __halves2bfloat162(h0, h1);
    hi[o2 + 1] = __halves2bfloat162(h2, h3);
    lo[o2 + 0] = __halves2bfloat162(__float2bfloat16(v.x - __bfloat162float(h0)),
                                    __float2bfloat16(v.y - __bfloat162float(h1)));
    lo[o2 + 1] = __halves2bfloat162(__float2bfloat16(v.z - __bfloat162float(h2)),
                                    __float2bfloat16(v.w - __bfloat162float(h3)));
}

__global__ __launch_bounds__(256) void split_kernel(const float4* __restrict__ src,
                                                    __nv_bfloat162* __restrict__ hi,
                                                    __nv_bfloat162* __restrict__ lo,
                                                    int n4) {
    int i = blockIdx.x * blockDim.x + threadIdx.x;
    if (i >= n4) return;
    split4(src[i], hi, lo, 2 * (size_t)i);
}

// fused split of ALL weights: Wq||Wk||Wv -> wc, Wproj -> wp
#define WQ4 (DMODEL*DMODEL/4)
#define WK4 (KVD*DMODEL/4)
#define WC4 (WQ4 + 2*WK4)
__global__ __launch_bounds__(256) void split_weights(const float4* __restrict__ wq,
                                                     const float4* __restrict__ wk,
                                                     const float4* __restrict__ wv,
                                                     const float4* __restrict__ wp,
                                                     __nv_bfloat162* __restrict__ chi,
                                                     __nv_bfloat162* __restrict__ clo,
                                                     __nv_bfloat162* __restrict__ phi,
                                                     __nv_bfloat162* __restrict__ plo) {
    int i = blockIdx.x * blockDim.x + threadIdx.x;
    if (i < WC4) {
        float4 v;
        if (i < WQ4) v = wq[i];
        else if (i < WQ4 + WK4) v = wk[i - WQ4];
        else v = wv[i - WQ4 - WK4];
        split4(v, chi, clo, 2 * (size_t)i);
    } else if (i < WC4 + WQ4) {
        int j = i - WC4;
        split4(wp[j], phi, plo, 2 * (size_t)j);
    }
}

// strided split: rows x cols out of a wider row of rstride
__global__ __launch_bounds__(256) void split_strided(const float* __restrict__ src,
                                                     __nv_bfloat162* __restrict__ hi,
                                                     __nv_bfloat162* __restrict__ lo,
                                                     int rows, int cols, int rstride, int coloff) {
    int i = blockIdx.x * blockDim.x + threadIdx.x;
    int c4 = cols / 4;
    if (i >= rows * c4) return;
    int row = i / c4, cc = (i % c4) * 4;
    float4 v = *(const float4*)(src + (size_t)row * rstride + coloff + cc);
    split4(v, hi, lo, ((size_t)row * cols + cc) / 2);
}

// ---------------- bf16x3 mma.sync GEMM: C[M,N] = A[M,K] @ B[N,K]^T ---------
#define GSTAGES 3
#define GBK 32
#define GTILEB (128*GBK*2)
#define GSTAGEB (4*GTILEB)
#define GSMEM_TOTAL (GSTAGES*GSTAGEB)

__device__ __forceinline__ uint32_t sw_off(int row, int chunk) {
    return (uint32_t)(row * 64 + ((chunk ^ (row & 3)) << 4));
}
__device__ __forceinline__ void g_load_stage(const __nv_bfloat16* Ahi, const __nv_bfloat16* Alo,
                                             const __nv_bfloat16* Bhi, const __nv_bfloat16* Blo,
                                             int bm, int bn, int K, int kc,
                                             uint32_t tb, int tid) {
    size_t kcol = (size_t)kc * GBK;
#pragma unroll
    for (int j = 0; j < 2; j++) {
        int idx = tid + j * 256;
        int row = idx >> 2, c = idx & 3;
        uint32_t so = sw_off(row, c);
        size_t ga = (size_t)(bm + row) * K + kcol + c * 8;
        size_t gb = (size_t)(bn + row) * K + kcol + c * 8;
        CP_ASYNC16(tb + so, Ahi + ga);
        CP_ASYNC16(tb + GTILEB + so, Alo + ga);
        CP_ASYNC16(tb + 2 * GTILEB + so, Bhi + gb);
        CP_ASYNC16(tb + 3 * GTILEB + so, Blo + gb);
    }
}

__global__ __launch_bounds__(256, 2) void gemm_bf16x3(
    const __nv_bfloat16* __restrict__ Ahi, const __nv_bfloat16* __restrict__ Alo,
    const __nv_bfloat16* __restrict__ Bhi, const __nv_bfloat16* __restrict__ Blo,
    float* __restrict__ C, int M, int N, int K) {
    extern __shared__ char smem[];
    uint32_t sb = smem_u32(smem);
    int tid = threadIdx.x, wid = tid >> 5, lane = tid & 31;
    int bm = blockIdx.y * 128, bn = blockIdx.x * 128;
    int wm = (wid >> 2) * 64;
    int wn = (wid & 3) * 32;
    const int NK = K / GBK;

    float acc[4][4][4];
#pragma unroll
    for (int a = 0; a < 4; a++)
#pragma unroll
        for (int b = 0; b < 4; b++)
#pragma unroll
            for (int c = 0; c < 4; c++) acc[a][b][c] = 0.f;

#pragma unroll
    for (int s = 0; s < GSTAGES - 1; s++) {
        g_load_stage(Ahi, Alo, Bhi, Blo, bm, bn, K, s, sb + s * GSTAGEB, tid);
        asm volatile("cp.async.commit_group;" ::: "memory");
    }

    for (int kc = 0; kc < NK; kc++) {
        asm volatile("cp.async.wait_group %0;" :: "n"(GSTAGES - 2) : "memory");
        __syncthreads();
        uint32_t tb = sb + (kc % GSTAGES) * GSTAGEB;

#pragma unroll
        for (int ks = 0; ks < 2; ks++) {
            uint32_t ah[4][4], al[4][4], bh[2][4], bl[2][4];
#pragma unroll
            for (int mt = 0; mt < 4; mt++) {
                int row = wm + mt * 16 + (lane & 15);
                uint32_t off = sw_off(row, ks * 2 + (lane >> 4));
                ldsm_x4(ah[mt], tb + off);
                ldsm_x4(al[mt], tb + GTILEB + off);
            }
#pragma unroll
            for (int pr = 0; pr < 2; pr++) {
                int row = wn + pr * 16 + (lane & 7) + ((lane >> 4) << 3);
                uint32_t off = sw_off(row, ks * 2 + ((lane >> 3) & 1));
                ldsm_x4(bh[pr], tb + 2 * GTILEB + off);
                ldsm_x4(bl[pr], tb + 3 * GTILEB + off);
            }
#pragma unroll
            for (int mt = 0; mt < 4; mt++)
#pragma unroll
                for (int nt = 0; nt < 4; nt++) {
                    const uint32_t* bhp = &bh[nt >> 1][(nt & 1) * 2];
                    const uint32_t* blp = &bl[nt >> 1][(nt & 1) * 2];
                    mma_bf16(acc[mt][nt], ah[mt], bhp);
                    mma_bf16(acc[mt][nt], ah[mt], blp);
                    mma_bf16(acc[mt][nt], al[mt], bhp);
                }
        }
        __syncthreads();
        if (kc + GSTAGES - 1 < NK) {
            int pst = (kc + GSTAGES - 1) % GSTAGES;
            g_load_stage(Ahi, Alo, Bhi, Blo, bm, bn, K, kc + GSTAGES - 1, sb + pst * GSTAGEB, tid);
        }
        asm volatile("cp.async.commit_group;" ::: "memory");
    }

#pragma unroll
    for (int mt = 0; mt < 4; mt++) {
        int row0 = bm + wm + mt * 16 + (lane >> 2);
#pragma unroll
        for (int nt = 0; nt < 4; nt++) {
            int col = bn + wn + nt * 8 + (lane & 3) * 2;
            *(float2*)(C + (size_t)row0 * N + col) = make_float2(acc[mt][nt][0], acc[mt][nt][1]);
            *(float2*)(C + (size_t)(row0 + 8) * N + col) = make_float2(acc[mt][nt][2], acc[mt][nt][3]);
        }
    }
}

// ---------------- RoPE table ------------------------------------------------
__global__ void rope_table_kernel() {
    int i = threadIdx.x;
    int t = blockIdx.x;
    double inv = exp(-((double)(2 * i) / 128.0) * log(10000.0));
    double a = (double)t * inv;
    g_cos[t * 64 + i] = (float)cos(a);
    g_sin[t * 64 + i] = (float)sin(a);
}

// ---------------- fused RMSNorm + RoPE (Q and K in one launch) --------------
__global__ __launch_bounds__(128) void rmsnorm_rope_qk(const float* __restrict__ src,
                                                       __nv_bfloat16* __restrict__ qhi,
                                                       __nv_bfloat16* __restrict__ qlo,
                                                       __nv_bfloat16* __restrict__ khi,
                                                       __nv_bfloat16* __restrict__ klo,
                                                       const float* __restrict__ gain) {
    int token = blockIdx.x;
    int hh = blockIdx.y;                 // 0..NH-1 = Q heads, NH..NH+NKV-1 = K heads
    int d = threadIdx.x;
    int s = token & (SEQ - 1);
    bool isQ = hh < NH;
    int coloff = isQ ? hh * HD : DMODEL + (hh - NH) * HD;
    float v = src[(size_t)token * NQKV + coloff + d];

    float ss = v * v;
#pragma unroll
    for (int o = 16; o; o >>= 1) ss += __shfl_xor_sync(0xffffffffu, ss, o);
    __shared__ float ws[4];
    int lane = d & 31, w = d >> 5;
    if (lane == 0) ws[w] = ss;
    __syncthreads();
    float tot = ws[0] + ws[1] + ws[2] + ws[3];
    float inv = rsqrtf(tot * (1.0f / HD) + 1.1920928955078125e-7f);
    v *= inv;

    __shared__ float sv[HD];
    sv[d] = v;
    __syncthreads();

    float out;
    if (d < 64) {
        float c = g_cos[s * 64 + d], si = g_sin[s * 64 + d];
        out = v * c + sv[d + 64] * si;
    } else {
        int i = d - 64;
        float c = g_cos[s * 64 + i], si = g_sin[s * 64 + i];
        out = -sv[i] * si + v * c;
    }
    __nv_bfloat16 hv;
    if (isQ) {
        out *= gain[hh] * 0.08838834764831845f;
        size_t idx = ((size_t)token * NH + hh) * HD + d;
        hv = __float2bfloat16(out);
        qhi[idx] = hv;
        qlo[idx] = __float2bfloat16(out - __bfloat162float(hv));
    } else {
        size_t idx = ((size_t)token * NKV + (hh - NH)) * HD + d;
        hv = __float2bfloat16(out);
        khi[idx] = hv;
        klo[idx] = __float2bfloat16(out - __bfloat162float(hv));
    }
}

// ---------------- tensor-core flash attention (causal, GQA, bf16x3) ---------
#define FBQ 128
#define FBK 64
#define F_QHI 0
#define F_QLO 32768
#define F_STAGE0 65536
#define F_STAGEB 65536
#define F_KH 0
#define F_KL 16384
#define F_VH 32768
#define F_VL 49152
#define FSMEM_TOTAL (65536 + 2*F_STAGEB)

__device__ __forceinline__ uint32_t f_off(int row, int chunk) {
    return (uint32_t)(row * 256 + ((chunk ^ (row & 7)) << 4));
}

__device__ __forceinline__ void f_load_kv(uint32_t st,
                                          const __nv_bfloat16* kh, const __nv_bfloat16* kl,
                                          const __nv_bfloat16* vh, const __nv_bfloat16* vl,
                                          size_t gbase, int tid) {
#pragma unroll
    for (int j = 0; j < 4; j++) {
        int id = tid + j * 256;
        int row = id >> 4, c = id & 15;
        uint32_t so = f_off(row, c);
        size_t g = gbase + (size_t)row * KVD + c * 8;
        CP_ASYNC16(st + F_KH + so, kh + g);
        CP_ASYNC16(st + F_KL + so, kl + g);
        CP_ASYNC16(st + F_VH + so, vh + g);
        CP_ASYNC16(st + F_VL + so, vl + g);
    }
}

__global__ __launch_bounds__(256, 1) void flash_mma(
    const __nv_bfloat16* __restrict__ qh, const __nv_bfloat16* __restrict__ ql,
    const __nv_bfloat16* __restrict__ kh, const __nv_bfloat16* __restrict__ kl,
    const __nv_bfloat16* __restrict__ vh, const __nv_bfloat16* __restrict__ vl,
    __nv_bfloat16* __restrict__ yhi, __nv_bfloat16* __restrict__ ylo) {
    extern __shared__ char smem[];
    uint32_t sb = smem_u32(smem);
    int tid = threadIdx.x, lane = tid & 31, w = tid >> 5;
    int bh_ = blockIdx.y;
    int b = bh_ >> 4, h = bh_ & 15, hkv = h >> 2;
    // LPT scheduling: longest CTAs (largest qb) launch first
    int qb = (gridDim.x - 1 - blockIdx.x) * FBQ;
    int q0 = w * 16;

    // ---- Q (hi+lo) -> smem ----
#pragma unroll
    for (int j = 0; j < 8; j++) {
        int id = tid + j * 256;
        int row = id >> 4, c = id & 15;
        uint32_t so = f_off(row, c);
        size_t g = ((size_t)(b * SEQ + qb + row)) * DMODEL + h * HD + c * 8;
        CP_ASYNC16(sb + F_QHI + so, qh + g);
        CP_ASYNC16(sb + F_QLO + so, ql + g);
    }
    asm volatile("cp.async.commit_group;" ::: "memory");

    size_t kvhead = (size_t)(b * SEQ) * KVD + hkv * HD;
    int ntiles = qb / FBK + 2;

    f_load_kv(sb + F_STAGE0, kh, kl, vh, vl, kvhead, tid);
    asm volatile("cp.async.commit_group;" ::: "memory");

    // ---- hoist Q fragments into registers (loop-invariant) ----
    asm volatile("cp.async.wait_group 1;" ::: "memory");
    __syncthreads();
    uint32_t qfh[8][4], qfl[8][4];
#pragma unroll
    for (int ds = 0; ds < 8; ds++) {
        uint32_t qoff = f_off(q0 + (lane & 15), ds * 2 + (lane >> 4));
        ldsm_x4(qfh[ds], sb + F_QHI + qoff);
        ldsm_x4(qfl[ds], sb + F_QLO + qoff);
    }

    float o[16][4];
#pragma unroll
    for (int nt = 0; nt < 16; nt++)
#pragma unroll
        for (int e = 0; e < 4; e++) o[nt][e] = 0.f;
    float m0 = -1e30f, m1 = -1e30f, l0 = 0.f, l1 = 0.f;

    int qmax = qb + q0 + 15;
    int rr0 = qb + q0 + (lane >> 2);
    int rr1 = rr0 + 8;

    for (int t = 0; t < ntiles; t++) {
        if (t + 1 < ntiles)
            f_load_kv(sb + F_STAGE0 + ((t + 1) & 1) * F_STAGEB, kh, kl, vh, vl,
                      kvhead + (size_t)(t + 1) * FBK * KVD, tid);
        asm volatile("cp.async.commit_group;" ::: "memory");
        asm volatile("cp.async.wait_group 1;" ::: "memory");
        __syncthreads();

        int kv = t * FBK;
        if (kv <= qmax) {
            uint32_t st = sb + F_STAGE0 + (t & 1) * F_STAGEB;

            // ---- S = Q K^T (bf16x3); skip all-masked 16-key groups ----
            float c[8][4];
#pragma unroll
            for (int nt = 0; nt < 8; nt++)
#pragma unroll
                for (int e = 0; e < 4; e++) c[nt][e] = 0.f;

#pragma unroll
            for (int ds = 0; ds < 8; ds++) {
#pragma unroll
                for (int g = 0; g < 4; g++) {
                    if (kv + g * 16 <= qmax) {
                        int rowk = g * 16 + (lane & 7) + ((lane >> 4) << 3);
                        uint32_t koff = f_off(rowk, ds * 2 + ((lane >> 3) & 1));
                        uint32_t bh4[4], bl4[4];
                        ldsm_x4(bh4, st + F_KH + koff);
                        ldsm_x4(bl4, st + F_KL + koff);
#pragma unroll
                        for (int sub = 0; sub < 2; sub++) {
                            int nt = g * 2 + sub;
                            mma_bf16(c[nt], qfh[ds], &bh4[sub * 2]);
                            mma_bf16(c[nt], qfh[ds], &bl4[sub * 2]);
                            mma_bf16(c[nt], qfl[ds], &bh4[sub * 2]);
                        }
                    }
                }
            }

            if (kv + FBK - 1 > qb + q0) {
#pragma unroll
                for (int nt = 0; nt < 8; nt++) {
                    int col = kv + nt * 8 + (lane & 3) * 2;
                    if (col > rr0) c[nt][0] = -1e30f;
                    if (col + 1 > rr0) c[nt][1] = -1e30f;
                    if (col > rr1) c[nt][2] = -1e30f;
                    if (col + 1 > rr1) c[nt][3] = -1e30f;
                }
            }
            // groups skipped above have c==0; mask them (all cols > qmax >= rr)
#pragma unroll
            for (int g = 0; g < 4; g++)
                if (kv + g * 16 > qmax) {
#pragma unroll
                    for (int sub = 0; sub < 2; sub++) {
                        c[g * 2 + sub][0] = -1e30f; c[g * 2 + sub][1] = -1e30f;
                        c[g * 2 + sub][2] = -1e30f; c[g * 2 + sub][3] = -1e30f;
                    }
                }

            float mx0 = -1e30f, mx1 = -1e30f;
#pragma unroll
            for (int nt = 0; nt < 8; nt++) {
                mx0 = fmaxf(mx0, fmaxf(c[nt][0], c[nt][1]));
                mx1 = fmaxf(mx1, fmaxf(c[nt][2], c[nt][3]));
            }
            mx0 = fmaxf(mx0, __shfl_xor_sync(0xffffffffu, mx0, 1));
            mx0 = fmaxf(mx0, __shfl_xor_sync(0xffffffffu, mx0, 2));
            mx1 = fmaxf(mx1, __shfl_xor_sync(0xffffffffu, mx1, 1));
            mx1 = fmaxf(mx1, __shfl_xor_sync(0xffffffffu, mx1, 2));
            float m0n = fmaxf(m0, mx0), m1n = fmaxf(m1, mx1);
            float rs0 = exp2f((m0 - m0n) * LOG2E);
            float rs1 = exp2f((m1 - m1n) * LOG2E);
            float s0 = 0.f, s1 = 0.f;
#pragma unroll
            for (int nt = 0; nt < 8; nt++) {
                c[nt][0] = exp2f((c[nt][0] - m0n) * LOG2E);
                c[nt][1] = exp2f((c[nt][1] - m0n) * LOG2E);
                c[nt][2] = exp2f((c[nt][2] - m1n) * LOG2E);
                c[nt][3] = exp2f((c[nt][3] - m1n) * LOG2E);
                s0 += c[nt][0] + c[nt][1];
                s1 += c[nt][2] + c[nt][3];
            }
            s0 += __shfl_xor_sync(0xffffffffu, s0, 1);
            s0 += __shfl_xor_sync(0xffffffffu, s0, 2);
            s1 += __shfl_xor_sync(0xffffffffu, s1, 1);
            s1 += __shfl_xor_sync(0xffffffffu, s1, 2);
            l0 = l0 * rs0 + s0;
            l1 = l1 * rs1 + s1;
            m0 = m0n; m1 = m1n;
#pragma unroll
            for (int nt = 0; nt < 16; nt++) {
                o[nt][0] *= rs0; o[nt][1] *= rs0;
                o[nt][2] *= rs1; o[nt][3] *= rs1;
            }

            // ---- P x V (bf16x3); skip all-masked key groups ----
#pragma unroll
            for (int kt = 0; kt < 4; kt++) {
                if (kv + kt * 16 <= qmax) {
                    uint32_t aph[4], apl[4];
#pragma unroll
                    for (int half = 0; half < 2; half++) {
                        const float* cc = c[2 * kt + half];
#pragma unroll
                        for (int rh = 0; rh < 2; rh++) {
                            float v0 = cc[rh * 2], v1 = cc[rh * 2 + 1];
                            uint32_t hp = pack_bf16x2(v0, v1);
                            __nv_bfloat162 hb;
                            memcpy(&hb, &hp, 4);
                            float r0 = v0 - __bfloat162float(__low2bfloat16(hb));
                            float r1 = v1 - __bfloat162float(__high2bfloat16(hb));
                            aph[half * 2 + rh] = hp;
                            apl[half * 2 + rh] = pack_bf16x2(r0, r1);
                        }
                    }
#pragma unroll
                    for (int g = 0; g < 8; g++) {
                        int rowv = kt * 16 + (lane & 15);
                        uint32_t voff = f_off(rowv, g * 2 + (lane >> 4));
                        uint32_t vh4[4], vl4[4];
                        ldsm_x4_t(vh4, st + F_VH + voff);
                        ldsm_x4_t(vl4, st + F_VL + voff);
                        mma_bf16(o[2 * g], aph, &vh4[0]);
                        mma_bf16(o[2 * g], aph, &vl4[0]);
                        mma_bf16(o[2 * g], apl, &vh4[0]);
                        mma_bf16(o[2 * g + 1], aph, &vh4[2]);
                        mma_bf16(o[2 * g + 1], aph, &vl4[2]);
                        mma_bf16(o[2 * g + 1], apl, &vh4[2]);
                    }
                }
            }
        }
        __syncthreads();
    }

    float iv0 = 1.f / l0, iv1 = 1.f / l1;
    size_t base0 = ((size_t)(b * SEQ) + rr0) * DMODEL + h * HD;
    size_t base1 = base0 + (size_t)8 * DMODEL;
#pragma unroll
    for (int nt = 0; nt < 16; nt++) {
        int d = nt * 8 + (lane & 3) * 2;
        float v0 = o[nt][0] * iv0, v1 = o[nt][1] * iv0;
        float v2 = o[nt][2] * iv1, v3 = o[nt][3] * iv1;
        uint32_t hi0 = pack_bf16x2(v0, v1);
        uint32_t hi1 = pack_bf16x2(v2, v3);
        __nv_bfloat162 hb0, hb1;
        memcpy(&hb0, &hi0, 4);
        memcpy(&hb1, &hi1, 4);
        uint32_t lo0 = pack_bf16x2(v0 - __bfloat162float(__low2bfloat16(hb0)),
                                   v1 - __bfloat162float(__high2bfloat16(hb0)));
        uint32_t lo1 = pack_bf16x2(v2 - __bfloat162float(__low2bfloat16(hb1)),
                                   v3 - __bfloat162float(__high2bfloat16(hb1)));
        *(uint32_t*)(yhi + base0 + d) = hi0;
        *(uint32_t*)(ylo + base0 + d) = lo0;
        *(uint32_t*)(yhi + base1 + d) = hi1;
        *(uint32_t*)(ylo + base1 + d) = lo1;
    }
}

// ---------------------------------------------------------------------------
extern "C" void kernel_launch(void* const* d_in, const int* in_sizes, int n_in,
                              void* d_out, int out_size) {
    const float* x     = (const float*)d_in[0];
    const float* Wq    = (const float*)d_in[1];
    const float* Wk    = (const float*)d_in[2];
    const float* Wv    = (const float*)d_in[3];
    const float* Wproj = (const float*)d_in[4];
    const float* qgain = (const float*)d_in[5];

    float* qkv;
    cudaGetSymbolAddress((void**)&qkv, g_qkv);
    __nv_bfloat16 *xhi, *xlo, *yhi, *ylo, *qh, *ql, *kh, *kl, *vh, *vl;
    __nv_bfloat16 *wch, *wcl, *wph, *wpl;
    cudaGetSymbolAddress((void**)&xhi, g_xhi);  cudaGetSymbolAddress((void**)&xlo, g_xlo);
    cudaGetSymbolAddress((void**)&yhi, g_yhi);  cudaGetSymbolAddress((void**)&ylo, g_ylo);
    cudaGetSymbolAddress((void**)&qh, g_qhi);   cudaGetSymbolAddress((void**)&ql, g_qlo);
    cudaGetSymbolAddress((void**)&kh, g_khi);   cudaGetSymbolAddress((void**)&kl, g_klo);
    cudaGetSymbolAddress((void**)&vh, g_vhi);   cudaGetSymbolAddress((void**)&vl, g_vlo);
    cudaGetSymbolAddress((void**)&wch, g_wchi); cudaGetSymbolAddress((void**)&wcl, g_wclo);
    cudaGetSymbolAddress((void**)&wph, g_wphi); cudaGetSymbolAddress((void**)&wpl, g_wplo);

    cudaFuncSetAttribute(gemm_bf16x3, cudaFuncAttributeMaxDynamicSharedMemorySize, GSMEM_TOTAL);
    cudaFuncSetAttribute(flash_mma, cudaFuncAttributeMaxDynamicSharedMemorySize, FSMEM_TOTAL);

    rope_table_kernel<<<SEQ, 64>>>();

    {
        int n4 = BS * DMODEL / 4;
        split_kernel<<<(n4 + 255) / 256, 256>>>((const float4*)x, (__nv_bfloat162*)xhi, (__nv_bfloat162*)xlo, n4);
        int nw = WC4 + WQ4;
        split_weights<<<(nw + 255) / 256, 256>>>((const float4*)Wq, (const float4*)Wk,
                                                 (const float4*)Wv, (const float4*)Wproj,
                                                 (__nv_bfloat162*)wch, (__nv_bfloat162*)wcl,
                                                 (__nv_bfloat162*)wph, (__nv_bfloat162*)wpl);
    }

    gemm_bf16x3<<<dim3(NQKV / 128, BS / 128), 256, GSMEM_TOTAL>>>(
        xhi, xlo, wch, wcl, qkv, BS, NQKV, DMODEL);

    rmsnorm_rope_qk<<<dim3(BS, NH + NKV), HD>>>(qkv, qh, ql, kh, kl, qgain);
    {
        int n = BS * KVD / 4;
        split_strided<<<(n + 255) / 256, 256>>>(qkv, (__nv_bfloat162*)vh, (__nv_bfloat162*)vl,
                                                BS, KVD, NQKV, DMODEL + KVD);
    }

    flash_mma<<<dim3(SEQ / FBQ, BATCH * NH), 256, FSMEM_TOTAL>>>(qh, ql, kh, kl, vh, vl, yhi, ylo);

    gemm_bf16x3<<<dim3(DMODEL / 128, BS / 128), 256, GSMEM_TOTAL>>>(
        yhi, ylo, wph, wpl, (float*)d_out, BS, DMODEL, DMODEL);
}

// round 9
// speedup vs baseline: 1.0773x; 1.0773x over previous
#include <cuda_runtime.h>
#include <cuda_bf16.h>
#include <math.h>
#include <stdint.h>
#include <string.h>

#define BATCH 2
#define SEQ 2048
#define DMODEL 2048
#define NH 16
#define NKV 4
#define HD 128
#define BS (BATCH*SEQ)
#define KVD (NKV*HD)
#define NQKV (DMODEL + 2*KVD)     // 3072
#define LOG2E 1.4426950408889634f

// ---------------- scratch (__device__ globals; no allocs allowed) ----------
__device__ float g_qkv[(size_t)BS*NQKV];
__device__ float g_cos[SEQ*64];
__device__ float g_sin[SEQ*64];

__device__ __nv_bfloat16 g_xhi[(size_t)BS*DMODEL];
__device__ __nv_bfloat16 g_xlo[(size_t)BS*DMODEL];
__device__ __nv_bfloat16 g_yhi[(size_t)BS*DMODEL];
__device__ __nv_bfloat16 g_ylo[(size_t)BS*DMODEL];
__device__ __nv_bfloat16 g_qhi[(size_t)BS*DMODEL];
__device__ __nv_bfloat16 g_qlo[(size_t)BS*DMODEL];
__device__ __nv_bfloat16 g_khi[(size_t)BS*KVD];
__device__ __nv_bfloat16 g_klo[(size_t)BS*KVD];
__device__ __nv_bfloat16 g_vhi[(size_t)BS*KVD];
__device__ __nv_bfloat16 g_vlo[(size_t)BS*KVD];
__device__ __nv_bfloat16 g_wchi[(size_t)NQKV*DMODEL];   // [Wq;Wk;Wv]
__device__ __nv_bfloat16 g_wclo[(size_t)NQKV*DMODEL];
__device__ __nv_bfloat16 g_wphi[(size_t)DMODEL*DMODEL];
__device__ __nv_bfloat16 g_wplo[(size_t)DMODEL*DMODEL];

// ---------------- mma.sync helpers -----------------------------------------
__device__ __forceinline__ uint32_t smem_u32(const void* p) {
    uint32_t a;
    asm("{ .reg .u64 t; cvta.to.shared.u64 t, %1; cvt.u32.u64 %0, t; }" : "=r"(a) : "l"(p));
    return a;
}
__device__ __forceinline__ void ldsm_x4(uint32_t* r, uint32_t addr) {
    asm volatile("ldmatrix.sync.aligned.m8n8.x4.shared.b16 {%0,%1,%2,%3}, [%4];"
                 : "=r"(r[0]), "=r"(r[1]), "=r"(r[2]), "=r"(r[3]) : "r"(addr));
}
__device__ __forceinline__ void ldsm_x4_t(uint32_t* r, uint32_t addr) {
    asm volatile("ldmatrix.sync.aligned.m8n8.x4.trans.shared.b16 {%0,%1,%2,%3}, [%4];"
                 : "=r"(r[0]), "=r"(r[1]), "=r"(r[2]), "=r"(r[3]) : "r"(addr));
}
__device__ __forceinline__ void mma_bf16(float* d, const uint32_t* a, const uint32_t* b) {
    asm volatile("mma.sync.aligned.m16n8k16.row.col.f32.bf16.bf16.f32 "
                 "{%0,%1,%2,%3}, {%4,%5,%6,%7}, {%8,%9}, {%0,%1,%2,%3};"
                 : "+f"(d[0]), "+f"(d[1]), "+f"(d[2]), "+f"(d[3])
                 : "r"(a[0]), "r"(a[1]), "r"(a[2]), "r"(a[3]), "r"(b[0]), "r"(b[1]));
}
__device__ __forceinline__ uint32_t pack_bf16x2(float v0, float v1) {
    uint32_t r;
    asm("cvt.rn.bf16x2.f32 %0, %1, %2;" : "=r"(r) : "f"(v1), "f"(v0));
    return r;
}
#define CP_ASYNC16(s, g) \
    asm volatile("cp.async.cg.shared.global [%0], [%1], 16;" :: "r"(s), "l"(g))

// ---------------- fp32 -> bf16 hi/lo split ---------------------------------
__device__ __forceinline__ void split4(float4 v, __nv_bfloat162* hi, __nv_bfloat162* lo, size_t o2) {
    __nv_bfloat16 h0 = __float2bfloat16(v.x), h1 = __float2bfloat16(v.y);
    __nv_bfloat16 h2 = __float2bfloat16(v.z), h3 = __float2bfloat16(v.w);
    hi[o2 + 0] = __halves2bfloat162(h0, h1);
    hi[o2 + 1] = __halves2bfloat162(h2, h3);
    lo[o2 + 0] = __halves2bfloat162(__float2bfloat16(v.x - __bfloat162float(h0)),
                                    __float2bfloat16(v.y - __bfloat162float(h1)));
    lo[o2 + 1] = __halves2bfloat162(__float2bfloat16(v.z - __bfloat162float(h2)),
                                    __float2bfloat16(v.w - __bfloat162float(h3)));
}

__global__ __launch_bounds__(256) void split_kernel(const float4* __restrict__ src,
                                                    __nv_bfloat162* __restrict__ hi,
                                                    __nv_bfloat162* __restrict__ lo,
                                                    int n4) {
    int i = blockIdx.x * blockDim.x + threadIdx.x;
    if (i >= n4) return;
    split4(src[i], hi, lo, 2 * (size_t)i);
}

// fused split of ALL weights: Wq||Wk||Wv -> wc, Wproj -> wp
#define WQ4 (DMODEL*DMODEL/4)
#define WK4 (KVD*DMODEL/4)
#define WC4 (WQ4 + 2*WK4)
__global__ __launch_bounds__(256) void split_weights(const float4* __restrict__ wq,
                                                     const float4* __restrict__ wk,
                                                     const float4* __restrict__ wv,
                                                     const float4* __restrict__ wp,
                                                     __nv_bfloat162* __restrict__ chi,
                                                     __nv_bfloat162* __restrict__ clo,
                                                     __nv_bfloat162* __restrict__ phi,
                                                     __nv_bfloat162* __restrict__ plo) {
    int i = blockIdx.x * blockDim.x + threadIdx.x;
    if (i < WC4) {
        float4 v;
        if (i < WQ4) v = wq[i];
        else if (i < WQ4 + WK4) v = wk[i - WQ4];
        else v = wv[i - WQ4 - WK4];
        split4(v, chi, clo, 2 * (size_t)i);
    } else if (i < WC4 + WQ4) {
        int j = i - WC4;
        split4(wp[j], phi, plo, 2 * (size_t)j);
    }
}

// strided split: rows x cols out of a wider row of rstride
__global__ __launch_bounds__(256) void split_strided(const float* __restrict__ src,
                                                     __nv_bfloat162* __restrict__ hi,
                                                     __nv_bfloat162* __restrict__ lo,
                                                     int rows, int cols, int rstride, int coloff) {
    int i = blockIdx.x * blockDim.x + threadIdx.x;
    int c4 = cols / 4;
    if (i >= rows * c4) return;
    int row = i / c4, cc = (i % c4) * 4;
    float4 v = *(const float4*)(src + (size_t)row * rstride + coloff + cc);
    split4(v, hi, lo, ((size_t)row * cols + cc) / 2);
}

// ---------------- bf16x3 mma.sync GEMM: C[M,N] = A[M,K] @ B[N,K]^T ---------
// 128x128 CTA tile, BK=32, 3-stage cp.async pipeline, ONE barrier per chunk.
#define GSTAGES 3
#define GBK 32
#define GTILEB (128*GBK*2)
#define GSTAGEB (4*GTILEB)
#define GSMEM_TOTAL (GSTAGES*GSTAGEB)

__device__ __forceinline__ uint32_t sw_off(int row, int chunk) {
    return (uint32_t)(row * 64 + ((chunk ^ (row & 3)) << 4));
}
__device__ __forceinline__ void g_load_stage(const __nv_bfloat16* Ahi, const __nv_bfloat16* Alo,
                                             const __nv_bfloat16* Bhi, const __nv_bfloat16* Blo,
                                             int bm, int bn, int K, int kc,
                                             uint32_t tb, int tid) {
    size_t kcol = (size_t)kc * GBK;
#pragma unroll
    for (int j = 0; j < 2; j++) {
        int idx = tid + j * 256;
        int row = idx >> 2, c = idx & 3;
        uint32_t so = sw_off(row, c);
        size_t ga = (size_t)(bm + row) * K + kcol + c * 8;
        size_t gb = (size_t)(bn + row) * K + kcol + c * 8;
        CP_ASYNC16(tb + so, Ahi + ga);
        CP_ASYNC16(tb + GTILEB + so, Alo + ga);
        CP_ASYNC16(tb + 2 * GTILEB + so, Bhi + gb);
        CP_ASYNC16(tb + 3 * GTILEB + so, Blo + gb);
    }
}

__global__ __launch_bounds__(256, 2) void gemm_bf16x3(
    const __nv_bfloat16* __restrict__ Ahi, const __nv_bfloat16* __restrict__ Alo,
    const __nv_bfloat16* __restrict__ Bhi, const __nv_bfloat16* __restrict__ Blo,
    float* __restrict__ C, int M, int N, int K) {
    extern __shared__ char smem[];
    uint32_t sb = smem_u32(smem);
    int tid = threadIdx.x, wid = tid >> 5, lane = tid & 31;
    int bm = blockIdx.y * 128, bn = blockIdx.x * 128;
    int wm = (wid >> 2) * 64;
    int wn = (wid & 3) * 32;
    const int NK = K / GBK;

    float acc[4][4][4];
#pragma unroll
    for (int a = 0; a < 4; a++)
#pragma unroll
        for (int b = 0; b < 4; b++)
#pragma unroll
            for (int c = 0; c < 4; c++) acc[a][b][c] = 0.f;

#pragma unroll
    for (int s = 0; s < GSTAGES - 1; s++) {
        g_load_stage(Ahi, Alo, Bhi, Blo, bm, bn, K, s, sb + s * GSTAGEB, tid);
        asm volatile("cp.async.commit_group;" ::: "memory");
    }

    for (int kc = 0; kc < NK; kc++) {
        asm volatile("cp.async.wait_group %0;" :: "n"(GSTAGES - 2) : "memory");
        __syncthreads();
        // Safe: refill target stage (kc+2)%3 == (kc-1)%3 was last read in iter
        // kc-1, and every warp passed the barrier above after finishing it.
        uint32_t tb = sb + (kc % GSTAGES) * GSTAGEB;

#pragma unroll
        for (int ks = 0; ks < 2; ks++) {
            uint32_t ah[4][4], al[4][4], bh[2][4], bl[2][4];
#pragma unroll
            for (int mt = 0; mt < 4; mt++) {
                int row = wm + mt * 16 + (lane & 15);
                uint32_t off = sw_off(row, ks * 2 + (lane >> 4));
                ldsm_x4(ah[mt], tb + off);
                ldsm_x4(al[mt], tb + GTILEB + off);
            }
#pragma unroll
            for (int pr = 0; pr < 2; pr++) {
                int row = wn + pr * 16 + (lane & 7) + ((lane >> 4) << 3);
                uint32_t off = sw_off(row, ks * 2 + ((lane >> 3) & 1));
                ldsm_x4(bh[pr], tb + 2 * GTILEB + off);
                ldsm_x4(bl[pr], tb + 3 * GTILEB + off);
            }
#pragma unroll
            for (int mt = 0; mt < 4; mt++)
#pragma unroll
                for (int nt = 0; nt < 4; nt++) {
                    const uint32_t* bhp = &bh[nt >> 1][(nt & 1) * 2];
                    const uint32_t* blp = &bl[nt >> 1][(nt & 1) * 2];
                    mma_bf16(acc[mt][nt], ah[mt], bhp);
                    mma_bf16(acc[mt][nt], ah[mt], blp);
                    mma_bf16(acc[mt][nt], al[mt], bhp);
                }
        }
        // no barrier here (see note above)
        if (kc + GSTAGES - 1 < NK) {
            int pst = (kc + GSTAGES - 1) % GSTAGES;
            g_load_stage(Ahi, Alo, Bhi, Blo, bm, bn, K, kc + GSTAGES - 1, sb + pst * GSTAGEB, tid);
        }
        asm volatile("cp.async.commit_group;" ::: "memory");
    }

#pragma unroll
    for (int mt = 0; mt < 4; mt++) {
        int row0 = bm + wm + mt * 16 + (lane >> 2);
#pragma unroll
        for (int nt = 0; nt < 4; nt++) {
            int col = bn + wn + nt * 8 + (lane & 3) * 2;
            *(float2*)(C + (size_t)row0 * N + col) = make_float2(acc[mt][nt][0], acc[mt][nt][1]);
            *(float2*)(C + (size_t)(row0 + 8) * N + col) = make_float2(acc[mt][nt][2], acc[mt][nt][3]);
        }
    }
}

// ---------------- RoPE table ------------------------------------------------
__global__ void rope_table_kernel() {
    int i = threadIdx.x;
    int t = blockIdx.x;
    double inv = exp(-((double)(2 * i) / 128.0) * log(10000.0));
    double a = (double)t * inv;
    g_cos[t * 64 + i] = (float)cos(a);
    g_sin[t * 64 + i] = (float)sin(a);
}

// ---------------- fused RMSNorm + RoPE (Q and K in one launch) --------------
__global__ __launch_bounds__(128) void rmsnorm_rope_qk(const float* __restrict__ src,
                                                       __nv_bfloat16* __restrict__ qhi,
                                                       __nv_bfloat16* __restrict__ qlo,
                                                       __nv_bfloat16* __restrict__ khi,
                                                       __nv_bfloat16* __restrict__ klo,
                                                       const float* __restrict__ gain) {
    int token = blockIdx.x;
    int hh = blockIdx.y;
    int d = threadIdx.x;
    int s = token & (SEQ - 1);
    bool isQ = hh < NH;
    int coloff = isQ ? hh * HD : DMODEL + (hh - NH) * HD;
    float v = src[(size_t)token * NQKV + coloff + d];

    float ss = v * v;
#pragma unroll
    for (int o = 16; o; o >>= 1) ss += __shfl_xor_sync(0xffffffffu, ss, o);
    __shared__ float ws[4];
    int lane = d & 31, w = d >> 5;
    if (lane == 0) ws[w] = ss;
    __syncthreads();
    float tot = ws[0] + ws[1] + ws[2] + ws[3];
    float inv = rsqrtf(tot * (1.0f / HD) + 1.1920928955078125e-7f);
    v *= inv;

    __shared__ float sv[HD];
    sv[d] = v;
    __syncthreads();

    float out;
    if (d < 64) {
        float c = g_cos[s * 64 + d], si = g_sin[s * 64 + d];
        out = v * c + sv[d + 64] * si;
    } else {
        int i = d - 64;
        float c = g_cos[s * 64 + i], si = g_sin[s * 64 + i];
        out = -sv[i] * si + v * c;
    }
    __nv_bfloat16 hv;
    if (isQ) {
        out *= gain[hh] * 0.08838834764831845f;
        size_t idx = ((size_t)token * NH + hh) * HD + d;
        hv = __float2bfloat16(out);
        qhi[idx] = hv;
        qlo[idx] = __float2bfloat16(out - __bfloat162float(hv));
    } else {
        size_t idx = ((size_t)token * NKV + (hh - NH)) * HD + d;
        hv = __float2bfloat16(out);
        khi[idx] = hv;
        klo[idx] = __float2bfloat16(out - __bfloat162float(hv));
    }
}

// ---------------- tensor-core flash attention (causal, GQA, bf16x3) ---------
#define FBQ 128
#define FBK 64
#define F_QHI 0
#define F_QLO 32768
#define F_STAGE0 65536
#define F_STAGEB 65536
#define F_KH 0
#define F_KL 16384
#define F_VH 32768
#define F_VL 49152
#define FSMEM_TOTAL (65536 + 2*F_STAGEB)

__device__ __forceinline__ uint32_t f_off(int row, int chunk) {
    return (uint32_t)(row * 256 + ((chunk ^ (row & 7)) << 4));
}

__device__ __forceinline__ void f_load_kv(uint32_t st,
                                          const __nv_bfloat16* kh, const __nv_bfloat16* kl,
                                          const __nv_bfloat16* vh, const __nv_bfloat16* vl,
                                          size_t gbase, int tid) {
#pragma unroll
    for (int j = 0; j < 4; j++) {
        int id = tid + j * 256;
        int row = id >> 4, c = id & 15;
        uint32_t so = f_off(row, c);
        size_t g = gbase + (size_t)row * KVD + c * 8;
        CP_ASYNC16(st + F_KH + so, kh + g);
        CP_ASYNC16(st + F_KL + so, kl + g);
        CP_ASYNC16(st + F_VH + so, vh + g);
        CP_ASYNC16(st + F_VL + so, vl + g);
    }
}

__global__ __launch_bounds__(256, 1) void flash_mma(
    const __nv_bfloat16* __restrict__ qh, const __nv_bfloat16* __restrict__ ql,
    const __nv_bfloat16* __restrict__ kh, const __nv_bfloat16* __restrict__ kl,
    const __nv_bfloat16* __restrict__ vh, const __nv_bfloat16* __restrict__ vl,
    __nv_bfloat16* __restrict__ yhi, __nv_bfloat16* __restrict__ ylo) {
    extern __shared__ char smem[];
    uint32_t sb = smem_u32(smem);
    int tid = threadIdx.x, lane = tid & 31, w = tid >> 5;
    int bh_ = blockIdx.y;
    int b = bh_ >> 4, h = bh_ & 15, hkv = h >> 2;
    // LPT scheduling: longest CTAs (largest qb) launch first
    int qb = (gridDim.x - 1 - blockIdx.x) * FBQ;
    int q0 = w * 16;

    // ---- Q (hi+lo) -> smem ----
#pragma unroll
    for (int j = 0; j < 8; j++) {
        int id = tid + j * 256;
        int row = id >> 4, c = id & 15;
        uint32_t so = f_off(row, c);
        size_t g = ((size_t)(b * SEQ + qb + row)) * DMODEL + h * HD + c * 8;
        CP_ASYNC16(sb + F_QHI + so, qh + g);
        CP_ASYNC16(sb + F_QLO + so, ql + g);
    }
    asm volatile("cp.async.commit_group;" ::: "memory");

    size_t kvhead = (size_t)(b * SEQ) * KVD + hkv * HD;
    int ntiles = qb / FBK + 2;

    f_load_kv(sb + F_STAGE0, kh, kl, vh, vl, kvhead, tid);
    asm volatile("cp.async.commit_group;" ::: "memory");

    // ---- hoist Q fragments into registers (loop-invariant) ----
    asm volatile("cp.async.wait_group 1;" ::: "memory");
    __syncthreads();
    uint32_t qfh[8][4], qfl[8][4];
#pragma unroll
    for (int ds = 0; ds < 8; ds++) {
        uint32_t qoff = f_off(q0 + (lane & 15), ds * 2 + (lane >> 4));
        ldsm_x4(qfh[ds], sb + F_QHI + qoff);
        ldsm_x4(qfl[ds], sb + F_QLO + qoff);
    }

    float o[16][4];
#pragma unroll
    for (int nt = 0; nt < 16; nt++)
#pragma unroll
        for (int e = 0; e < 4; e++) o[nt][e] = 0.f;
    float m0 = -1e30f, m1 = -1e30f, l0 = 0.f, l1 = 0.f;

    int qmax = qb + q0 + 15;
    int rr0 = qb + q0 + (lane >> 2);
    int rr1 = rr0 + 8;

    for (int t = 0; t < ntiles; t++) {
        if (t + 1 < ntiles)
            f_load_kv(sb + F_STAGE0 + ((t + 1) & 1) * F_STAGEB, kh, kl, vh, vl,
                      kvhead + (size_t)(t + 1) * FBK * KVD, tid);
        asm volatile("cp.async.commit_group;" ::: "memory");
        asm volatile("cp.async.wait_group 1;" ::: "memory");
        __syncthreads();

        int kv = t * FBK;
        if (kv <= qmax) {
            uint32_t st = sb + F_STAGE0 + (t & 1) * F_STAGEB;

            // ---- S = Q K^T (bf16x3), Q from registers ----
            float c[8][4];
#pragma unroll
            for (int nt = 0; nt < 8; nt++)
#pragma unroll
                for (int e = 0; e < 4; e++) c[nt][e] = 0.f;

#pragma unroll
            for (int ds = 0; ds < 8; ds++) {
                uint32_t bh4[4][4], bl4[4][4];
#pragma unroll
                for (int g = 0; g < 4; g++) {
                    int rowk = g * 16 + (lane & 7) + ((lane >> 4) << 3);
                    uint32_t koff = f_off(rowk, ds * 2 + ((lane >> 3) & 1));
                    ldsm_x4(bh4[g], st + F_KH + koff);
                    ldsm_x4(bl4[g], st + F_KL + koff);
                }
#pragma unroll
                for (int g = 0; g < 4; g++)
#pragma unroll
                    for (int sub = 0; sub < 2; sub++) {
                        int nt = g * 2 + sub;
                        mma_bf16(c[nt], qfh[ds], &bh4[g][sub * 2]);
                        mma_bf16(c[nt], qfh[ds], &bl4[g][sub * 2]);
                        mma_bf16(c[nt], qfl[ds], &bh4[g][sub * 2]);
                    }
            }

            if (kv + FBK - 1 > qb + q0) {
#pragma unroll
                for (int nt = 0; nt < 8; nt++) {
                    int col = kv + nt * 8 + (lane & 3) * 2;
                    if (col > rr0) c[nt][0] = -1e30f;
                    if (col + 1 > rr0) c[nt][1] = -1e30f;
                    if (col > rr1) c[nt][2] = -1e30f;
                    if (col + 1 > rr1) c[nt][3] = -1e30f;
                }
            }

            float mx0 = -1e30f, mx1 = -1e30f;
#pragma unroll
            for (int nt = 0; nt < 8; nt++) {
                mx0 = fmaxf(mx0, fmaxf(c[nt][0], c[nt][1]));
                mx1 = fmaxf(mx1, fmaxf(c[nt][2], c[nt][3]));
            }
            mx0 = fmaxf(mx0, __shfl_xor_sync(0xffffffffu, mx0, 1));
            mx0 = fmaxf(mx0, __shfl_xor_sync(0xffffffffu, mx0, 2));
            mx1 = fmaxf(mx1, __shfl_xor_sync(0xffffffffu, mx1, 1));
            mx1 = fmaxf(mx1, __shfl_xor_sync(0xffffffffu, mx1, 2));
            float m0n = fmaxf(m0, mx0), m1n = fmaxf(m1, mx1);
            float rs0 = exp2f((m0 - m0n) * LOG2E);
            float rs1 = exp2f((m1 - m1n) * LOG2E);
            float s0 = 0.f, s1 = 0.f;
#pragma unroll
            for (int nt = 0; nt < 8; nt++) {
                c[nt][0] = exp2f((c[nt][0] - m0n) * LOG2E);
                c[nt][1] = exp2f((c[nt][1] - m0n) * LOG2E);
                c[nt][2] = exp2f((c[nt][2] - m1n) * LOG2E);
                c[nt][3] = exp2f((c[nt][3] - m1n) * LOG2E);
                s0 += c[nt][0] + c[nt][1];
                s1 += c[nt][2] + c[nt][3];
            }
            s0 += __shfl_xor_sync(0xffffffffu, s0, 1);
            s0 += __shfl_xor_sync(0xffffffffu, s0, 2);
            s1 += __shfl_xor_sync(0xffffffffu, s1, 1);
            s1 += __shfl_xor_sync(0xffffffffu, s1, 2);
            l0 = l0 * rs0 + s0;
            l1 = l1 * rs1 + s1;
            m0 = m0n; m1 = m1n;
#pragma unroll
            for (int nt = 0; nt < 16; nt++) {
                o[nt][0] *= rs0; o[nt][1] *= rs0;
                o[nt][2] *= rs1; o[nt][3] *= rs1;
            }

#pragma unroll
            for (int kt = 0; kt < 4; kt++) {
                uint32_t aph[4], apl[4];
#pragma unroll
                for (int half = 0; half < 2; half++) {
                    const float* cc = c[2 * kt + half];
#pragma unroll
                    for (int rh = 0; rh < 2; rh++) {
                        float v0 = cc[rh * 2], v1 = cc[rh * 2 + 1];
                        uint32_t hp = pack_bf16x2(v0, v1);
                        __nv_bfloat162 hb;
                        memcpy(&hb, &hp, 4);
                        float r0 = v0 - __bfloat162float(__low2bfloat16(hb));
                        float r1 = v1 - __bfloat162float(__high2bfloat16(hb));
                        aph[half * 2 + rh] = hp;
                        apl[half * 2 + rh] = pack_bf16x2(r0, r1);
                    }
                }
#pragma unroll
                for (int g = 0; g < 8; g++) {
                    int rowv = kt * 16 + (lane & 15);
                    uint32_t voff = f_off(rowv, g * 2 + (lane >> 4));
                    uint32_t vh4[4], vl4[4];
                    ldsm_x4_t(vh4, st + F_VH + voff);
                    ldsm_x4_t(vl4, st + F_VL + voff);
                    mma_bf16(o[2 * g], aph, &vh4[0]);
                    mma_bf16(o[2 * g], aph, &vl4[0]);
                    mma_bf16(o[2 * g], apl, &vh4[0]);
                    mma_bf16(o[2 * g + 1], aph, &vh4[2]);
                    mma_bf16(o[2 * g + 1], aph, &vl4[2]);
                    mma_bf16(o[2 * g + 1], apl, &vh4[2]);
                }
            }
        }
        __syncthreads();
    }

    float iv0 = 1.f / l0, iv1 = 1.f / l1;
    size_t base0 = ((size_t)(b * SEQ) + rr0) * DMODEL + h * HD;
    size_t base1 = base0 + (size_t)8 * DMODEL;
#pragma unroll
    for (int nt = 0; nt < 16; nt++) {
        int d = nt * 8 + (lane & 3) * 2;
        float v0 = o[nt][0] * iv0, v1 = o[nt][1] * iv0;
        float v2 = o[nt][2] * iv1, v3 = o[nt][3] * iv1;
        uint32_t hi0 = pack_bf16x2(v0, v1);
        uint32_t hi1 = pack_bf16x2(v2, v3);
        __nv_bfloat162 hb0, hb1;
        memcpy(&hb0, &hi0, 4);
        memcpy(&hb1, &hi1, 4);
        uint32_t lo0 = pack_bf16x2(v0 - __bfloat162float(__low2bfloat16(hb0)),
                                   v1 - __bfloat162float(__high2bfloat16(hb0)));
        uint32_t lo1 = pack_bf16x2(v2 - __bfloat162float(__low2bfloat16(hb1)),
                                   v3 - __bfloat162float(__high2bfloat16(hb1)));
        *(uint32_t*)(yhi + base0 + d) = hi0;
        *(uint32_t*)(ylo + base0 + d) = lo0;
        *(uint32_t*)(yhi + base1 + d) = hi1;
        *(uint32_t*)(ylo + base1 + d) = lo1;
    }
}

// ---------------------------------------------------------------------------
extern "C" void kernel_launch(void* const* d_in, const int* in_sizes, int n_in,
                              void* d_out, int out_size) {
    const float* x     = (const float*)d_in[0];
    const float* Wq    = (const float*)d_in[1];
    const float* Wk    = (const float*)d_in[2];
    const float* Wv    = (const float*)d_in[3];
    const float* Wproj = (const float*)d_in[4];
    const float* qgain = (const float*)d_in[5];

    float* qkv;
    cudaGetSymbolAddress((void**)&qkv, g_qkv);
    __nv_bfloat16 *xhi, *xlo, *yhi, *ylo, *qh, *ql, *kh, *kl, *vh, *vl;
    __nv_bfloat16 *wch, *wcl, *wph, *wpl;
    cudaGetSymbolAddress((void**)&xhi, g_xhi);  cudaGetSymbolAddress((void**)&xlo, g_xlo);
    cudaGetSymbolAddress((void**)&yhi, g_yhi);  cudaGetSymbolAddress((void**)&ylo, g_ylo);
    cudaGetSymbolAddress((void**)&qh, g_qhi);   cudaGetSymbolAddress((void**)&ql, g_qlo);
    cudaGetSymbolAddress((void**)&kh, g_khi);   cudaGetSymbolAddress((void**)&kl, g_klo);
    cudaGetSymbolAddress((void**)&vh, g_vhi);   cudaGetSymbolAddress((void**)&vl, g_vlo);
    cudaGetSymbolAddress((void**)&wch, g_wchi); cudaGetSymbolAddress((void**)&wcl, g_wclo);
    cudaGetSymbolAddress((void**)&wph, g_wphi); cudaGetSymbolAddress((void**)&wpl, g_wplo);

    cudaFuncSetAttribute(gemm_bf16x3, cudaFuncAttributeMaxDynamicSharedMemorySize, GSMEM_TOTAL);
    cudaFuncSetAttribute(flash_mma, cudaFuncAttributeMaxDynamicSharedMemorySize, FSMEM_TOTAL);

    rope_table_kernel<<<SEQ, 64>>>();

    {
        int n4 = BS * DMODEL / 4;
        split_kernel<<<(n4 + 255) / 256, 256>>>((const float4*)x, (__nv_bfloat162*)xhi, (__nv_bfloat162*)xlo, n4);
        int nw = WC4 + WQ4;
        split_weights<<<(nw + 255) / 256, 256>>>((const float4*)Wq, (const float4*)Wk,
                                                 (const float4*)Wv, (const float4*)Wproj,
                                                 (__nv_bfloat162*)wch, (__nv_bfloat162*)wcl,
                                                 (__nv_bfloat162*)wph, (__nv_bfloat162*)wpl);
    }

    gemm_bf16x3<<<dim3(NQKV / 128, BS / 128), 256, GSMEM_TOTAL>>>(
        xhi, xlo, wch, wcl, qkv, BS, NQKV, DMODEL);

    rmsnorm_rope_qk<<<dim3(BS, NH + NKV), HD>>>(qkv, qh, ql, kh, kl, qgain);
    {
        int n = BS * KVD / 4;
        split_strided<<<(n + 255) / 256, 256>>>(qkv, (__nv_bfloat162*)vh, (__nv_bfloat162*)vl,
                                                BS, KVD, NQKV, DMODEL + KVD);
    }

    flash_mma<<<dim3(SEQ / FBQ, BATCH * NH), 256, FSMEM_TOTAL>>>(qh, ql, kh, kl, vh, vl, yhi, ylo);

    gemm_bf16x3<<<dim3(DMODEL / 128, BS / 128), 256, GSMEM_TOTAL>>>(
        yhi, ylo, wph, wpl, (float*)d_out, BS, DMODEL, DMODEL);
}

// round 10
// speedup vs baseline: 1.0800x; 1.0026x over previous
#include <cuda_runtime.h>
#include <cuda_bf16.h>
#include <math.h>
#include <stdint.h>
#include <string.h>

#define BATCH 2
#define SEQ 2048
#define DMODEL 2048
#define NH 16
#define NKV 4
#define HD 128
#define BS (BATCH*SEQ)
#define KVD (NKV*HD)
#define NQKV (DMODEL + 2*KVD)     // 3072
#define LOG2E 1.4426950408889634f

// ---------------- scratch (__device__ globals; no allocs allowed) ----------
__device__ float g_qkv[(size_t)BS*NQKV];
__device__ float g_cos[SEQ*64];
__device__ float g_sin[SEQ*64];

__device__ __nv_bfloat16 g_xhi[(size_t)BS*DMODEL];
__device__ __nv_bfloat16 g_xlo[(size_t)BS*DMODEL];
__device__ __nv_bfloat16 g_yhi[(size_t)BS*DMODEL];
__device__ __nv_bfloat16 g_ylo[(size_t)BS*DMODEL];
__device__ __nv_bfloat16 g_qhi[(size_t)BS*DMODEL];
__device__ __nv_bfloat16 g_qlo[(size_t)BS*DMODEL];
__device__ __nv_bfloat16 g_khi[(size_t)BS*KVD];
__device__ __nv_bfloat16 g_klo[(size_t)BS*KVD];
__device__ __nv_bfloat16 g_vhi[(size_t)BS*KVD];
__device__ __nv_bfloat16 g_vlo[(size_t)BS*KVD];
__device__ __nv_bfloat16 g_wchi[(size_t)NQKV*DMODEL];   // [Wq;Wk;Wv]
__device__ __nv_bfloat16 g_wclo[(size_t)NQKV*DMODEL];
__device__ __nv_bfloat16 g_wphi[(size_t)DMODEL*DMODEL];
__device__ __nv_bfloat16 g_wplo[(size_t)DMODEL*DMODEL];

// ---------------- mma.sync helpers -----------------------------------------
__device__ __forceinline__ uint32_t smem_u32(const void* p) {
    uint32_t a;
    asm("{ .reg .u64 t; cvta.to.shared.u64 t, %1; cvt.u32.u64 %0, t; }" : "=r"(a) : "l"(p));
    return a;
}
__device__ __forceinline__ void ldsm_x4(uint32_t* r, uint32_t addr) {
    asm volatile("ldmatrix.sync.aligned.m8n8.x4.shared.b16 {%0,%1,%2,%3}, [%4];"
                 : "=r"(r[0]), "=r"(r[1]), "=r"(r[2]), "=r"(r[3]) : "r"(addr));
}
__device__ __forceinline__ void ldsm_x4_t(uint32_t* r, uint32_t addr) {
    asm volatile("ldmatrix.sync.aligned.m8n8.x4.trans.shared.b16 {%0,%1,%2,%3}, [%4];"
                 : "=r"(r[0]), "=r"(r[1]), "=r"(r[2]), "=r"(r[3]) : "r"(addr));
}
__device__ __forceinline__ void mma_bf16(float* d, const uint32_t* a, const uint32_t* b) {
    asm volatile("mma.sync.aligned.m16n8k16.row.col.f32.bf16.bf16.f32 "
                 "{%0,%1,%2,%3}, {%4,%5,%6,%7}, {%8,%9}, {%0,%1,%2,%3};"
                 : "+f"(d[0]), "+f"(d[1]), "+f"(d[2]), "+f"(d[3])
                 : "r"(a[0]), "r"(a[1]), "r"(a[2]), "r"(a[3]), "r"(b[0]), "r"(b[1]));
}
__device__ __forceinline__ uint32_t pack_bf16x2(float v0, float v1) {
    uint32_t r;
    asm("cvt.rn.bf16x2.f32 %0, %1, %2;" : "=r"(r) : "f"(v1), "f"(v0));
    return r;
}
#define CP_ASYNC16(s, g) \
    asm volatile("cp.async.cg.shared.global [%0], [%1], 16;" :: "r"(s), "l"(g))

// ---------------- fp32 -> bf16 hi/lo split ---------------------------------
__device__ __forceinline__ void split4(float4 v, __nv_bfloat162* hi, __nv_bfloat162* lo, size_t o2) {
    __nv_bfloat16 h0 = __float2bfloat16(v.x), h1 = __float2bfloat16(v.y);
    __nv_bfloat16 h2 = __float2bfloat16(v.z), h3 = __float2bfloat16(v.w);
    hi[o2 + 0] = __halves2bfloat162(h0, h1);
    hi[o2 + 1] = __halves2bfloat162(h2, h3);
    lo[o2 + 0] = __halves2bfloat162(__float2bfloat16(v.x - __bfloat162float(h0)),
                                    __float2bfloat16(v.y - __bfloat162float(h1)));
    lo[o2 + 1] = __halves2bfloat162(__float2bfloat16(v.z - __bfloat162float(h2)),
                                    __float2bfloat16(v.w - __bfloat162float(h3)));
}

__global__ __launch_bounds__(256) void split_kernel(const float4* __restrict__ src,
                                                    __nv_bfloat162* __restrict__ hi,
                                                    __nv_bfloat162* __restrict__ lo,
                                                    int n4) {
    int i = blockIdx.x * blockDim.x + threadIdx.x;
    if (i >= n4) return;
    split4(src[i], hi, lo, 2 * (size_t)i);
}

// fused split of ALL weights: Wq||Wk||Wv -> wc, Wproj -> wp
#define WQ4 (DMODEL*DMODEL/4)
#define WK4 (KVD*DMODEL/4)
#define WC4 (WQ4 + 2*WK4)
__global__ __launch_bounds__(256) void split_weights(const float4* __restrict__ wq,
                                                     const float4* __restrict__ wk,
                                                     const float4* __restrict__ wv,
                                                     const float4* __restrict__ wp,
                                                     __nv_bfloat162* __restrict__ chi,
                                                     __nv_bfloat162* __restrict__ clo,
                                                     __nv_bfloat162* __restrict__ phi,
                                                     __nv_bfloat162* __restrict__ plo) {
    int i = blockIdx.x * blockDim.x + threadIdx.x;
    if (i < WC4) {
        float4 v;
        if (i < WQ4) v = wq[i];
        else if (i < WQ4 + WK4) v = wk[i - WQ4];
        else v = wv[i - WQ4 - WK4];
        split4(v, chi, clo, 2 * (size_t)i);
    } else if (i < WC4 + WQ4) {
        int j = i - WC4;
        split4(wp[j], phi, plo, 2 * (size_t)j);
    }
}

// strided split: rows x cols out of a wider row of rstride
__global__ __launch_bounds__(256) void split_strided(const float* __restrict__ src,
                                                     __nv_bfloat162* __restrict__ hi,
                                                     __nv_bfloat162* __restrict__ lo,
                                                     int rows, int cols, int rstride, int coloff) {
    int i = blockIdx.x * blockDim.x + threadIdx.x;
    int c4 = cols / 4;
    if (i >= rows * c4) return;
    int row = i / c4, cc = (i % c4) * 4;
    float4 v = *(const float4*)(src + (size_t)row * rstride + coloff + cc);
    split4(v, hi, lo, ((size_t)row * cols + cc) / 2);
}

// ---------------- bf16x3 mma.sync GEMM: C[M,N] = A[M,K] @ B[N,K]^T ---------
// 256x128 CTA tile, 8 warps of 64x64, BK=32, 3-stage cp.async, 1 CTA/SM.
#define GSTAGES 3
#define GBK 32
#define A_SZ (256*GBK*2)            // 16KB per matrix
#define B_SZ (128*GBK*2)            // 8KB per matrix
#define GSTAGEB (2*A_SZ + 2*B_SZ)   // 48KB
#define G_ALO  A_SZ
#define G_BHI  (2*A_SZ)
#define G_BLO  (2*A_SZ + B_SZ)
#define GSMEM_TOTAL (GSTAGES*GSTAGEB)

__device__ __forceinline__ uint32_t sw_off(int row, int chunk) {
    return (uint32_t)(row * 64 + ((chunk ^ (row & 3)) << 4));
}
__device__ __forceinline__ void g_load_stage(const __nv_bfloat16* Ahi, const __nv_bfloat16* Alo,
                                             const __nv_bfloat16* Bhi, const __nv_bfloat16* Blo,
                                             int bm, int bn, int K, int kc,
                                             uint32_t tb, int tid) {
    size_t kcol = (size_t)kc * GBK;
#pragma unroll
    for (int j = 0; j < 4; j++) {              // A: 256 rows
        int idx = tid + j * 256;
        int row = idx >> 2, c = idx & 3;
        uint32_t so = sw_off(row, c);
        size_t ga = (size_t)(bm + row) * K + kcol + c * 8;
        CP_ASYNC16(tb + so, Ahi + ga);
        CP_ASYNC16(tb + G_ALO + so, Alo + ga);
    }
#pragma unroll
    for (int j = 0; j < 2; j++) {              // B: 128 rows
        int idx = tid + j * 256;
        int row = idx >> 2, c = idx & 3;
        uint32_t so = sw_off(row, c);
        size_t gb = (size_t)(bn + row) * K + kcol + c * 8;
        CP_ASYNC16(tb + G_BHI + so, Bhi + gb);
        CP_ASYNC16(tb + G_BLO + so, Blo + gb);
    }
}

__global__ __launch_bounds__(256, 1) void gemm_bf16x3(
    const __nv_bfloat16* __restrict__ Ahi, const __nv_bfloat16* __restrict__ Alo,
    const __nv_bfloat16* __restrict__ Bhi, const __nv_bfloat16* __restrict__ Blo,
    float* __restrict__ C, int M, int N, int K) {
    extern __shared__ char smem[];
    uint32_t sb = smem_u32(smem);
    int tid = threadIdx.x, wid = tid >> 5, lane = tid & 31;
    int bm = blockIdx.y * 256, bn = blockIdx.x * 128;
    int wm = (wid >> 1) * 64;       // 0,64,128,192
    int wn = (wid & 1) * 64;        // 0,64
    const int NK = K / GBK;

    float acc[4][8][4];
#pragma unroll
    for (int a = 0; a < 4; a++)
#pragma unroll
        for (int b = 0; b < 8; b++)
#pragma unroll
            for (int c = 0; c < 4; c++) acc[a][b][c] = 0.f;

#pragma unroll
    for (int s = 0; s < GSTAGES - 1; s++) {
        g_load_stage(Ahi, Alo, Bhi, Blo, bm, bn, K, s, sb + s * GSTAGEB, tid);
        asm volatile("cp.async.commit_group;" ::: "memory");
    }

    for (int kc = 0; kc < NK; kc++) {
        asm volatile("cp.async.wait_group %0;" :: "n"(GSTAGES - 2) : "memory");
        __syncthreads();
        // one barrier per chunk: refill target (kc+2)%3 == (kc-1)%3 was fully
        // consumed before every warp passed the barrier above.
        uint32_t tb = sb + (kc % GSTAGES) * GSTAGEB;

#pragma unroll
        for (int ks = 0; ks < 2; ks++) {
            uint32_t bh[4][4], bl[4][4];
#pragma unroll
            for (int pr = 0; pr < 4; pr++) {
                int row = wn + pr * 16 + (lane & 7) + ((lane >> 4) << 3);
                uint32_t off = sw_off(row, ks * 2 + ((lane >> 3) & 1));
                ldsm_x4(bh[pr], tb + G_BHI + off);
                ldsm_x4(bl[pr], tb + G_BLO + off);
            }
#pragma unroll
            for (int mt = 0; mt < 4; mt++) {
                uint32_t ah[4], al[4];
                int row = wm + mt * 16 + (lane & 15);
                uint32_t off = sw_off(row, ks * 2 + (lane >> 4));
                ldsm_x4(ah, tb + off);
                ldsm_x4(al, tb + G_ALO + off);
#pragma unroll
                for (int nt = 0; nt < 8; nt++) {
                    const uint32_t* bhp = &bh[nt >> 1][(nt & 1) * 2];
                    const uint32_t* blp = &bl[nt >> 1][(nt & 1) * 2];
                    mma_bf16(acc[mt][nt], ah, bhp);
                    mma_bf16(acc[mt][nt], ah, blp);
                    mma_bf16(acc[mt][nt], al, bhp);
                }
            }
        }
        if (kc + GSTAGES - 1 < NK) {
            int pst = (kc + GSTAGES - 1) % GSTAGES;
            g_load_stage(Ahi, Alo, Bhi, Blo, bm, bn, K, kc + GSTAGES - 1, sb + pst * GSTAGEB, tid);
        }
        asm volatile("cp.async.commit_group;" ::: "memory");
    }

#pragma unroll
    for (int mt = 0; mt < 4; mt++) {
        int row0 = bm + wm + mt * 16 + (lane >> 2);
#pragma unroll
        for (int nt = 0; nt < 8; nt++) {
            int col = bn + wn + nt * 8 + (lane & 3) * 2;
            *(float2*)(C + (size_t)row0 * N + col) = make_float2(acc[mt][nt][0], acc[mt][nt][1]);
            *(float2*)(C + (size_t)(row0 + 8) * N + col) = make_float2(acc[mt][nt][2], acc[mt][nt][3]);
        }
    }
}

// ---------------- RoPE table ------------------------------------------------
__global__ void rope_table_kernel() {
    int i = threadIdx.x;
    int t = blockIdx.x;
    double inv = exp(-((double)(2 * i) / 128.0) * log(10000.0));
    double a = (double)t * inv;
    g_cos[t * 64 + i] = (float)cos(a);
    g_sin[t * 64 + i] = (float)sin(a);
}

// ---------------- fused RMSNorm + RoPE (Q and K in one launch) --------------
__global__ __launch_bounds__(128) void rmsnorm_rope_qk(const float* __restrict__ src,
                                                       __nv_bfloat16* __restrict__ qhi,
                                                       __nv_bfloat16* __restrict__ qlo,
                                                       __nv_bfloat16* __restrict__ khi,
                                                       __nv_bfloat16* __restrict__ klo,
                                                       const float* __restrict__ gain) {
    int token = blockIdx.x;
    int hh = blockIdx.y;
    int d = threadIdx.x;
    int s = token & (SEQ - 1);
    bool isQ = hh < NH;
    int coloff = isQ ? hh * HD : DMODEL + (hh - NH) * HD;
    float v = src[(size_t)token * NQKV + coloff + d];

    float ss = v * v;
#pragma unroll
    for (int o = 16; o; o >>= 1) ss += __shfl_xor_sync(0xffffffffu, ss, o);
    __shared__ float ws[4];
    int lane = d & 31, w = d >> 5;
    if (lane == 0) ws[w] = ss;
    __syncthreads();
    float tot = ws[0] + ws[1] + ws[2] + ws[3];
    float inv = rsqrtf(tot * (1.0f / HD) + 1.1920928955078125e-7f);
    v *= inv;

    __shared__ float sv[HD];
    sv[d] = v;
    __syncthreads();

    float out;
    if (d < 64) {
        float c = g_cos[s * 64 + d], si = g_sin[s * 64 + d];
        out = v * c + sv[d + 64] * si;
    } else {
        int i = d - 64;
        float c = g_cos[s * 64 + i], si = g_sin[s * 64 + i];
        out = -sv[i] * si + v * c;
    }
    __nv_bfloat16 hv;
    if (isQ) {
        out *= gain[hh] * 0.08838834764831845f;
        size_t idx = ((size_t)token * NH + hh) * HD + d;
        hv = __float2bfloat16(out);
        qhi[idx] = hv;
        qlo[idx] = __float2bfloat16(out - __bfloat162float(hv));
    } else {
        size_t idx = ((size_t)token * NKV + (hh - NH)) * HD + d;
        hv = __float2bfloat16(out);
        khi[idx] = hv;
        klo[idx] = __float2bfloat16(out - __bfloat162float(hv));
    }
}

// ---------------- tensor-core flash attention (causal, GQA, bf16x3) ---------
#define FBQ 128
#define FBK 64
#define F_QHI 0
#define F_QLO 32768
#define F_STAGE0 65536
#define F_STAGEB 65536
#define F_KH 0
#define F_KL 16384
#define F_VH 32768
#define F_VL 49152
#define FSMEM_TOTAL (65536 + 2*F_STAGEB)

__device__ __forceinline__ uint32_t f_off(int row, int chunk) {
    return (uint32_t)(row * 256 + ((chunk ^ (row & 7)) << 4));
}

__device__ __forceinline__ void f_load_kv(uint32_t st,
                                          const __nv_bfloat16* kh, const __nv_bfloat16* kl,
                                          const __nv_bfloat16* vh, const __nv_bfloat16* vl,
                                          size_t gbase, int tid) {
#pragma unroll
    for (int j = 0; j < 4; j++) {
        int id = tid + j * 256;
        int row = id >> 4, c = id & 15;
        uint32_t so = f_off(row, c);
        size_t g = gbase + (size_t)row * KVD + c * 8;
        CP_ASYNC16(st + F_KH + so, kh + g);
        CP_ASYNC16(st + F_KL + so, kl + g);
        CP_ASYNC16(st + F_VH + so, vh + g);
        CP_ASYNC16(st + F_VL + so, vl + g);
    }
}

__global__ __launch_bounds__(256, 1) void flash_mma(
    const __nv_bfloat16* __restrict__ qh, const __nv_bfloat16* __restrict__ ql,
    const __nv_bfloat16* __restrict__ kh, const __nv_bfloat16* __restrict__ kl,
    const __nv_bfloat16* __restrict__ vh, const __nv_bfloat16* __restrict__ vl,
    __nv_bfloat16* __restrict__ yhi, __nv_bfloat16* __restrict__ ylo) {
    extern __shared__ char smem[];
    uint32_t sb = smem_u32(smem);
    int tid = threadIdx.x, lane = tid & 31, w = tid >> 5;
    int bh_ = blockIdx.y;
    int b = bh_ >> 4, h = bh_ & 15, hkv = h >> 2;
    int qb = (gridDim.x - 1 - blockIdx.x) * FBQ;   // LPT order
    int q0 = w * 16;

#pragma unroll
    for (int j = 0; j < 8; j++) {
        int id = tid + j * 256;
        int row = id >> 4, c = id & 15;
        uint32_t so = f_off(row, c);
        size_t g = ((size_t)(b * SEQ + qb + row)) * DMODEL + h * HD + c * 8;
        CP_ASYNC16(sb + F_QHI + so, qh + g);
        CP_ASYNC16(sb + F_QLO + so, ql + g);
    }
    asm volatile("cp.async.commit_group;" ::: "memory");

    size_t kvhead = (size_t)(b * SEQ) * KVD + hkv * HD;
    int ntiles = qb / FBK + 2;

    f_load_kv(sb + F_STAGE0, kh, kl, vh, vl, kvhead, tid);
    asm volatile("cp.async.commit_group;" ::: "memory");

    asm volatile("cp.async.wait_group 1;" ::: "memory");
    __syncthreads();
    uint32_t qfh[8][4], qfl[8][4];
#pragma unroll
    for (int ds = 0; ds < 8; ds++) {
        uint32_t qoff = f_off(q0 + (lane & 15), ds * 2 + (lane >> 4));
        ldsm_x4(qfh[ds], sb + F_QHI + qoff);
        ldsm_x4(qfl[ds], sb + F_QLO + qoff);
    }

    float o[16][4];
#pragma unroll
    for (int nt = 0; nt < 16; nt++)
#pragma unroll
        for (int e = 0; e < 4; e++) o[nt][e] = 0.f;
    float m0 = -1e30f, m1 = -1e30f, l0 = 0.f, l1 = 0.f;

    int qmax = qb + q0 + 15;
    int rr0 = qb + q0 + (lane >> 2);
    int rr1 = rr0 + 8;

    for (int t = 0; t < ntiles; t++) {
        if (t + 1 < ntiles)
            f_load_kv(sb + F_STAGE0 + ((t + 1) & 1) * F_STAGEB, kh, kl, vh, vl,
                      kvhead + (size_t)(t + 1) * FBK * KVD, tid);
        asm volatile("cp.async.commit_group;" ::: "memory");
        asm volatile("cp.async.wait_group 1;" ::: "memory");
        __syncthreads();

        int kv = t * FBK;
        if (kv <= qmax) {
            uint32_t st = sb + F_STAGE0 + (t & 1) * F_STAGEB;

            float c[8][4];
#pragma unroll
            for (int nt = 0; nt < 8; nt++)
#pragma unroll
                for (int e = 0; e < 4; e++) c[nt][e] = 0.f;

#pragma unroll
            for (int ds = 0; ds < 8; ds++) {
                uint32_t bh4[4][4], bl4[4][4];
#pragma unroll
                for (int g = 0; g < 4; g++) {
                    int rowk = g * 16 + (lane & 7) + ((lane >> 4) << 3);
                    uint32_t koff = f_off(rowk, ds * 2 + ((lane >> 3) & 1));
                    ldsm_x4(bh4[g], st + F_KH + koff);
                    ldsm_x4(bl4[g], st + F_KL + koff);
                }
#pragma unroll
                for (int g = 0; g < 4; g++)
#pragma unroll
                    for (int sub = 0; sub < 2; sub++) {
                        int nt = g * 2 + sub;
                        mma_bf16(c[nt], qfh[ds], &bh4[g][sub * 2]);
                        mma_bf16(c[nt], qfh[ds], &bl4[g][sub * 2]);
                        mma_bf16(c[nt], qfl[ds], &bh4[g][sub * 2]);
                    }
            }

            if (kv + FBK - 1 > qb + q0) {
#pragma unroll
                for (int nt = 0; nt < 8; nt++) {
                    int col = kv + nt * 8 + (lane & 3) * 2;
                    if (col > rr0) c[nt][0] = -1e30f;
                    if (col + 1 > rr0) c[nt][1] = -1e30f;
                    if (col > rr1) c[nt][2] = -1e30f;
                    if (col + 1 > rr1) c[nt][3] = -1e30f;
                }
            }

            float mx0 = -1e30f, mx1 = -1e30f;
#pragma unroll
            for (int nt = 0; nt < 8; nt++) {
                mx0 = fmaxf(mx0, fmaxf(c[nt][0], c[nt][1]));
                mx1 = fmaxf(mx1, fmaxf(c[nt][2], c[nt][3]));
            }
            mx0 = fmaxf(mx0, __shfl_xor_sync(0xffffffffu, mx0, 1));
            mx0 = fmaxf(mx0, __shfl_xor_sync(0xffffffffu, mx0, 2));
            mx1 = fmaxf(mx1, __shfl_xor_sync(0xffffffffu, mx1, 1));
            mx1 = fmaxf(mx1, __shfl_xor_sync(0xffffffffu, mx1, 2));
            float m0n = fmaxf(m0, mx0), m1n = fmaxf(m1, mx1);
            float rs0 = exp2f((m0 - m0n) * LOG2E);
            float rs1 = exp2f((m1 - m1n) * LOG2E);
            float s0 = 0.f, s1 = 0.f;
#pragma unroll
            for (int nt = 0; nt < 8; nt++) {
                c[nt][0] = exp2f((c[nt][0] - m0n) * LOG2E);
                c[nt][1] = exp2f((c[nt][1] - m0n) * LOG2E);
                c[nt][2] = exp2f((c[nt][2] - m1n) * LOG2E);
                c[nt][3] = exp2f((c[nt][3] - m1n) * LOG2E);
                s0 += c[nt][0] + c[nt][1];
                s1 += c[nt][2] + c[nt][3];
            }
            s0 += __shfl_xor_sync(0xffffffffu, s0, 1);
            s0 += __shfl_xor_sync(0xffffffffu, s0, 2);
            s1 += __shfl_xor_sync(0xffffffffu, s1, 1);
            s1 += __shfl_xor_sync(0xffffffffu, s1, 2);
            l0 = l0 * rs0 + s0;
            l1 = l1 * rs1 + s1;
            m0 = m0n; m1 = m1n;
#pragma unroll
            for (int nt = 0; nt < 16; nt++) {
                o[nt][0] *= rs0; o[nt][1] *= rs0;
                o[nt][2] *= rs1; o[nt][3] *= rs1;
            }

#pragma unroll
            for (int kt = 0; kt < 4; kt++) {
                uint32_t aph[4], apl[4];
#pragma unroll
                for (int half = 0; half < 2; half++) {
                    const float* cc = c[2 * kt + half];
#pragma unroll
                    for (int rh = 0; rh < 2; rh++) {
                        float v0 = cc[rh * 2], v1 = cc[rh * 2 + 1];
                        uint32_t hp = pack_bf16x2(v0, v1);
                        __nv_bfloat162 hb;
                        memcpy(&hb, &hp, 4);
                        float r0 = v0 - __bfloat162float(__low2bfloat16(hb));
                        float r1 = v1 - __bfloat162float(__high2bfloat16(hb));
                        aph[half * 2 + rh] = hp;
                        apl[half * 2 + rh] = pack_bf16x2(r0, r1);
                    }
                }
#pragma unroll
                for (int g = 0; g < 8; g++) {
                    int rowv = kt * 16 + (lane & 15);
                    uint32_t voff = f_off(rowv, g * 2 + (lane >> 4));
                    uint32_t vh4[4], vl4[4];
                    ldsm_x4_t(vh4, st + F_VH + voff);
                    ldsm_x4_t(vl4, st + F_VL + voff);
                    mma_bf16(o[2 * g], aph, &vh4[0]);
                    mma_bf16(o[2 * g], aph, &vl4[0]);
                    mma_bf16(o[2 * g], apl, &vh4[0]);
                    mma_bf16(o[2 * g + 1], aph, &vh4[2]);
                    mma_bf16(o[2 * g + 1], aph, &vl4[2]);
                    mma_bf16(o[2 * g + 1], apl, &vh4[2]);
                }
            }
        }
        __syncthreads();
    }

    float iv0 = 1.f / l0, iv1 = 1.f / l1;
    size_t base0 = ((size_t)(b * SEQ) + rr0) * DMODEL + h * HD;
    size_t base1 = base0 + (size_t)8 * DMODEL;
#pragma unroll
    for (int nt = 0; nt < 16; nt++) {
        int d = nt * 8 + (lane & 3) * 2;
        float v0 = o[nt][0] * iv0, v1 = o[nt][1] * iv0;
        float v2 = o[nt][2] * iv1, v3 = o[nt][3] * iv1;
        uint32_t hi0 = pack_bf16x2(v0, v1);
        uint32_t hi1 = pack_bf16x2(v2, v3);
        __nv_bfloat162 hb0, hb1;
        memcpy(&hb0, &hi0, 4);
        memcpy(&hb1, &hi1, 4);
        uint32_t lo0 = pack_bf16x2(v0 - __bfloat162float(__low2bfloat16(hb0)),
                                   v1 - __bfloat162float(__high2bfloat16(hb0)));
        uint32_t lo1 = pack_bf16x2(v2 - __bfloat162float(__low2bfloat16(hb1)),
                                   v3 - __bfloat162float(__high2bfloat16(hb1)));
        *(uint32_t*)(yhi + base0 + d) = hi0;
        *(uint32_t*)(ylo + base0 + d) = lo0;
        *(uint32_t*)(yhi + base1 + d) = hi1;
        *(uint32_t*)(ylo + base1 + d) = lo1;
    }
}

// ---------------------------------------------------------------------------
extern "C" void kernel_launch(void* const* d_in, const int* in_sizes, int n_in,
                              void* d_out, int out_size) {
    const float* x     = (const float*)d_in[0];
    const float* Wq    = (const float*)d_in[1];
    const float* Wk    = (const float*)d_in[2];
    const float* Wv    = (const float*)d_in[3];
    const float* Wproj = (const float*)d_in[4];
    const float* qgain = (const float*)d_in[5];

    float* qkv;
    cudaGetSymbolAddress((void**)&qkv, g_qkv);
    __nv_bfloat16 *xhi, *xlo, *yhi, *ylo, *qh, *ql, *kh, *kl, *vh, *vl;
    __nv_bfloat16 *wch, *wcl, *wph, *wpl;
    cudaGetSymbolAddress((void**)&xhi, g_xhi);  cudaGetSymbolAddress((void**)&xlo, g_xlo);
    cudaGetSymbolAddress((void**)&yhi, g_yhi);  cudaGetSymbolAddress((void**)&ylo, g_ylo);
    cudaGetSymbolAddress((void**)&qh, g_qhi);   cudaGetSymbolAddress((void**)&ql, g_qlo);
    cudaGetSymbolAddress((void**)&kh, g_khi);   cudaGetSymbolAddress((void**)&kl, g_klo);
    cudaGetSymbolAddress((void**)&vh, g_vhi);   cudaGetSymbolAddress((void**)&vl, g_vlo);
    cudaGetSymbolAddress((void**)&wch, g_wchi); cudaGetSymbolAddress((void**)&wcl, g_wclo);
    cudaGetSymbolAddress((void**)&wph, g_wphi); cudaGetSymbolAddress((void**)&wpl, g_wplo);

    cudaFuncSetAttribute(gemm_bf16x3, cudaFuncAttributeMaxDynamicSharedMemorySize, GSMEM_TOTAL);
    cudaFuncSetAttribute(flash_mma, cudaFuncAttributeMaxDynamicSharedMemorySize, FSMEM_TOTAL);

    rope_table_kernel<<<SEQ, 64>>>();

    {
        int n4 = BS * DMODEL / 4;
        split_kernel<<<(n4 + 255) / 256, 256>>>((const float4*)x, (__nv_bfloat162*)xhi, (__nv_bfloat162*)xlo, n4);
        int nw = WC4 + WQ4;
        split_weights<<<(nw + 255) / 256, 256>>>((const float4*)Wq, (const float4*)Wk,
                                                 (const float4*)Wv, (const float4*)Wproj,
                                                 (__nv_bfloat162*)wch, (__nv_bfloat162*)wcl,
                                                 (__nv_bfloat162*)wph, (__nv_bfloat162*)wpl);
    }

    gemm_bf16x3<<<dim3(NQKV / 128, BS / 256), 256, GSMEM_TOTAL>>>(
        xhi, xlo, wch, wcl, qkv, BS, NQKV, DMODEL);

    rmsnorm_rope_qk<<<dim3(BS, NH + NKV), HD>>>(qkv, qh, ql, kh, kl, qgain);
    {
        int n = BS * KVD / 4;
        split_strided<<<(n + 255) / 256, 256>>>(qkv, (__nv_bfloat162*)vh, (__nv_bfloat162*)vl,
                                                BS, KVD, NQKV, DMODEL + KVD);
    }

    flash_mma<<<dim3(SEQ / FBQ, BATCH * NH), 256, FSMEM_TOTAL>>>(qh, ql, kh, kl, vh, vl, yhi, ylo);

    gemm_bf16x3<<<dim3(DMODEL / 128, BS / 256), 256, GSMEM_TOTAL>>>(
        yhi, ylo, wph, wpl, (float*)d_out, BS, DMODEL, DMODEL);
}

// round 11
// speedup vs baseline: 1.3382x; 1.2391x over previous
#include <cuda_runtime.h>
#include <cuda_bf16.h>
#include <cuda_fp16.h>
#include <math.h>
#include <stdint.h>
#include <string.h>

#define BATCH 2
#define SEQ 2048
#define DMODEL 2048
#define NH 16
#define NKV 4
#define HD 128
#define BS (BATCH*SEQ)
#define KVD (NKV*HD)
#define NQKV (DMODEL + 2*KVD)     // 3072
#define LOG2E 1.4426950408889634f

// ---------------- scratch (__device__ globals; no allocs allowed) ----------
__device__ float g_qkv[(size_t)BS*NQKV];
__device__ float g_cos[SEQ*64];
__device__ float g_sin[SEQ*64];

__device__ __half g_xh[(size_t)BS*DMODEL];              // A-side fp16 (single)
__device__ __half g_yh[(size_t)BS*DMODEL];              // attention out fp16
__device__ __half g_wch[(size_t)NQKV*DMODEL];           // [Wq;Wk;Wv] hi
__device__ __half g_wcl[(size_t)NQKV*DMODEL];           // lo
__device__ __half g_wph[(size_t)DMODEL*DMODEL];
__device__ __half g_wpl[(size_t)DMODEL*DMODEL];

__device__ __nv_bfloat16 g_qhi[(size_t)BS*DMODEL];
__device__ __nv_bfloat16 g_qlo[(size_t)BS*DMODEL];
__device__ __nv_bfloat16 g_khi[(size_t)BS*KVD];
__device__ __nv_bfloat16 g_klo[(size_t)BS*KVD];
__device__ __nv_bfloat16 g_vhi[(size_t)BS*KVD];
__device__ __nv_bfloat16 g_vlo[(size_t)BS*KVD];

// ---------------- mma.sync helpers -----------------------------------------
__device__ __forceinline__ uint32_t smem_u32(const void* p) {
    uint32_t a;
    asm("{ .reg .u64 t; cvta.to.shared.u64 t, %1; cvt.u32.u64 %0, t; }" : "=r"(a) : "l"(p));
    return a;
}
__device__ __forceinline__ void ldsm_x4(uint32_t* r, uint32_t addr) {
    asm volatile("ldmatrix.sync.aligned.m8n8.x4.shared.b16 {%0,%1,%2,%3}, [%4];"
                 : "=r"(r[0]), "=r"(r[1]), "=r"(r[2]), "=r"(r[3]) : "r"(addr));
}
__device__ __forceinline__ void ldsm_x4_t(uint32_t* r, uint32_t addr) {
    asm volatile("ldmatrix.sync.aligned.m8n8.x4.trans.shared.b16 {%0,%1,%2,%3}, [%4];"
                 : "=r"(r[0]), "=r"(r[1]), "=r"(r[2]), "=r"(r[3]) : "r"(addr));
}
__device__ __forceinline__ void mma_bf16(float* d, const uint32_t* a, const uint32_t* b) {
    asm volatile("mma.sync.aligned.m16n8k16.row.col.f32.bf16.bf16.f32 "
                 "{%0,%1,%2,%3}, {%4,%5,%6,%7}, {%8,%9}, {%0,%1,%2,%3};"
                 : "+f"(d[0]), "+f"(d[1]), "+f"(d[2]), "+f"(d[3])
                 : "r"(a[0]), "r"(a[1]), "r"(a[2]), "r"(a[3]), "r"(b[0]), "r"(b[1]));
}
__device__ __forceinline__ void mma_f16(float* d, const uint32_t* a, const uint32_t* b) {
    asm volatile("mma.sync.aligned.m16n8k16.row.col.f32.f16.f16.f32 "
                 "{%0,%1,%2,%3}, {%4,%5,%6,%7}, {%8,%9}, {%0,%1,%2,%3};"
                 : "+f"(d[0]), "+f"(d[1]), "+f"(d[2]), "+f"(d[3])
                 : "r"(a[0]), "r"(a[1]), "r"(a[2]), "r"(a[3]), "r"(b[0]), "r"(b[1]));
}
__device__ __forceinline__ uint32_t pack_bf16x2(float v0, float v1) {
    uint32_t r;
    asm("cvt.rn.bf16x2.f32 %0, %1, %2;" : "=r"(r) : "f"(v1), "f"(v0));
    return r;
}
#define CP_ASYNC16(s, g) \
    asm volatile("cp.async.cg.shared.global [%0], [%1], 16;" :: "r"(s), "l"(g))

// ---------------- split kernels ---------------------------------------------
// x -> plain fp16 (A-side of QKV GEMM)
__global__ __launch_bounds__(256) void split_x_h(const float4* __restrict__ src,
                                                 __half2* __restrict__ dst, int n4) {
    int i = blockIdx.x * blockDim.x + threadIdx.x;
    if (i >= n4) return;
    float4 v = src[i];
    dst[2 * i + 0] = __floats2half2_rn(v.x, v.y);
    dst[2 * i + 1] = __floats2half2_rn(v.z, v.w);
}

// weights -> fp16 hi/lo (B-side)
__device__ __forceinline__ void wsplit4(float4 v, __half2* hi, __half2* lo, size_t o2) {
    __half h0 = __float2half_rn(v.x), h1 = __float2half_rn(v.y);
    __half h2 = __float2half_rn(v.z), h3 = __float2half_rn(v.w);
    hi[o2 + 0] = __halves2half2(h0, h1);
    hi[o2 + 1] = __halves2half2(h2, h3);
    lo[o2 + 0] = __halves2half2(__float2half_rn(v.x - __half2float(h0)),
                                __float2half_rn(v.y - __half2float(h1)));
    lo[o2 + 1] = __halves2half2(__float2half_rn(v.z - __half2float(h2)),
                                __float2half_rn(v.w - __half2float(h3)));
}

#define WQ4 (DMODEL*DMODEL/4)
#define WK4 (KVD*DMODEL/4)
#define WC4 (WQ4 + 2*WK4)
__global__ __launch_bounds__(256) void split_weights(const float4* __restrict__ wq,
                                                     const float4* __restrict__ wk,
                                                     const float4* __restrict__ wv,
                                                     const float4* __restrict__ wp,
                                                     __half2* __restrict__ chi,
                                                     __half2* __restrict__ clo,
                                                     __half2* __restrict__ phi,
                                                     __half2* __restrict__ plo) {
    int i = blockIdx.x * blockDim.x + threadIdx.x;
    if (i < WC4) {
        float4 v;
        if (i < WQ4) v = wq[i];
        else if (i < WQ4 + WK4) v = wk[i - WQ4];
        else v = wv[i - WQ4 - WK4];
        wsplit4(v, chi, clo, 2 * (size_t)i);
    } else if (i < WC4 + WQ4) {
        int j = i - WC4;
        wsplit4(wp[j], phi, plo, 2 * (size_t)j);
    }
}

// strided bf16 hi/lo split (V from qkv)
__global__ __launch_bounds__(256) void split_strided(const float* __restrict__ src,
                                                     __nv_bfloat162* __restrict__ hi,
                                                     __nv_bfloat162* __restrict__ lo,
                                                     int rows, int cols, int rstride, int coloff) {
    int i = blockIdx.x * blockDim.x + threadIdx.x;
    int c4 = cols / 4;
    if (i >= rows * c4) return;
    int row = i / c4, cc = (i % c4) * 4;
    float4 v = *(const float4*)(src + (size_t)row * rstride + coloff + cc);
    __nv_bfloat16 h0 = __float2bfloat16(v.x), h1 = __float2bfloat16(v.y);
    __nv_bfloat16 h2 = __float2bfloat16(v.z), h3 = __float2bfloat16(v.w);
    size_t o2 = ((size_t)row * cols + cc) / 2;
    hi[o2 + 0] = __halves2bfloat162(h0, h1);
    hi[o2 + 1] = __halves2bfloat162(h2, h3);
    lo[o2 + 0] = __halves2bfloat162(__float2bfloat16(v.x - __bfloat162float(h0)),
                                    __float2bfloat16(v.y - __bfloat162float(h1)));
    lo[o2 + 1] = __halves2bfloat162(__float2bfloat16(v.z - __bfloat162float(h2)),
                                    __float2bfloat16(v.w - __bfloat162float(h3)));
}

// ---------------- fp16x2 mma.sync GEMM: C[M,N] = A[M,K] @ B[N,K]^T ----------
// A fp16 single, B fp16 hi+lo, 2 MMA passes. 128x128 tile, BK=32, 3 stages,
// 2 CTAs/SM, one barrier per chunk.
#define GSTAGES 3
#define GBK 32
#define GTILEB (128*GBK*2)          // 8KB
#define G_BHI  GTILEB
#define G_BLO  (2*GTILEB)
#define GSTAGEB (3*GTILEB)          // 24KB
#define GSMEM_TOTAL (GSTAGES*GSTAGEB)

__device__ __forceinline__ uint32_t sw_off(int row, int chunk) {
    return (uint32_t)(row * 64 + ((chunk ^ (row & 3)) << 4));
}
__device__ __forceinline__ void g_load_stage(const __half* Ah,
                                             const __half* Bh, const __half* Bl,
                                             int bm, int bn, int K, int kc,
                                             uint32_t tb, int tid) {
    size_t kcol = (size_t)kc * GBK;
#pragma unroll
    for (int j = 0; j < 2; j++) {
        int idx = tid + j * 256;
        int row = idx >> 2, c = idx & 3;
        uint32_t so = sw_off(row, c);
        size_t ga = (size_t)(bm + row) * K + kcol + c * 8;
        size_t gb = (size_t)(bn + row) * K + kcol + c * 8;
        CP_ASYNC16(tb + so, Ah + ga);
        CP_ASYNC16(tb + G_BHI + so, Bh + gb);
        CP_ASYNC16(tb + G_BLO + so, Bl + gb);
    }
}

__global__ __launch_bounds__(256, 2) void gemm_f16x2(
    const __half* __restrict__ Ah,
    const __half* __restrict__ Bh, const __half* __restrict__ Bl,
    float* __restrict__ C, int M, int N, int K) {
    extern __shared__ char smem[];
    uint32_t sb = smem_u32(smem);
    int tid = threadIdx.x, wid = tid >> 5, lane = tid & 31;
    int bm = blockIdx.y * 128, bn = blockIdx.x * 128;
    int wm = (wid >> 2) * 64;
    int wn = (wid & 3) * 32;
    const int NK = K / GBK;

    float acc[4][4][4];
#pragma unroll
    for (int a = 0; a < 4; a++)
#pragma unroll
        for (int b = 0; b < 4; b++)
#pragma unroll
            for (int c = 0; c < 4; c++) acc[a][b][c] = 0.f;

#pragma unroll
    for (int s = 0; s < GSTAGES - 1; s++) {
        g_load_stage(Ah, Bh, Bl, bm, bn, K, s, sb + s * GSTAGEB, tid);
        asm volatile("cp.async.commit_group;" ::: "memory");
    }

    for (int kc = 0; kc < NK; kc++) {
        asm volatile("cp.async.wait_group %0;" :: "n"(GSTAGES - 2) : "memory");
        __syncthreads();
        uint32_t tb = sb + (kc % GSTAGES) * GSTAGEB;

#pragma unroll
        for (int ks = 0; ks < 2; ks++) {
            uint32_t ah[4][4], bh[2][4], bl[2][4];
#pragma unroll
            for (int mt = 0; mt < 4; mt++) {
                int row = wm + mt * 16 + (lane & 15);
                uint32_t off = sw_off(row, ks * 2 + (lane >> 4));
                ldsm_x4(ah[mt], tb + off);
            }
#pragma unroll
            for (int pr = 0; pr < 2; pr++) {
                int row = wn + pr * 16 + (lane & 7) + ((lane >> 4) << 3);
                uint32_t off = sw_off(row, ks * 2 + ((lane >> 3) & 1));
                ldsm_x4(bh[pr], tb + G_BHI + off);
                ldsm_x4(bl[pr], tb + G_BLO + off);
            }
#pragma unroll
            for (int mt = 0; mt < 4; mt++)
#pragma unroll
                for (int nt = 0; nt < 4; nt++) {
                    const uint32_t* bhp = &bh[nt >> 1][(nt & 1) * 2];
                    const uint32_t* blp = &bl[nt >> 1][(nt & 1) * 2];
                    mma_f16(acc[mt][nt], ah[mt], bhp);
                    mma_f16(acc[mt][nt], ah[mt], blp);
                }
        }
        if (kc + GSTAGES - 1 < NK) {
            int pst = (kc + GSTAGES - 1) % GSTAGES;
            g_load_stage(Ah, Bh, Bl, bm, bn, K, kc + GSTAGES - 1, sb + pst * GSTAGEB, tid);
        }
        asm volatile("cp.async.commit_group;" ::: "memory");
    }

#pragma unroll
    for (int mt = 0; mt < 4; mt++) {
        int row0 = bm + wm + mt * 16 + (lane >> 2);
#pragma unroll
        for (int nt = 0; nt < 4; nt++) {
            int col = bn + wn + nt * 8 + (lane & 3) * 2;
            *(float2*)(C + (size_t)row0 * N + col) = make_float2(acc[mt][nt][0], acc[mt][nt][1]);
            *(float2*)(C + (size_t)(row0 + 8) * N + col) = make_float2(acc[mt][nt][2], acc[mt][nt][3]);
        }
    }
}

// ---------------- RoPE table ------------------------------------------------
__global__ void rope_table_kernel() {
    int i = threadIdx.x;
    int t = blockIdx.x;
    double inv = exp(-((double)(2 * i) / 128.0) * log(10000.0));
    double a = (double)t * inv;
    g_cos[t * 64 + i] = (float)cos(a);
    g_sin[t * 64 + i] = (float)sin(a);
}

// ---------------- fused RMSNorm + RoPE (Q and K in one launch) --------------
__global__ __launch_bounds__(128) void rmsnorm_rope_qk(const float* __restrict__ src,
                                                       __nv_bfloat16* __restrict__ qhi,
                                                       __nv_bfloat16* __restrict__ qlo,
                                                       __nv_bfloat16* __restrict__ khi,
                                                       __nv_bfloat16* __restrict__ klo,
                                                       const float* __restrict__ gain) {
    int token = blockIdx.x;
    int hh = blockIdx.y;
    int d = threadIdx.x;
    int s = token & (SEQ - 1);
    bool isQ = hh < NH;
    int coloff = isQ ? hh * HD : DMODEL + (hh - NH) * HD;
    float v = src[(size_t)token * NQKV + coloff + d];

    float ss = v * v;
#pragma unroll
    for (int o = 16; o; o >>= 1) ss += __shfl_xor_sync(0xffffffffu, ss, o);
    __shared__ float ws[4];
    int lane = d & 31, w = d >> 5;
    if (lane == 0) ws[w] = ss;
    __syncthreads();
    float tot = ws[0] + ws[1] + ws[2] + ws[3];
    float inv = rsqrtf(tot * (1.0f / HD) + 1.1920928955078125e-7f);
    v *= inv;

    __shared__ float sv[HD];
    sv[d] = v;
    __syncthreads();

    float out;
    if (d < 64) {
        float c = g_cos[s * 64 + d], si = g_sin[s * 64 + d];
        out = v * c + sv[d + 64] * si;
    } else {
        int i = d - 64;
        float c = g_cos[s * 64 + i], si = g_sin[s * 64 + i];
        out = -sv[i] * si + v * c;
    }
    __nv_bfloat16 hv;
    if (isQ) {
        out *= gain[hh] * 0.08838834764831845f;
        size_t idx = ((size_t)token * NH + hh) * HD + d;
        hv = __float2bfloat16(out);
        qhi[idx] = hv;
        qlo[idx] = __float2bfloat16(out - __bfloat162float(hv));
    } else {
        size_t idx = ((size_t)token * NKV + (hh - NH)) * HD + d;
        hv = __float2bfloat16(out);
        khi[idx] = hv;
        klo[idx] = __float2bfloat16(out - __bfloat162float(hv));
    }
}

// ---------------- tensor-core flash attention (causal, GQA, bf16x3) ---------
#define FBQ 128
#define FBK 64
#define F_QHI 0
#define F_QLO 32768
#define F_STAGE0 65536
#define F_STAGEB 65536
#define F_KH 0
#define F_KL 16384
#define F_VH 32768
#define F_VL 49152
#define FSMEM_TOTAL (65536 + 2*F_STAGEB)

__device__ __forceinline__ uint32_t f_off(int row, int chunk) {
    return (uint32_t)(row * 256 + ((chunk ^ (row & 7)) << 4));
}

__device__ __forceinline__ void f_load_kv(uint32_t st,
                                          const __nv_bfloat16* kh, const __nv_bfloat16* kl,
                                          const __nv_bfloat16* vh, const __nv_bfloat16* vl,
                                          size_t gbase, int tid) {
#pragma unroll
    for (int j = 0; j < 4; j++) {
        int id = tid + j * 256;
        int row = id >> 4, c = id & 15;
        uint32_t so = f_off(row, c);
        size_t g = gbase + (size_t)row * KVD + c * 8;
        CP_ASYNC16(st + F_KH + so, kh + g);
        CP_ASYNC16(st + F_KL + so, kl + g);
        CP_ASYNC16(st + F_VH + so, vh + g);
        CP_ASYNC16(st + F_VL + so, vl + g);
    }
}

__global__ __launch_bounds__(256, 1) void flash_mma(
    const __nv_bfloat16* __restrict__ qh, const __nv_bfloat16* __restrict__ ql,
    const __nv_bfloat16* __restrict__ kh, const __nv_bfloat16* __restrict__ kl,
    const __nv_bfloat16* __restrict__ vh, const __nv_bfloat16* __restrict__ vl,
    __half* __restrict__ yh) {
    extern __shared__ char smem[];
    uint32_t sb = smem_u32(smem);
    int tid = threadIdx.x, lane = tid & 31, w = tid >> 5;
    int bh_ = blockIdx.y;
    int b = bh_ >> 4, h = bh_ & 15, hkv = h >> 2;
    int qb = (gridDim.x - 1 - blockIdx.x) * FBQ;   // LPT order
    int q0 = w * 16;

#pragma unroll
    for (int j = 0; j < 8; j++) {
        int id = tid + j * 256;
        int row = id >> 4, c = id & 15;
        uint32_t so = f_off(row, c);
        size_t g = ((size_t)(b * SEQ + qb + row)) * DMODEL + h * HD + c * 8;
        CP_ASYNC16(sb + F_QHI + so, qh + g);
        CP_ASYNC16(sb + F_QLO + so, ql + g);
    }
    asm volatile("cp.async.commit_group;" ::: "memory");

    size_t kvhead = (size_t)(b * SEQ) * KVD + hkv * HD;
    int ntiles = qb / FBK + 2;

    f_load_kv(sb + F_STAGE0, kh, kl, vh, vl, kvhead, tid);
    asm volatile("cp.async.commit_group;" ::: "memory");

    asm volatile("cp.async.wait_group 1;" ::: "memory");
    __syncthreads();
    uint32_t qfh[8][4], qfl[8][4];
#pragma unroll
    for (int ds = 0; ds < 8; ds++) {
        uint32_t qoff = f_off(q0 + (lane & 15), ds * 2 + (lane >> 4));
        ldsm_x4(qfh[ds], sb + F_QHI + qoff);
        ldsm_x4(qfl[ds], sb + F_QLO + qoff);
    }

    float o[16][4];
#pragma unroll
    for (int nt = 0; nt < 16; nt++)
#pragma unroll
        for (int e = 0; e < 4; e++) o[nt][e] = 0.f;
    float m0 = -1e30f, m1 = -1e30f, l0 = 0.f, l1 = 0.f;

    int qmax = qb + q0 + 15;
    int rr0 = qb + q0 + (lane >> 2);
    int rr1 = rr0 + 8;

    for (int t = 0; t < ntiles; t++) {
        if (t + 1 < ntiles)
            f_load_kv(sb + F_STAGE0 + ((t + 1) & 1) * F_STAGEB, kh, kl, vh, vl,
                      kvhead + (size_t)(t + 1) * FBK * KVD, tid);
        asm volatile("cp.async.commit_group;" ::: "memory");
        asm volatile("cp.async.wait_group 1;" ::: "memory");
        __syncthreads();

        int kv = t * FBK;
        if (kv <= qmax) {
            uint32_t st = sb + F_STAGE0 + (t & 1) * F_STAGEB;

            float c[8][4];
#pragma unroll
            for (int nt = 0; nt < 8; nt++)
#pragma unroll
                for (int e = 0; e < 4; e++) c[nt][e] = 0.f;

#pragma unroll
            for (int ds = 0; ds < 8; ds++) {
                uint32_t bh4[4][4], bl4[4][4];
#pragma unroll
                for (int g = 0; g < 4; g++) {
                    int rowk = g * 16 + (lane & 7) + ((lane >> 4) << 3);
                    uint32_t koff = f_off(rowk, ds * 2 + ((lane >> 3) & 1));
                    ldsm_x4(bh4[g], st + F_KH + koff);
                    ldsm_x4(bl4[g], st + F_KL + koff);
                }
#pragma unroll
                for (int g = 0; g < 4; g++)
#pragma unroll
                    for (int sub = 0; sub < 2; sub++) {
                        int nt = g * 2 + sub;
                        mma_bf16(c[nt], qfh[ds], &bh4[g][sub * 2]);
                        mma_bf16(c[nt], qfh[ds], &bl4[g][sub * 2]);
                        mma_bf16(c[nt], qfl[ds], &bh4[g][sub * 2]);
                    }
            }

            if (kv + FBK - 1 > qb + q0) {
#pragma unroll
                for (int nt = 0; nt < 8; nt++) {
                    int col = kv + nt * 8 + (lane & 3) * 2;
                    if (col > rr0) c[nt][0] = -1e30f;
                    if (col + 1 > rr0) c[nt][1] = -1e30f;
                    if (col > rr1) c[nt][2] = -1e30f;
                    if (col + 1 > rr1) c[nt][3] = -1e30f;
                }
            }

            float mx0 = -1e30f, mx1 = -1e30f;
#pragma unroll
            for (int nt = 0; nt < 8; nt++) {
                mx0 = fmaxf(mx0, fmaxf(c[nt][0], c[nt][1]));
                mx1 = fmaxf(mx1, fmaxf(c[nt][2], c[nt][3]));
            }
            mx0 = fmaxf(mx0, __shfl_xor_sync(0xffffffffu, mx0, 1));
            mx0 = fmaxf(mx0, __shfl_xor_sync(0xffffffffu, mx0, 2));
            mx1 = fmaxf(mx1, __shfl_xor_sync(0xffffffffu, mx1, 1));
            mx1 = fmaxf(mx1, __shfl_xor_sync(0xffffffffu, mx1, 2));
            float m0n = fmaxf(m0, mx0), m1n = fmaxf(m1, mx1);
            float rs0 = exp2f((m0 - m0n) * LOG2E);
            float rs1 = exp2f((m1 - m1n) * LOG2E);
            float s0 = 0.f, s1 = 0.f;
#pragma unroll
            for (int nt = 0; nt < 8; nt++) {
                c[nt][0] = exp2f((c[nt][0] - m0n) * LOG2E);
                c[nt][1] = exp2f((c[nt][1] - m0n) * LOG2E);
                c[nt][2] = exp2f((c[nt][2] - m1n) * LOG2E);
                c[nt][3] = exp2f((c[nt][3] - m1n) * LOG2E);
                s0 += c[nt][0] + c[nt][1];
                s1 += c[nt][2] + c[nt][3];
            }
            s0 += __shfl_xor_sync(0xffffffffu, s0, 1);
            s0 += __shfl_xor_sync(0xffffffffu, s0, 2);
            s1 += __shfl_xor_sync(0xffffffffu, s1, 1);
            s1 += __shfl_xor_sync(0xffffffffu, s1, 2);
            l0 = l0 * rs0 + s0;
            l1 = l1 * rs1 + s1;
            m0 = m0n; m1 = m1n;
#pragma unroll
            for (int nt = 0; nt < 16; nt++) {
                o[nt][0] *= rs0; o[nt][1] *= rs0;
                o[nt][2] *= rs1; o[nt][3] *= rs1;
            }

#pragma unroll
            for (int kt = 0; kt < 4; kt++) {
                uint32_t aph[4], apl[4];
#pragma unroll
                for (int half = 0; half < 2; half++) {
                    const float* cc = c[2 * kt + half];
#pragma unroll
                    for (int rh = 0; rh < 2; rh++) {
                        float v0 = cc[rh * 2], v1 = cc[rh * 2 + 1];
                        uint32_t hp = pack_bf16x2(v0, v1);
                        __nv_bfloat162 hb;
                        memcpy(&hb, &hp, 4);
                        float r0 = v0 - __bfloat162float(__low2bfloat16(hb));
                        float r1 = v1 - __bfloat162float(__high2bfloat16(hb));
                        aph[half * 2 + rh] = hp;
                        apl[half * 2 + rh] = pack_bf16x2(r0, r1);
                    }
                }
#pragma unroll
                for (int g = 0; g < 8; g++) {
                    int rowv = kt * 16 + (lane & 15);
                    uint32_t voff = f_off(rowv, g * 2 + (lane >> 4));
                    uint32_t vh4[4], vl4[4];
                    ldsm_x4_t(vh4, st + F_VH + voff);
                    ldsm_x4_t(vl4, st + F_VL + voff);
                    mma_bf16(o[2 * g], aph, &vh4[0]);
                    mma_bf16(o[2 * g], aph, &vl4[0]);
                    mma_bf16(o[2 * g], apl, &vh4[0]);
                    mma_bf16(o[2 * g + 1], aph, &vh4[2]);
                    mma_bf16(o[2 * g + 1], aph, &vl4[2]);
                    mma_bf16(o[2 * g + 1], apl, &vh4[2]);
                }
            }
        }
        __syncthreads();
    }

    // epilogue: normalize, write fp16 y (A-side of proj GEMM, single precision)
    float iv0 = 1.f / l0, iv1 = 1.f / l1;
    size_t base0 = ((size_t)(b * SEQ) + rr0) * DMODEL + h * HD;
    size_t base1 = base0 + (size_t)8 * DMODEL;
#pragma unroll
    for (int nt = 0; nt < 16; nt++) {
        int d = nt * 8 + (lane & 3) * 2;
        __half2 h0 = __floats2half2_rn(o[nt][0] * iv0, o[nt][1] * iv0);
        __half2 h1 = __floats2half2_rn(o[nt][2] * iv1, o[nt][3] * iv1);
        *(__half2*)(yh + base0 + d) = h0;
        *(__half2*)(yh + base1 + d) = h1;
    }
}

// ---------------------------------------------------------------------------
extern "C" void kernel_launch(void* const* d_in, const int* in_sizes, int n_in,
                              void* d_out, int out_size) {
    const float* x     = (const float*)d_in[0];
    const float* Wq    = (const float*)d_in[1];
    const float* Wk    = (const float*)d_in[2];
    const float* Wv    = (const float*)d_in[3];
    const float* Wproj = (const float*)d_in[4];
    const float* qgain = (const float*)d_in[5];

    float* qkv;
    cudaGetSymbolAddress((void**)&qkv, g_qkv);
    __half *xh, *yh, *wch, *wcl, *wph, *wpl;
    __nv_bfloat16 *qh, *ql, *kh, *kl, *vh, *vl;
    cudaGetSymbolAddress((void**)&xh, g_xh);
    cudaGetSymbolAddress((void**)&yh, g_yh);
    cudaGetSymbolAddress((void**)&wch, g_wch); cudaGetSymbolAddress((void**)&wcl, g_wcl);
    cudaGetSymbolAddress((void**)&wph, g_wph); cudaGetSymbolAddress((void**)&wpl, g_wpl);
    cudaGetSymbolAddress((void**)&qh, g_qhi);  cudaGetSymbolAddress((void**)&ql, g_qlo);
    cudaGetSymbolAddress((void**)&kh, g_khi);  cudaGetSymbolAddress((void**)&kl, g_klo);
    cudaGetSymbolAddress((void**)&vh, g_vhi);  cudaGetSymbolAddress((void**)&vl, g_vlo);

    cudaFuncSetAttribute(gemm_f16x2, cudaFuncAttributeMaxDynamicSharedMemorySize, GSMEM_TOTAL);
    cudaFuncSetAttribute(flash_mma, cudaFuncAttributeMaxDynamicSharedMemorySize, FSMEM_TOTAL);

    rope_table_kernel<<<SEQ, 64>>>();

    {
        int n4 = BS * DMODEL / 4;
        split_x_h<<<(n4 + 255) / 256, 256>>>((const float4*)x, (__half2*)xh, n4);
        int nw = WC4 + WQ4;
        split_weights<<<(nw + 255) / 256, 256>>>((const float4*)Wq, (const float4*)Wk,
                                                 (const float4*)Wv, (const float4*)Wproj,
                                                 (__half2*)wch, (__half2*)wcl,
                                                 (__half2*)wph, (__half2*)wpl);
    }

    // fused QKV projection (fp16x2)
    gemm_f16x2<<<dim3(NQKV / 128, BS / 128), 256, GSMEM_TOTAL>>>(
        xh, wch, wcl, qkv, BS, NQKV, DMODEL);

    rmsnorm_rope_qk<<<dim3(BS, NH + NKV), HD>>>(qkv, qh, ql, kh, kl, qgain);
    {
        int n = BS * KVD / 4;
        split_strided<<<(n + 255) / 256, 256>>>(qkv, (__nv_bfloat162*)vh, (__nv_bfloat162*)vl,
                                                BS, KVD, NQKV, DMODEL + KVD);
    }

    flash_mma<<<dim3(SEQ / FBQ, BATCH * NH), 256, FSMEM_TOTAL>>>(qh, ql, kh, kl, vh, vl, yh);

    // output projection (fp16x2)
    gemm_f16x2<<<dim3(DMODEL / 128, BS / 128), 256, GSMEM_TOTAL>>>(
        yh, wph, wpl, (float*)d_out, BS, DMODEL, DMODEL);
}

// round 12
// speedup vs baseline: 1.5010x; 1.1216x over previous
#include <cuda_runtime.h>
#include <cuda_bf16.h>
#include <cuda_fp16.h>
#include <math.h>
#include <stdint.h>
#include <string.h>

#define BATCH 2
#define SEQ 2048
#define DMODEL 2048
#define NH 16
#define NKV 4
#define HD 128
#define BS (BATCH*SEQ)
#define KVD (NKV*HD)
#define NQKV (DMODEL + 2*KVD)     // 3072
#define LOG2E 1.4426950408889634f

// ---------------- scratch (__device__ globals; no allocs allowed) ----------
__device__ float g_qkv[(size_t)BS*NQKV];
__device__ float g_cos[SEQ*64];
__device__ float g_sin[SEQ*64];

__device__ __half g_xh[(size_t)BS*DMODEL];              // A-side fp16 (single)
__device__ __half g_yh[(size_t)BS*DMODEL];              // attention out fp16
__device__ __half g_wch[(size_t)NQKV*DMODEL];           // [Wq;Wk;Wv] hi
__device__ __half g_wcl[(size_t)NQKV*DMODEL];           // lo
__device__ __half g_wph[(size_t)DMODEL*DMODEL];
__device__ __half g_wpl[(size_t)DMODEL*DMODEL];

__device__ __half g_q16[(size_t)BS*DMODEL];             // Q single fp16
__device__ __half g_k16h[(size_t)BS*KVD];               // K fp16 hi
__device__ __half g_k16l[(size_t)BS*KVD];               // K fp16 lo
__device__ __half g_v16h[(size_t)BS*KVD];
__device__ __half g_v16l[(size_t)BS*KVD];

// ---------------- mma.sync helpers -----------------------------------------
__device__ __forceinline__ uint32_t smem_u32(const void* p) {
    uint32_t a;
    asm("{ .reg .u64 t; cvta.to.shared.u64 t, %1; cvt.u32.u64 %0, t; }" : "=r"(a) : "l"(p));
    return a;
}
__device__ __forceinline__ void ldsm_x4(uint32_t* r, uint32_t addr) {
    asm volatile("ldmatrix.sync.aligned.m8n8.x4.shared.b16 {%0,%1,%2,%3}, [%4];"
                 : "=r"(r[0]), "=r"(r[1]), "=r"(r[2]), "=r"(r[3]) : "r"(addr));
}
__device__ __forceinline__ void ldsm_x4_t(uint32_t* r, uint32_t addr) {
    asm volatile("ldmatrix.sync.aligned.m8n8.x4.trans.shared.b16 {%0,%1,%2,%3}, [%4];"
                 : "=r"(r[0]), "=r"(r[1]), "=r"(r[2]), "=r"(r[3]) : "r"(addr));
}
__device__ __forceinline__ void mma_f16(float* d, const uint32_t* a, const uint32_t* b) {
    asm volatile("mma.sync.aligned.m16n8k16.row.col.f32.f16.f16.f32 "
                 "{%0,%1,%2,%3}, {%4,%5,%6,%7}, {%8,%9}, {%0,%1,%2,%3};"
                 : "+f"(d[0]), "+f"(d[1]), "+f"(d[2]), "+f"(d[3])
                 : "r"(a[0]), "r"(a[1]), "r"(a[2]), "r"(a[3]), "r"(b[0]), "r"(b[1]));
}
__device__ __forceinline__ uint32_t pack_h16x2(float v0, float v1) {
    __half2 h = __floats2half2_rn(v0, v1);
    uint32_t r;
    memcpy(&r, &h, 4);
    return r;
}
#define CP_ASYNC16(s, g) \
    asm volatile("cp.async.cg.shared.global [%0], [%1], 16;" :: "r"(s), "l"(g))

// ---------------- split kernels ---------------------------------------------
__global__ __launch_bounds__(256) void split_x_h(const float4* __restrict__ src,
                                                 __half2* __restrict__ dst, int n4) {
    int i = blockIdx.x * blockDim.x + threadIdx.x;
    if (i >= n4) return;
    float4 v = src[i];
    dst[2 * i + 0] = __floats2half2_rn(v.x, v.y);
    dst[2 * i + 1] = __floats2half2_rn(v.z, v.w);
}

__device__ __forceinline__ void wsplit4(float4 v, __half2* hi, __half2* lo, size_t o2) {
    __half h0 = __float2half_rn(v.x), h1 = __float2half_rn(v.y);
    __half h2 = __float2half_rn(v.z), h3 = __float2half_rn(v.w);
    hi[o2 + 0] = __halves2half2(h0, h1);
    hi[o2 + 1] = __halves2half2(h2, h3);
    lo[o2 + 0] = __halves2half2(__float2half_rn(v.x - __half2float(h0)),
                                __float2half_rn(v.y - __half2float(h1)));
    lo[o2 + 1] = __halves2half2(__float2half_rn(v.z - __half2float(h2)),
                                __float2half_rn(v.w - __half2float(h3)));
}

#define WQ4 (DMODEL*DMODEL/4)
#define WK4 (KVD*DMODEL/4)
#define WC4 (WQ4 + 2*WK4)
__global__ __launch_bounds__(256) void split_weights(const float4* __restrict__ wq,
                                                     const float4* __restrict__ wk,
                                                     const float4* __restrict__ wv,
                                                     const float4* __restrict__ wp,
                                                     __half2* __restrict__ chi,
                                                     __half2* __restrict__ clo,
                                                     __half2* __restrict__ phi,
                                                     __half2* __restrict__ plo) {
    int i = blockIdx.x * blockDim.x + threadIdx.x;
    if (i < WC4) {
        float4 v;
        if (i < WQ4) v = wq[i];
        else if (i < WQ4 + WK4) v = wk[i - WQ4];
        else v = wv[i - WQ4 - WK4];
        wsplit4(v, chi, clo, 2 * (size_t)i);
    } else if (i < WC4 + WQ4) {
        int j = i - WC4;
        wsplit4(wp[j], phi, plo, 2 * (size_t)j);
    }
}

// strided fp16 hi/lo split (V from qkv)
__global__ __launch_bounds__(256) void split_strided_h(const float* __restrict__ src,
                                                       __half2* __restrict__ hi,
                                                       __half2* __restrict__ lo,
                                                       int rows, int cols, int rstride, int coloff) {
    int i = blockIdx.x * blockDim.x + threadIdx.x;
    int c4 = cols / 4;
    if (i >= rows * c4) return;
    int row = i / c4, cc = (i % c4) * 4;
    float4 v = *(const float4*)(src + (size_t)row * rstride + coloff + cc);
    wsplit4(v, hi, lo, ((size_t)row * cols + cc) / 2);
}

// ---------------- fp16x2 mma.sync GEMM: C[M,N] = A[M,K] @ B[N,K]^T ----------
#define GSTAGES 3
#define GBK 32
#define GTILEB (128*GBK*2)          // 8KB
#define G_BHI  GTILEB
#define G_BLO  (2*GTILEB)
#define GSTAGEB (3*GTILEB)          // 24KB
#define GSMEM_TOTAL (GSTAGES*GSTAGEB)

__device__ __forceinline__ uint32_t sw_off(int row, int chunk) {
    return (uint32_t)(row * 64 + ((chunk ^ (row & 3)) << 4));
}
__device__ __forceinline__ void g_load_stage(const __half* Ah,
                                             const __half* Bh, const __half* Bl,
                                             int bm, int bn, int K, int kc,
                                             uint32_t tb, int tid) {
    size_t kcol = (size_t)kc * GBK;
#pragma unroll
    for (int j = 0; j < 2; j++) {
        int idx = tid + j * 256;
        int row = idx >> 2, c = idx & 3;
        uint32_t so = sw_off(row, c);
        size_t ga = (size_t)(bm + row) * K + kcol + c * 8;
        size_t gb = (size_t)(bn + row) * K + kcol + c * 8;
        CP_ASYNC16(tb + so, Ah + ga);
        CP_ASYNC16(tb + G_BHI + so, Bh + gb);
        CP_ASYNC16(tb + G_BLO + so, Bl + gb);
    }
}

__global__ __launch_bounds__(256, 2) void gemm_f16x2(
    const __half* __restrict__ Ah,
    const __half* __restrict__ Bh, const __half* __restrict__ Bl,
    float* __restrict__ C, int M, int N, int K) {
    extern __shared__ char smem[];
    uint32_t sb = smem_u32(smem);
    int tid = threadIdx.x, wid = tid >> 5, lane = tid & 31;
    int bm = blockIdx.y * 128, bn = blockIdx.x * 128;
    int wm = (wid >> 2) * 64;
    int wn = (wid & 3) * 32;
    const int NK = K / GBK;

    float acc[4][4][4];
#pragma unroll
    for (int a = 0; a < 4; a++)
#pragma unroll
        for (int b = 0; b < 4; b++)
#pragma unroll
            for (int c = 0; c < 4; c++) acc[a][b][c] = 0.f;

#pragma unroll
    for (int s = 0; s < GSTAGES - 1; s++) {
        g_load_stage(Ah, Bh, Bl, bm, bn, K, s, sb + s * GSTAGEB, tid);
        asm volatile("cp.async.commit_group;" ::: "memory");
    }

    for (int kc = 0; kc < NK; kc++) {
        asm volatile("cp.async.wait_group %0;" :: "n"(GSTAGES - 2) : "memory");
        __syncthreads();
        uint32_t tb = sb + (kc % GSTAGES) * GSTAGEB;

#pragma unroll
        for (int ks = 0; ks < 2; ks++) {
            uint32_t ah[4][4], bh[2][4], bl[2][4];
#pragma unroll
            for (int mt = 0; mt < 4; mt++) {
                int row = wm + mt * 16 + (lane & 15);
                uint32_t off = sw_off(row, ks * 2 + (lane >> 4));
                ldsm_x4(ah[mt], tb + off);
            }
#pragma unroll
            for (int pr = 0; pr < 2; pr++) {
                int row = wn + pr * 16 + (lane & 7) + ((lane >> 4) << 3);
                uint32_t off = sw_off(row, ks * 2 + ((lane >> 3) & 1));
                ldsm_x4(bh[pr], tb + G_BHI + off);
                ldsm_x4(bl[pr], tb + G_BLO + off);
            }
#pragma unroll
            for (int mt = 0; mt < 4; mt++)
#pragma unroll
                for (int nt = 0; nt < 4; nt++) {
                    const uint32_t* bhp = &bh[nt >> 1][(nt & 1) * 2];
                    const uint32_t* blp = &bl[nt >> 1][(nt & 1) * 2];
                    mma_f16(acc[mt][nt], ah[mt], bhp);
                    mma_f16(acc[mt][nt], ah[mt], blp);
                }
        }
        if (kc + GSTAGES - 1 < NK) {
            int pst = (kc + GSTAGES - 1) % GSTAGES;
            g_load_stage(Ah, Bh, Bl, bm, bn, K, kc + GSTAGES - 1, sb + pst * GSTAGEB, tid);
        }
        asm volatile("cp.async.commit_group;" ::: "memory");
    }

#pragma unroll
    for (int mt = 0; mt < 4; mt++) {
        int row0 = bm + wm + mt * 16 + (lane >> 2);
#pragma unroll
        for (int nt = 0; nt < 4; nt++) {
            int col = bn + wn + nt * 8 + (lane & 3) * 2;
            *(float2*)(C + (size_t)row0 * N + col) = make_float2(acc[mt][nt][0], acc[mt][nt][1]);
            *(float2*)(C + (size_t)(row0 + 8) * N + col) = make_float2(acc[mt][nt][2], acc[mt][nt][3]);
        }
    }
}

// ---------------- RoPE table ------------------------------------------------
__global__ void rope_table_kernel() {
    int i = threadIdx.x;
    int t = blockIdx.x;
    double inv = exp(-((double)(2 * i) / 128.0) * log(10000.0));
    double a = (double)t * inv;
    g_cos[t * 64 + i] = (float)cos(a);
    g_sin[t * 64 + i] = (float)sin(a);
}

// ---------------- fused RMSNorm + RoPE (Q single fp16, K fp16 hi/lo) --------
__global__ __launch_bounds__(128) void rmsnorm_rope_qk(const float* __restrict__ src,
                                                       __half* __restrict__ q16,
                                                       __half* __restrict__ k16h,
                                                       __half* __restrict__ k16l,
                                                       const float* __restrict__ gain) {
    int token = blockIdx.x;
    int hh = blockIdx.y;
    int d = threadIdx.x;
    int s = token & (SEQ - 1);
    bool isQ = hh < NH;
    int coloff = isQ ? hh * HD : DMODEL + (hh - NH) * HD;
    float v = src[(size_t)token * NQKV + coloff + d];

    float ss = v * v;
#pragma unroll
    for (int o = 16; o; o >>= 1) ss += __shfl_xor_sync(0xffffffffu, ss, o);
    __shared__ float ws[4];
    int lane = d & 31, w = d >> 5;
    if (lane == 0) ws[w] = ss;
    __syncthreads();
    float tot = ws[0] + ws[1] + ws[2] + ws[3];
    float inv = rsqrtf(tot * (1.0f / HD) + 1.1920928955078125e-7f);
    v *= inv;

    __shared__ float sv[HD];
    sv[d] = v;
    __syncthreads();

    float out;
    if (d < 64) {
        float c = g_cos[s * 64 + d], si = g_sin[s * 64 + d];
        out = v * c + sv[d + 64] * si;
    } else {
        int i = d - 64;
        float c = g_cos[s * 64 + i], si = g_sin[s * 64 + i];
        out = -sv[i] * si + v * c;
    }
    if (isQ) {
        out *= gain[hh] * 0.08838834764831845f;
        q16[((size_t)token * NH + hh) * HD + d] = __float2half_rn(out);
    } else {
        size_t idx = ((size_t)token * NKV + (hh - NH)) * HD + d;
        __half hv = __float2half_rn(out);
        k16h[idx] = hv;
        k16l[idx] = __float2half_rn(out - __half2float(hv));
    }
}

// ---------------- tensor-core flash attention (causal, GQA, fp16 2-pass) ----
#define FBQ 128
#define FBK 64
#define F_Q 0
#define F_STAGE0 32768
#define F_STAGEB 65536
#define F_KH 0
#define F_KL 16384
#define F_VH 32768
#define F_VL 49152
#define FSMEM_TOTAL (32768 + 2*F_STAGEB)

__device__ __forceinline__ uint32_t f_off(int row, int chunk) {
    return (uint32_t)(row * 256 + ((chunk ^ (row & 7)) << 4));
}

__device__ __forceinline__ void f_load_kv(uint32_t st,
                                          const __half* kh, const __half* kl,
                                          const __half* vh, const __half* vl,
                                          size_t gbase, int tid) {
#pragma unroll
    for (int j = 0; j < 4; j++) {
        int id = tid + j * 256;
        int row = id >> 4, c = id & 15;
        uint32_t so = f_off(row, c);
        size_t g = gbase + (size_t)row * KVD + c * 8;
        CP_ASYNC16(st + F_KH + so, kh + g);
        CP_ASYNC16(st + F_KL + so, kl + g);
        CP_ASYNC16(st + F_VH + so, vh + g);
        CP_ASYNC16(st + F_VL + so, vl + g);
    }
}

__global__ __launch_bounds__(256, 1) void flash_mma(
    const __half* __restrict__ q16,
    const __half* __restrict__ kh, const __half* __restrict__ kl,
    const __half* __restrict__ vh, const __half* __restrict__ vl,
    __half* __restrict__ yh) {
    extern __shared__ char smem[];
    uint32_t sb = smem_u32(smem);
    int tid = threadIdx.x, lane = tid & 31, w = tid >> 5;
    int bh_ = blockIdx.y;
    int b = bh_ >> 4, h = bh_ & 15, hkv = h >> 2;
    int qb = (gridDim.x - 1 - blockIdx.x) * FBQ;   // LPT order
    int q0 = w * 16;

    // ---- Q (fp16 single) -> smem ----
#pragma unroll
    for (int j = 0; j < 8; j++) {
        int id = tid + j * 256;
        int row = id >> 4, c = id & 15;
        uint32_t so = f_off(row, c);
        size_t g = ((size_t)(b * SEQ + qb + row)) * DMODEL + h * HD + c * 8;
        CP_ASYNC16(sb + F_Q + so, q16 + g);
    }
    asm volatile("cp.async.commit_group;" ::: "memory");

    size_t kvhead = (size_t)(b * SEQ) * KVD + hkv * HD;
    int ntiles = qb / FBK + 2;

    f_load_kv(sb + F_STAGE0, kh, kl, vh, vl, kvhead, tid);
    asm volatile("cp.async.commit_group;" ::: "memory");

    // hoist Q fragments (loop-invariant)
    asm volatile("cp.async.wait_group 1;" ::: "memory");
    __syncthreads();
    uint32_t qf[8][4];
#pragma unroll
    for (int ds = 0; ds < 8; ds++) {
        uint32_t qoff = f_off(q0 + (lane & 15), ds * 2 + (lane >> 4));
        ldsm_x4(qf[ds], sb + F_Q + qoff);
    }

    float o[16][4];
#pragma unroll
    for (int nt = 0; nt < 16; nt++)
#pragma unroll
        for (int e = 0; e < 4; e++) o[nt][e] = 0.f;
    float m0 = -1e30f, m1 = -1e30f, l0 = 0.f, l1 = 0.f;

    int qmax = qb + q0 + 15;
    int rr0 = qb + q0 + (lane >> 2);
    int rr1 = rr0 + 8;

    for (int t = 0; t < ntiles; t++) {
        if (t + 1 < ntiles)
            f_load_kv(sb + F_STAGE0 + ((t + 1) & 1) * F_STAGEB, kh, kl, vh, vl,
                      kvhead + (size_t)(t + 1) * FBK * KVD, tid);
        asm volatile("cp.async.commit_group;" ::: "memory");
        asm volatile("cp.async.wait_group 1;" ::: "memory");
        __syncthreads();

        int kv = t * FBK;
        if (kv <= qmax) {
            uint32_t st = sb + F_STAGE0 + (t & 1) * F_STAGEB;

            // ---- S = Q K^T (fp16, 2 passes: K hi + K lo) ----
            float c[8][4];
#pragma unroll
            for (int nt = 0; nt < 8; nt++)
#pragma unroll
                for (int e = 0; e < 4; e++) c[nt][e] = 0.f;

#pragma unroll
            for (int ds = 0; ds < 8; ds++) {
                uint32_t bh4[4][4], bl4[4][4];
#pragma unroll
                for (int g = 0; g < 4; g++) {
                    int rowk = g * 16 + (lane & 7) + ((lane >> 4) << 3);
                    uint32_t koff = f_off(rowk, ds * 2 + ((lane >> 3) & 1));
                    ldsm_x4(bh4[g], st + F_KH + koff);
                    ldsm_x4(bl4[g], st + F_KL + koff);
                }
#pragma unroll
                for (int g = 0; g < 4; g++)
#pragma unroll
                    for (int sub = 0; sub < 2; sub++) {
                        int nt = g * 2 + sub;
                        mma_f16(c[nt], qf[ds], &bh4[g][sub * 2]);
                        mma_f16(c[nt], qf[ds], &bl4[g][sub * 2]);
                    }
            }

            if (kv + FBK - 1 > qb + q0) {
#pragma unroll
                for (int nt = 0; nt < 8; nt++) {
                    int col = kv + nt * 8 + (lane & 3) * 2;
                    if (col > rr0) c[nt][0] = -1e30f;
                    if (col + 1 > rr0) c[nt][1] = -1e30f;
                    if (col > rr1) c[nt][2] = -1e30f;
                    if (col + 1 > rr1) c[nt][3] = -1e30f;
                }
            }

            float mx0 = -1e30f, mx1 = -1e30f;
#pragma unroll
            for (int nt = 0; nt < 8; nt++) {
                mx0 = fmaxf(mx0, fmaxf(c[nt][0], c[nt][1]));
                mx1 = fmaxf(mx1, fmaxf(c[nt][2], c[nt][3]));
            }
            mx0 = fmaxf(mx0, __shfl_xor_sync(0xffffffffu, mx0, 1));
            mx0 = fmaxf(mx0, __shfl_xor_sync(0xffffffffu, mx0, 2));
            mx1 = fmaxf(mx1, __shfl_xor_sync(0xffffffffu, mx1, 1));
            mx1 = fmaxf(mx1, __shfl_xor_sync(0xffffffffu, mx1, 2));
            float m0n = fmaxf(m0, mx0), m1n = fmaxf(m1, mx1);
            float rs0 = exp2f((m0 - m0n) * LOG2E);
            float rs1 = exp2f((m1 - m1n) * LOG2E);
            float s0 = 0.f, s1 = 0.f;
#pragma unroll
            for (int nt = 0; nt < 8; nt++) {
                c[nt][0] = exp2f((c[nt][0] - m0n) * LOG2E);
                c[nt][1] = exp2f((c[nt][1] - m0n) * LOG2E);
                c[nt][2] = exp2f((c[nt][2] - m1n) * LOG2E);
                c[nt][3] = exp2f((c[nt][3] - m1n) * LOG2E);
                s0 += c[nt][0] + c[nt][1];
                s1 += c[nt][2] + c[nt][3];
            }
            s0 += __shfl_xor_sync(0xffffffffu, s0, 1);
            s0 += __shfl_xor_sync(0xffffffffu, s0, 2);
            s1 += __shfl_xor_sync(0xffffffffu, s1, 1);
            s1 += __shfl_xor_sync(0xffffffffu, s1, 2);
            l0 = l0 * rs0 + s0;
            l1 = l1 * rs1 + s1;
            m0 = m0n; m1 = m1n;
#pragma unroll
            for (int nt = 0; nt < 16; nt++) {
                o[nt][0] *= rs0; o[nt][1] *= rs0;
                o[nt][2] *= rs1; o[nt][3] *= rs1;
            }

            // ---- P (fp16 single) x V (fp16 hi/lo, 2 passes) ----
#pragma unroll
            for (int kt = 0; kt < 4; kt++) {
                uint32_t ap[4];
#pragma unroll
                for (int half = 0; half < 2; half++) {
                    const float* cc = c[2 * kt + half];
                    ap[half * 2 + 0] = pack_h16x2(cc[0], cc[1]);
                    ap[half * 2 + 1] = pack_h16x2(cc[2], cc[3]);
                }
#pragma unroll
                for (int g = 0; g < 8; g++) {
                    int rowv = kt * 16 + (lane & 15);
                    uint32_t voff = f_off(rowv, g * 2 + (lane >> 4));
                    uint32_t vh4[4], vl4[4];
                    ldsm_x4_t(vh4, st + F_VH + voff);
                    ldsm_x4_t(vl4, st + F_VL + voff);
                    mma_f16(o[2 * g], ap, &vh4[0]);
                    mma_f16(o[2 * g], ap, &vl4[0]);
                    mma_f16(o[2 * g + 1], ap, &vh4[2]);
                    mma_f16(o[2 * g + 1], ap, &vl4[2]);
                }
            }
        }
        __syncthreads();
    }

    // epilogue: normalize, write fp16 y
    float iv0 = 1.f / l0, iv1 = 1.f / l1;
    size_t base0 = ((size_t)(b * SEQ) + rr0) * DMODEL + h * HD;
    size_t base1 = base0 + (size_t)8 * DMODEL;
#pragma unroll
    for (int nt = 0; nt < 16; nt++) {
        int d = nt * 8 + (lane & 3) * 2;
        __half2 h0 = __floats2half2_rn(o[nt][0] * iv0, o[nt][1] * iv0);
        __half2 h1 = __floats2half2_rn(o[nt][2] * iv1, o[nt][3] * iv1);
        *(__half2*)(yh + base0 + d) = h0;
        *(__half2*)(yh + base1 + d) = h1;
    }
}

// ---------------------------------------------------------------------------
extern "C" void kernel_launch(void* const* d_in, const int* in_sizes, int n_in,
                              void* d_out, int out_size) {
    const float* x     = (const float*)d_in[0];
    const float* Wq    = (const float*)d_in[1];
    const float* Wk    = (const float*)d_in[2];
    const float* Wv    = (const float*)d_in[3];
    const float* Wproj = (const float*)d_in[4];
    const float* qgain = (const float*)d_in[5];

    float* qkv;
    cudaGetSymbolAddress((void**)&qkv, g_qkv);
    __half *xh, *yh, *wch, *wcl, *wph, *wpl;
    __half *q16, *k16h, *k16l, *v16h, *v16l;
    cudaGetSymbolAddress((void**)&xh, g_xh);
    cudaGetSymbolAddress((void**)&yh, g_yh);
    cudaGetSymbolAddress((void**)&wch, g_wch);  cudaGetSymbolAddress((void**)&wcl, g_wcl);
    cudaGetSymbolAddress((void**)&wph, g_wph);  cudaGetSymbolAddress((void**)&wpl, g_wpl);
    cudaGetSymbolAddress((void**)&q16, g_q16);
    cudaGetSymbolAddress((void**)&k16h, g_k16h); cudaGetSymbolAddress((void**)&k16l, g_k16l);
    cudaGetSymbolAddress((void**)&v16h, g_v16h); cudaGetSymbolAddress((void**)&v16l, g_v16l);

    cudaFuncSetAttribute(gemm_f16x2, cudaFuncAttributeMaxDynamicSharedMemorySize, GSMEM_TOTAL);
    cudaFuncSetAttribute(flash_mma, cudaFuncAttributeMaxDynamicSharedMemorySize, FSMEM_TOTAL);

    rope_table_kernel<<<SEQ, 64>>>();

    {
        int n4 = BS * DMODEL / 4;
        split_x_h<<<(n4 + 255) / 256, 256>>>((const float4*)x, (__half2*)xh, n4);
        int nw = WC4 + WQ4;
        split_weights<<<(nw + 255) / 256, 256>>>((const float4*)Wq, (const float4*)Wk,
                                                 (const float4*)Wv, (const float4*)Wproj,
                                                 (__half2*)wch, (__half2*)wcl,
                                                 (__half2*)wph, (__half2*)wpl);
    }

    gemm_f16x2<<<dim3(NQKV / 128, BS / 128), 256, GSMEM_TOTAL>>>(
        xh, wch, wcl, qkv, BS, NQKV, DMODEL);

    rmsnorm_rope_qk<<<dim3(BS, NH + NKV), HD>>>(qkv, q16, k16h, k16l, qgain);
    {
        int n = BS * KVD / 4;
        split_strided_h<<<(n + 255) / 256, 256>>>(qkv, (__half2*)v16h, (__half2*)v16l,
                                                  BS, KVD, NQKV, DMODEL + KVD);
    }

    flash_mma<<<dim3(SEQ / FBQ, BATCH * NH), 256, FSMEM_TOTAL>>>(q16, k16h, k16l, v16h, v16l, yh);

    gemm_f16x2<<<dim3(DMODEL / 128, BS / 128), 256, GSMEM_TOTAL>>>(
        yh, wph, wpl, (float*)d_out, BS, DMODEL, DMODEL);
}

// round 13
// speedup vs baseline: 1.6867x; 1.1237x over previous
#include <cuda_runtime.h>
#include <cuda_bf16.h>
#include <cuda_fp16.h>
#include <math.h>
#include <stdint.h>
#include <string.h>

#define BATCH 2
#define SEQ 2048
#define DMODEL 2048
#define NH 16
#define NKV 4
#define HD 128
#define BS (BATCH*SEQ)
#define KVD (NKV*HD)
#define NQKV (DMODEL + 2*KVD)     // 3072
#define LOG2E 1.4426950408889634f

// ---------------- scratch (__device__ globals; no allocs allowed) ----------
__device__ float g_qkv[(size_t)BS*NQKV];
__device__ float g_cos[SEQ*64];
__device__ float g_sin[SEQ*64];

__device__ __half g_xh[(size_t)BS*DMODEL];
__device__ __half g_yh[(size_t)BS*DMODEL];
__device__ __half g_wch[(size_t)NQKV*DMODEL];           // [Wq;Wk;Wv] single fp16
__device__ __half g_wph[(size_t)DMODEL*DMODEL];
__device__ __half g_wpl[(size_t)DMODEL*DMODEL];

__device__ __half g_q16[(size_t)BS*DMODEL];
__device__ __half g_k16h[(size_t)BS*KVD];
__device__ __half g_k16l[(size_t)BS*KVD];
__device__ __half g_v16h[(size_t)BS*KVD];
__device__ __half g_v16l[(size_t)BS*KVD];

// ---------------- mma.sync helpers -----------------------------------------
__device__ __forceinline__ uint32_t smem_u32(const void* p) {
    uint32_t a;
    asm("{ .reg .u64 t; cvta.to.shared.u64 t, %1; cvt.u32.u64 %0, t; }" : "=r"(a) : "l"(p));
    return a;
}
__device__ __forceinline__ void ldsm_x4(uint32_t* r, uint32_t addr) {
    asm volatile("ldmatrix.sync.aligned.m8n8.x4.shared.b16 {%0,%1,%2,%3}, [%4];"
                 : "=r"(r[0]), "=r"(r[1]), "=r"(r[2]), "=r"(r[3]) : "r"(addr));
}
__device__ __forceinline__ void ldsm_x4_t(uint32_t* r, uint32_t addr) {
    asm volatile("ldmatrix.sync.aligned.m8n8.x4.trans.shared.b16 {%0,%1,%2,%3}, [%4];"
                 : "=r"(r[0]), "=r"(r[1]), "=r"(r[2]), "=r"(r[3]) : "r"(addr));
}
__device__ __forceinline__ void mma_f16(float* d, const uint32_t* a, const uint32_t* b) {
    asm volatile("mma.sync.aligned.m16n8k16.row.col.f32.f16.f16.f32 "
                 "{%0,%1,%2,%3}, {%4,%5,%6,%7}, {%8,%9}, {%0,%1,%2,%3};"
                 : "+f"(d[0]), "+f"(d[1]), "+f"(d[2]), "+f"(d[3])
                 : "r"(a[0]), "r"(a[1]), "r"(a[2]), "r"(a[3]), "r"(b[0]), "r"(b[1]));
}
__device__ __forceinline__ uint32_t pack_h16x2(float v0, float v1) {
    __half2 h = __floats2half2_rn(v0, v1);
    uint32_t r;
    memcpy(&r, &h, 4);
    return r;
}
#define CP_ASYNC16(s, g) \
    asm volatile("cp.async.cg.shared.global [%0], [%1], 16;" :: "r"(s), "l"(g))

// ---------------- split kernels ---------------------------------------------
__global__ __launch_bounds__(256) void split_x_h(const float4* __restrict__ src,
                                                 __half2* __restrict__ dst, int n4) {
    int i = blockIdx.x * blockDim.x + threadIdx.x;
    if (i >= n4) return;
    float4 v = src[i];
    dst[2 * i + 0] = __floats2half2_rn(v.x, v.y);
    dst[2 * i + 1] = __floats2half2_rn(v.z, v.w);
}

__device__ __forceinline__ void wsplit4(float4 v, __half2* hi, __half2* lo, size_t o2) {
    __half h0 = __float2half_rn(v.x), h1 = __float2half_rn(v.y);
    __half h2 = __float2half_rn(v.z), h3 = __float2half_rn(v.w);
    hi[o2 + 0] = __halves2half2(h0, h1);
    hi[o2 + 1] = __halves2half2(h2, h3);
    lo[o2 + 0] = __halves2half2(__float2half_rn(v.x - __half2float(h0)),
                                __float2half_rn(v.y - __half2float(h1)));
    lo[o2 + 1] = __halves2half2(__float2half_rn(v.z - __half2float(h2)),
                                __float2half_rn(v.w - __half2float(h3)));
}

// QKV weights -> single fp16 ; Wproj -> fp16 hi/lo
#define WQ4 (DMODEL*DMODEL/4)
#define WK4 (KVD*DMODEL/4)
#define WC4 (WQ4 + 2*WK4)
__global__ __launch_bounds__(256) void split_weights(const float4* __restrict__ wq,
                                                     const float4* __restrict__ wk,
                                                     const float4* __restrict__ wv,
                                                     const float4* __restrict__ wp,
                                                     __half2* __restrict__ ch,
                                                     __half2* __restrict__ phi,
                                                     __half2* __restrict__ plo) {
    int i = blockIdx.x * blockDim.x + threadIdx.x;
    if (i < WC4) {
        float4 v;
        if (i < WQ4) v = wq[i];
        else if (i < WQ4 + WK4) v = wk[i - WQ4];
        else v = wv[i - WQ4 - WK4];
        ch[2 * i + 0] = __floats2half2_rn(v.x, v.y);
        ch[2 * i + 1] = __floats2half2_rn(v.z, v.w);
    } else if (i < WC4 + WQ4) {
        int j = i - WC4;
        wsplit4(wp[j], phi, plo, 2 * (size_t)j);
    }
}

// ---------------- fp16 mma.sync GEMM (PASSES=1 or 2): C = A @ B^T -----------
#define GSTAGES 3
#define GBK 32
#define GTILEB (128*GBK*2)          // 8KB

__device__ __forceinline__ uint32_t sw_off(int row, int chunk) {
    return (uint32_t)(row * 64 + ((chunk ^ (row & 3)) << 4));
}

template<int PASSES>
__global__ __launch_bounds__(256, 2) void gemm_f16(
    const __half* __restrict__ Ah,
    const __half* __restrict__ Bh, const __half* __restrict__ Bl,
    float* __restrict__ C, int M, int N, int K) {
    extern __shared__ char smem[];
    const int NTILES = 1 + PASSES;                 // A + Bhi (+ Blo)
    const uint32_t STAGEB = NTILES * GTILEB;
    uint32_t sb = smem_u32(smem);
    int tid = threadIdx.x, wid = tid >> 5, lane = tid & 31;
    int bm = blockIdx.y * 128, bn = blockIdx.x * 128;
    int wm = (wid >> 2) * 64;
    int wn = (wid & 3) * 32;
    const int NK = K / GBK;

    float acc[4][4][4];
#pragma unroll
    for (int a = 0; a < 4; a++)
#pragma unroll
        for (int b = 0; b < 4; b++)
#pragma unroll
            for (int c = 0; c < 4; c++) acc[a][b][c] = 0.f;

    auto load_stage = [&](int kc, uint32_t tb) {
        size_t kcol = (size_t)kc * GBK;
#pragma unroll
        for (int j = 0; j < 2; j++) {
            int idx = tid + j * 256;
            int row = idx >> 2, c = idx & 3;
            uint32_t so = sw_off(row, c);
            size_t ga = (size_t)(bm + row) * K + kcol + c * 8;
            size_t gb = (size_t)(bn + row) * K + kcol + c * 8;
            CP_ASYNC16(tb + so, Ah + ga);
            CP_ASYNC16(tb + GTILEB + so, Bh + gb);
            if (PASSES == 2) CP_ASYNC16(tb + 2 * GTILEB + so, Bl + gb);
        }
    };

#pragma unroll
    for (int s = 0; s < GSTAGES - 1; s++) {
        load_stage(s, sb + s * STAGEB);
        asm volatile("cp.async.commit_group;" ::: "memory");
    }

    for (int kc = 0; kc < NK; kc++) {
        asm volatile("cp.async.wait_group %0;" :: "n"(GSTAGES - 2) : "memory");
        __syncthreads();
        uint32_t tb = sb + (kc % GSTAGES) * STAGEB;

#pragma unroll
        for (int ks = 0; ks < 2; ks++) {
            uint32_t ah[4][4], bh[2][4], bl[2][4];
#pragma unroll
            for (int mt = 0; mt < 4; mt++) {
                int row = wm + mt * 16 + (lane & 15);
                uint32_t off = sw_off(row, ks * 2 + (lane >> 4));
                ldsm_x4(ah[mt], tb + off);
            }
#pragma unroll
            for (int pr = 0; pr < 2; pr++) {
                int row = wn + pr * 16 + (lane & 7) + ((lane >> 4) << 3);
                uint32_t off = sw_off(row, ks * 2 + ((lane >> 3) & 1));
                ldsm_x4(bh[pr], tb + GTILEB + off);
                if (PASSES == 2) ldsm_x4(bl[pr], tb + 2 * GTILEB + off);
            }
#pragma unroll
            for (int mt = 0; mt < 4; mt++)
#pragma unroll
                for (int nt = 0; nt < 4; nt++) {
                    mma_f16(acc[mt][nt], ah[mt], &bh[nt >> 1][(nt & 1) * 2]);
                    if (PASSES == 2)
                        mma_f16(acc[mt][nt], ah[mt], &bl[nt >> 1][(nt & 1) * 2]);
                }
        }
        if (kc + GSTAGES - 1 < NK) {
            int pst = (kc + GSTAGES - 1) % GSTAGES;
            load_stage(kc + GSTAGES - 1, sb + pst * STAGEB);
        }
        asm volatile("cp.async.commit_group;" ::: "memory");
    }

#pragma unroll
    for (int mt = 0; mt < 4; mt++) {
        int row0 = bm + wm + mt * 16 + (lane >> 2);
#pragma unroll
        for (int nt = 0; nt < 4; nt++) {
            int col = bn + wn + nt * 8 + (lane & 3) * 2;
            *(float2*)(C + (size_t)row0 * N + col) = make_float2(acc[mt][nt][0], acc[mt][nt][1]);
            *(float2*)(C + (size_t)(row0 + 8) * N + col) = make_float2(acc[mt][nt][2], acc[mt][nt][3]);
        }
    }
}

// ---------------- RoPE table ------------------------------------------------
__global__ void rope_table_kernel() {
    int i = threadIdx.x;
    int t = blockIdx.x;
    double inv = exp(-((double)(2 * i) / 128.0) * log(10000.0));
    double a = (double)t * inv;
    g_cos[t * 64 + i] = (float)cos(a);
    g_sin[t * 64 + i] = (float)sin(a);
}

// --------- fused RMSNorm+RoPE for Q/K + plain hi/lo convert for V -----------
// grid.y: [0,NH) Q | [NH,NH+NKV) K | [NH+NKV, NH+2*NKV) V
__global__ __launch_bounds__(128) void rmsnorm_rope_qkv(const float* __restrict__ src,
                                                        __half* __restrict__ q16,
                                                        __half* __restrict__ k16h,
                                                        __half* __restrict__ k16l,
                                                        __half* __restrict__ v16h,
                                                        __half* __restrict__ v16l,
                                                        const float* __restrict__ gain) {
    int token = blockIdx.x;
    int hh = blockIdx.y;
    int d = threadIdx.x;

    if (hh >= NH + NKV) {                      // V: plain fp16 hi/lo convert
        int vh_ = hh - NH - NKV;
        float v = src[(size_t)token * NQKV + DMODEL + KVD + vh_ * HD + d];
        size_t idx = ((size_t)token * NKV + vh_) * HD + d;
        __half hv = __float2half_rn(v);
        v16h[idx] = hv;
        v16l[idx] = __float2half_rn(v - __half2float(hv));
        return;
    }

    int s = token & (SEQ - 1);
    bool isQ = hh < NH;
    int coloff = isQ ? hh * HD : DMODEL + (hh - NH) * HD;
    float v = src[(size_t)token * NQKV + coloff + d];

    float ss = v * v;
#pragma unroll
    for (int o = 16; o; o >>= 1) ss += __shfl_xor_sync(0xffffffffu, ss, o);
    __shared__ float ws[4];
    int lane = d & 31, w = d >> 5;
    if (lane == 0) ws[w] = ss;
    __syncthreads();
    float tot = ws[0] + ws[1] + ws[2] + ws[3];
    float inv = rsqrtf(tot * (1.0f / HD) + 1.1920928955078125e-7f);
    v *= inv;

    __shared__ float sv[HD];
    sv[d] = v;
    __syncthreads();

    float out;
    if (d < 64) {
        float c = g_cos[s * 64 + d], si = g_sin[s * 64 + d];
        out = v * c + sv[d + 64] * si;
    } else {
        int i = d - 64;
        float c = g_cos[s * 64 + i], si = g_sin[s * 64 + i];
        out = -sv[i] * si + v * c;
    }
    if (isQ) {
        out *= gain[hh] * 0.08838834764831845f;
        q16[((size_t)token * NH + hh) * HD + d] = __float2half_rn(out);
    } else {
        size_t idx = ((size_t)token * NKV + (hh - NH)) * HD + d;
        __half hv = __float2half_rn(out);
        k16h[idx] = hv;
        k16l[idx] = __float2half_rn(out - __half2float(hv));
    }
}

// ---------------- tensor-core flash attention (causal, GQA, fp16 2-pass) ----
#define FBQ 128
#define FBK 64
#define F_Q 0
#define F_STAGE0 32768
#define F_STAGEB 65536
#define F_KH 0
#define F_KL 16384
#define F_VH 32768
#define F_VL 49152
#define FSMEM_TOTAL (32768 + 2*F_STAGEB)

__device__ __forceinline__ uint32_t f_off(int row, int chunk) {
    return (uint32_t)(row * 256 + ((chunk ^ (row & 7)) << 4));
}

__device__ __forceinline__ void f_load_kv(uint32_t st,
                                          const __half* kh, const __half* kl,
                                          const __half* vh, const __half* vl,
                                          size_t gbase, int tid) {
#pragma unroll
    for (int j = 0; j < 4; j++) {
        int id = tid + j * 256;
        int row = id >> 4, c = id & 15;
        uint32_t so = f_off(row, c);
        size_t g = gbase + (size_t)row * KVD + c * 8;
        CP_ASYNC16(st + F_KH + so, kh + g);
        CP_ASYNC16(st + F_KL + so, kl + g);
        CP_ASYNC16(st + F_VH + so, vh + g);
        CP_ASYNC16(st + F_VL + so, vl + g);
    }
}

__global__ __launch_bounds__(256, 1) void flash_mma(
    const __half* __restrict__ q16,
    const __half* __restrict__ kh, const __half* __restrict__ kl,
    const __half* __restrict__ vh, const __half* __restrict__ vl,
    __half* __restrict__ yh) {
    extern __shared__ char smem[];
    uint32_t sb = smem_u32(smem);
    int tid = threadIdx.x, lane = tid & 31, w = tid >> 5;
    int bh_ = blockIdx.y;
    int b = bh_ >> 4, h = bh_ & 15, hkv = h >> 2;
    int qb = (gridDim.x - 1 - blockIdx.x) * FBQ;   // LPT order
    int q0 = w * 16;

#pragma unroll
    for (int j = 0; j < 8; j++) {
        int id = tid + j * 256;
        int row = id >> 4, c = id & 15;
        uint32_t so = f_off(row, c);
        size_t g = ((size_t)(b * SEQ + qb + row)) * DMODEL + h * HD + c * 8;
        CP_ASYNC16(sb + F_Q + so, q16 + g);
    }
    asm volatile("cp.async.commit_group;" ::: "memory");

    size_t kvhead = (size_t)(b * SEQ) * KVD + hkv * HD;
    int ntiles = qb / FBK + 2;

    f_load_kv(sb + F_STAGE0, kh, kl, vh, vl, kvhead, tid);
    asm volatile("cp.async.commit_group;" ::: "memory");

    asm volatile("cp.async.wait_group 1;" ::: "memory");
    __syncthreads();
    uint32_t qf[8][4];
#pragma unroll
    for (int ds = 0; ds < 8; ds++) {
        uint32_t qoff = f_off(q0 + (lane & 15), ds * 2 + (lane >> 4));
        ldsm_x4(qf[ds], sb + F_Q + qoff);
    }

    float o[16][4];
#pragma unroll
    for (int nt = 0; nt < 16; nt++)
#pragma unroll
        for (int e = 0; e < 4; e++) o[nt][e] = 0.f;
    float m0 = -1e30f, m1 = -1e30f, l0 = 0.f, l1 = 0.f;

    int qmax = qb + q0 + 15;
    int rr0 = qb + q0 + (lane >> 2);
    int rr1 = rr0 + 8;

    for (int t = 0; t < ntiles; t++) {
        if (t + 1 < ntiles)
            f_load_kv(sb + F_STAGE0 + ((t + 1) & 1) * F_STAGEB, kh, kl, vh, vl,
                      kvhead + (size_t)(t + 1) * FBK * KVD, tid);
        asm volatile("cp.async.commit_group;" ::: "memory");
        asm volatile("cp.async.wait_group 1;" ::: "memory");
        __syncthreads();

        int kv = t * FBK;
        if (kv <= qmax) {
            uint32_t st = sb + F_STAGE0 + (t & 1) * F_STAGEB;

            float c[8][4];
#pragma unroll
            for (int nt = 0; nt < 8; nt++)
#pragma unroll
                for (int e = 0; e < 4; e++) c[nt][e] = 0.f;

#pragma unroll
            for (int ds = 0; ds < 8; ds++) {
                uint32_t bh4[4][4], bl4[4][4];
#pragma unroll
                for (int g = 0; g < 4; g++) {
                    int rowk = g * 16 + (lane & 7) + ((lane >> 4) << 3);
                    uint32_t koff = f_off(rowk, ds * 2 + ((lane >> 3) & 1));
                    ldsm_x4(bh4[g], st + F_KH + koff);
                    ldsm_x4(bl4[g], st + F_KL + koff);
                }
#pragma unroll
                for (int g = 0; g < 4; g++)
#pragma unroll
                    for (int sub = 0; sub < 2; sub++) {
                        int nt = g * 2 + sub;
                        mma_f16(c[nt], qf[ds], &bh4[g][sub * 2]);
                        mma_f16(c[nt], qf[ds], &bl4[g][sub * 2]);
                    }
            }

            if (kv + FBK - 1 > qb + q0) {
#pragma unroll
                for (int nt = 0; nt < 8; nt++) {
                    int col = kv + nt * 8 + (lane & 3) * 2;
                    if (col > rr0) c[nt][0] = -1e30f;
                    if (col + 1 > rr0) c[nt][1] = -1e30f;
                    if (col > rr1) c[nt][2] = -1e30f;
                    if (col + 1 > rr1) c[nt][3] = -1e30f;
                }
            }

            float mx0 = -1e30f, mx1 = -1e30f;
#pragma unroll
            for (int nt = 0; nt < 8; nt++) {
                mx0 = fmaxf(mx0, fmaxf(c[nt][0], c[nt][1]));
                mx1 = fmaxf(mx1, fmaxf(c[nt][2], c[nt][3]));
            }
            mx0 = fmaxf(mx0, __shfl_xor_sync(0xffffffffu, mx0, 1));
            mx0 = fmaxf(mx0, __shfl_xor_sync(0xffffffffu, mx0, 2));
            mx1 = fmaxf(mx1, __shfl_xor_sync(0xffffffffu, mx1, 1));
            mx1 = fmaxf(mx1, __shfl_xor_sync(0xffffffffu, mx1, 2));
            float m0n = fmaxf(m0, mx0), m1n = fmaxf(m1, mx1);
            float rs0 = exp2f((m0 - m0n) * LOG2E);
            float rs1 = exp2f((m1 - m1n) * LOG2E);
            float s0 = 0.f, s1 = 0.f;
#pragma unroll
            for (int nt = 0; nt < 8; nt++) {
                c[nt][0] = exp2f((c[nt][0] - m0n) * LOG2E);
                c[nt][1] = exp2f((c[nt][1] - m0n) * LOG2E);
                c[nt][2] = exp2f((c[nt][2] - m1n) * LOG2E);
                c[nt][3] = exp2f((c[nt][3] - m1n) * LOG2E);
                s0 += c[nt][0] + c[nt][1];
                s1 += c[nt][2] + c[nt][3];
            }
            s0 += __shfl_xor_sync(0xffffffffu, s0, 1);
            s0 += __shfl_xor_sync(0xffffffffu, s0, 2);
            s1 += __shfl_xor_sync(0xffffffffu, s1, 1);
            s1 += __shfl_xor_sync(0xffffffffu, s1, 2);
            l0 = l0 * rs0 + s0;
            l1 = l1 * rs1 + s1;
            m0 = m0n; m1 = m1n;
#pragma unroll
            for (int nt = 0; nt < 16; nt++) {
                o[nt][0] *= rs0; o[nt][1] *= rs0;
                o[nt][2] *= rs1; o[nt][3] *= rs1;
            }

#pragma unroll
            for (int kt = 0; kt < 4; kt++) {
                uint32_t ap[4];
#pragma unroll
                for (int half = 0; half < 2; half++) {
                    const float* cc = c[2 * kt + half];
                    ap[half * 2 + 0] = pack_h16x2(cc[0], cc[1]);
                    ap[half * 2 + 1] = pack_h16x2(cc[2], cc[3]);
                }
#pragma unroll
                for (int g = 0; g < 8; g++) {
                    int rowv = kt * 16 + (lane & 15);
                    uint32_t voff = f_off(rowv, g * 2 + (lane >> 4));
                    uint32_t vh4[4], vl4[4];
                    ldsm_x4_t(vh4, st + F_VH + voff);
                    ldsm_x4_t(vl4, st + F_VL + voff);
                    mma_f16(o[2 * g], ap, &vh4[0]);
                    mma_f16(o[2 * g], ap, &vl4[0]);
                    mma_f16(o[2 * g + 1], ap, &vh4[2]);
                    mma_f16(o[2 * g + 1], ap, &vl4[2]);
                }
            }
        }
        __syncthreads();
    }

    float iv0 = 1.f / l0, iv1 = 1.f / l1;
    size_t base0 = ((size_t)(b * SEQ) + rr0) * DMODEL + h * HD;
    size_t base1 = base0 + (size_t)8 * DMODEL;
#pragma unroll
    for (int nt = 0; nt < 16; nt++) {
        int d = nt * 8 + (lane & 3) * 2;
        __half2 h0 = __floats2half2_rn(o[nt][0] * iv0, o[nt][1] * iv0);
        __half2 h1 = __floats2half2_rn(o[nt][2] * iv1, o[nt][3] * iv1);
        *(__half2*)(yh + base0 + d) = h0;
        *(__half2*)(yh + base1 + d) = h1;
    }
}

// ---------------------------------------------------------------------------
extern "C" void kernel_launch(void* const* d_in, const int* in_sizes, int n_in,
                              void* d_out, int out_size) {
    const float* x     = (const float*)d_in[0];
    const float* Wq    = (const float*)d_in[1];
    const float* Wk    = (const float*)d_in[2];
    const float* Wv    = (const float*)d_in[3];
    const float* Wproj = (const float*)d_in[4];
    const float* qgain = (const float*)d_in[5];

    float* qkv;
    cudaGetSymbolAddress((void**)&qkv, g_qkv);
    __half *xh, *yh, *wch, *wph, *wpl;
    __half *q16, *k16h, *k16l, *v16h, *v16l;
    cudaGetSymbolAddress((void**)&xh, g_xh);
    cudaGetSymbolAddress((void**)&yh, g_yh);
    cudaGetSymbolAddress((void**)&wch, g_wch);
    cudaGetSymbolAddress((void**)&wph, g_wph);  cudaGetSymbolAddress((void**)&wpl, g_wpl);
    cudaGetSymbolAddress((void**)&q16, g_q16);
    cudaGetSymbolAddress((void**)&k16h, g_k16h); cudaGetSymbolAddress((void**)&k16l, g_k16l);
    cudaGetSymbolAddress((void**)&v16h, g_v16h); cudaGetSymbolAddress((void**)&v16l, g_v16l);

    const int SM1 = GSTAGES * 2 * GTILEB;   // 48KB  (single-pass)
    const int SM2 = GSTAGES * 3 * GTILEB;   // 72KB  (2-pass)
    cudaFuncSetAttribute(gemm_f16<1>, cudaFuncAttributeMaxDynamicSharedMemorySize, SM1);
    cudaFuncSetAttribute(gemm_f16<2>, cudaFuncAttributeMaxDynamicSharedMemorySize, SM2);
    cudaFuncSetAttribute(flash_mma, cudaFuncAttributeMaxDynamicSharedMemorySize, FSMEM_TOTAL);

    rope_table_kernel<<<SEQ, 64>>>();

    {
        int n4 = BS * DMODEL / 4;
        split_x_h<<<(n4 + 255) / 256, 256>>>((const float4*)x, (__half2*)xh, n4);
        int nw = WC4 + WQ4;
        split_weights<<<(nw + 255) / 256, 256>>>((const float4*)Wq, (const float4*)Wk,
                                                 (const float4*)Wv, (const float4*)Wproj,
                                                 (__half2*)wch, (__half2*)wph, (__half2*)wpl);
    }

    // fused QKV projection — single-pass fp16
    gemm_f16<1><<<dim3(NQKV / 128, BS / 128), 256, SM1>>>(
        xh, wch, nullptr, qkv, BS, NQKV, DMODEL);

    // Q/K norm+rope + V convert, one launch
    rmsnorm_rope_qkv<<<dim3(BS, NH + 2 * NKV), HD>>>(qkv, q16, k16h, k16l, v16h, v16l, qgain);

    flash_mma<<<dim3(SEQ / FBQ, BATCH * NH), 256, FSMEM_TOTAL>>>(q16, k16h, k16l, v16h, v16l, yh);

    // output projection — 2-pass fp16 (keeps error budget)
    gemm_f16<2><<<dim3(DMODEL / 128, BS / 128), 256, SM2>>>(
        yh, wph, wpl, (float*)d_out, BS, DMODEL, DMODEL);
}

// round 14
// speedup vs baseline: 1.7355x; 1.0289x over previous
#include <cuda_runtime.h>
#include <cuda_bf16.h>
#include <cuda_fp16.h>
#include <math.h>
#include <stdint.h>
#include <string.h>

#define BATCH 2
#define SEQ 2048
#define DMODEL 2048
#define NH 16
#define NKV 4
#define HD 128
#define BS (BATCH*SEQ)
#define KVD (NKV*HD)
#define NQKV (DMODEL + 2*KVD)     // 3072
#define LOG2E 1.4426950408889634f

// ---------------- scratch (__device__ globals; no allocs allowed) ----------
__device__ float g_qkv[(size_t)BS*NQKV];
__device__ float g_cos[SEQ*64];
__device__ float g_sin[SEQ*64];

__device__ __half g_xh[(size_t)BS*DMODEL];
__device__ __half g_yh[(size_t)BS*DMODEL];
__device__ __half g_wch[(size_t)NQKV*DMODEL];           // [Wq;Wk;Wv] single fp16
__device__ __half g_wph[(size_t)DMODEL*DMODEL];
__device__ __half g_wpl[(size_t)DMODEL*DMODEL];

__device__ __half g_q16[(size_t)BS*DMODEL];
__device__ __half g_k16h[(size_t)BS*KVD];
__device__ __half g_k16l[(size_t)BS*KVD];
__device__ __half g_v16h[(size_t)BS*KVD];
__device__ __half g_v16l[(size_t)BS*KVD];

// ---------------- mma.sync helpers -----------------------------------------
__device__ __forceinline__ uint32_t smem_u32(const void* p) {
    uint32_t a;
    asm("{ .reg .u64 t; cvta.to.shared.u64 t, %1; cvt.u32.u64 %0, t; }" : "=r"(a) : "l"(p));
    return a;
}
__device__ __forceinline__ void ldsm_x4(uint32_t* r, uint32_t addr) {
    asm volatile("ldmatrix.sync.aligned.m8n8.x4.shared.b16 {%0,%1,%2,%3}, [%4];"
                 : "=r"(r[0]), "=r"(r[1]), "=r"(r[2]), "=r"(r[3]) : "r"(addr));
}
__device__ __forceinline__ void ldsm_x4_t(uint32_t* r, uint32_t addr) {
    asm volatile("ldmatrix.sync.aligned.m8n8.x4.trans.shared.b16 {%0,%1,%2,%3}, [%4];"
                 : "=r"(r[0]), "=r"(r[1]), "=r"(r[2]), "=r"(r[3]) : "r"(addr));
}
__device__ __forceinline__ void mma_f16(float* d, const uint32_t* a, const uint32_t* b) {
    asm volatile("mma.sync.aligned.m16n8k16.row.col.f32.f16.f16.f32 "
                 "{%0,%1,%2,%3}, {%4,%5,%6,%7}, {%8,%9}, {%0,%1,%2,%3};"
                 : "+f"(d[0]), "+f"(d[1]), "+f"(d[2]), "+f"(d[3])
                 : "r"(a[0]), "r"(a[1]), "r"(a[2]), "r"(a[3]), "r"(b[0]), "r"(b[1]));
}
__device__ __forceinline__ uint32_t pack_h16x2(float v0, float v1) {
    __half2 h = __floats2half2_rn(v0, v1);
    uint32_t r;
    memcpy(&r, &h, 4);
    return r;
}
#define CP_ASYNC16(s, g) \
    asm volatile("cp.async.cg.shared.global [%0], [%1], 16;" :: "r"(s), "l"(g))

// ---------------- split kernels ---------------------------------------------
__global__ __launch_bounds__(256) void split_x_h(const float4* __restrict__ src,
                                                 __half2* __restrict__ dst, int n4) {
    int i = blockIdx.x * blockDim.x + threadIdx.x;
    if (i >= n4) return;
    float4 v = src[i];
    dst[2 * i + 0] = __floats2half2_rn(v.x, v.y);
    dst[2 * i + 1] = __floats2half2_rn(v.z, v.w);
}

__device__ __forceinline__ void wsplit4(float4 v, __half2* hi, __half2* lo, size_t o2) {
    __half h0 = __float2half_rn(v.x), h1 = __float2half_rn(v.y);
    __half h2 = __float2half_rn(v.z), h3 = __float2half_rn(v.w);
    hi[o2 + 0] = __halves2half2(h0, h1);
    hi[o2 + 1] = __halves2half2(h2, h3);
    lo[o2 + 0] = __halves2half2(__float2half_rn(v.x - __half2float(h0)),
                                __float2half_rn(v.y - __half2float(h1)));
    lo[o2 + 1] = __halves2half2(__float2half_rn(v.z - __half2float(h2)),
                                __float2half_rn(v.w - __half2float(h3)));
}

#define WQ4 (DMODEL*DMODEL/4)
#define WK4 (KVD*DMODEL/4)
#define WC4 (WQ4 + 2*WK4)
__global__ __launch_bounds__(256) void split_weights(const float4* __restrict__ wq,
                                                     const float4* __restrict__ wk,
                                                     const float4* __restrict__ wv,
                                                     const float4* __restrict__ wp,
                                                     __half2* __restrict__ ch,
                                                     __half2* __restrict__ phi,
                                                     __half2* __restrict__ plo) {
    int i = blockIdx.x * blockDim.x + threadIdx.x;
    if (i < WC4) {
        float4 v;
        if (i < WQ4) v = wq[i];
        else if (i < WQ4 + WK4) v = wk[i - WQ4];
        else v = wv[i - WQ4 - WK4];
        ch[2 * i + 0] = __floats2half2_rn(v.x, v.y);
        ch[2 * i + 1] = __floats2half2_rn(v.z, v.w);
    } else if (i < WC4 + WQ4) {
        int j = i - WC4;
        wsplit4(wp[j], phi, plo, 2 * (size_t)j);
    }
}

__device__ __forceinline__ uint32_t sw_off(int row, int chunk) {
    return (uint32_t)(row * 64 + ((chunk ^ (row & 3)) << 4));
}

// ------- single-pass fp16 GEMM, 256x128 CTA tile, 8 warps of 64x64 ---------
#define GSTAGES 3
#define GBK 32
#define BA_SZ (256*GBK*2)           // 16KB A tile
#define BB_SZ (128*GBK*2)           // 8KB B tile
#define BSTAGEB (BA_SZ + BB_SZ)     // 24KB
#define BSMEM_TOTAL (GSTAGES*BSTAGEB)

__global__ __launch_bounds__(256, 1) void gemm_f16_1p(
    const __half* __restrict__ Ah, const __half* __restrict__ Bh,
    float* __restrict__ C, int M, int N, int K) {
    extern __shared__ char smem[];
    uint32_t sb = smem_u32(smem);
    int tid = threadIdx.x, wid = tid >> 5, lane = tid & 31;
    int bm = blockIdx.y * 256, bn = blockIdx.x * 128;
    int wm = (wid >> 1) * 64;
    int wn = (wid & 1) * 64;
    const int NK = K / GBK;

    float acc[4][8][4];
#pragma unroll
    for (int a = 0; a < 4; a++)
#pragma unroll
        for (int b = 0; b < 8; b++)
#pragma unroll
            for (int c = 0; c < 4; c++) acc[a][b][c] = 0.f;

    auto load_stage = [&](int kc, uint32_t tb) {
        size_t kcol = (size_t)kc * GBK;
#pragma unroll
        for (int j = 0; j < 4; j++) {          // A: 256 rows
            int idx = tid + j * 256;
            int row = idx >> 2, c = idx & 3;
            CP_ASYNC16(tb + sw_off(row, c), Ah + (size_t)(bm + row) * K + kcol + c * 8);
        }
#pragma unroll
        for (int j = 0; j < 2; j++) {          // B: 128 rows
            int idx = tid + j * 256;
            int row = idx >> 2, c = idx & 3;
            CP_ASYNC16(tb + BA_SZ + sw_off(row, c), Bh + (size_t)(bn + row) * K + kcol + c * 8);
        }
    };

#pragma unroll
    for (int s = 0; s < GSTAGES - 1; s++) {
        load_stage(s, sb + s * BSTAGEB);
        asm volatile("cp.async.commit_group;" ::: "memory");
    }

    for (int kc = 0; kc < NK; kc++) {
        asm volatile("cp.async.wait_group %0;" :: "n"(GSTAGES - 2) : "memory");
        __syncthreads();
        uint32_t tb = sb + (kc % GSTAGES) * BSTAGEB;

#pragma unroll
        for (int ks = 0; ks < 2; ks++) {
            uint32_t bh[4][4];
#pragma unroll
            for (int pr = 0; pr < 4; pr++) {
                int row = wn + pr * 16 + (lane & 7) + ((lane >> 4) << 3);
                ldsm_x4(bh[pr], tb + BA_SZ + sw_off(row, ks * 2 + ((lane >> 3) & 1)));
            }
#pragma unroll
            for (int mt = 0; mt < 4; mt++) {
                uint32_t ah[4];
                int row = wm + mt * 16 + (lane & 15);
                ldsm_x4(ah, tb + sw_off(row, ks * 2 + (lane >> 4)));
#pragma unroll
                for (int nt = 0; nt < 8; nt++)
                    mma_f16(acc[mt][nt], ah, &bh[nt >> 1][(nt & 1) * 2]);
            }
        }
        if (kc + GSTAGES - 1 < NK) {
            int pst = (kc + GSTAGES - 1) % GSTAGES;
            load_stage(kc + GSTAGES - 1, sb + pst * BSTAGEB);
        }
        asm volatile("cp.async.commit_group;" ::: "memory");
    }

#pragma unroll
    for (int mt = 0; mt < 4; mt++) {
        int row0 = bm + wm + mt * 16 + (lane >> 2);
#pragma unroll
        for (int nt = 0; nt < 8; nt++) {
            int col = bn + wn + nt * 8 + (lane & 3) * 2;
            *(float2*)(C + (size_t)row0 * N + col) = make_float2(acc[mt][nt][0], acc[mt][nt][1]);
            *(float2*)(C + (size_t)(row0 + 8) * N + col) = make_float2(acc[mt][nt][2], acc[mt][nt][3]);
        }
    }
}

// ------- 2-pass fp16 GEMM (proj), 128x128 tile, 2 CTAs/SM -------------------
#define GTILEB (128*GBK*2)
#define G2STAGEB (3*GTILEB)
#define G2SMEM (GSTAGES*G2STAGEB)

__global__ __launch_bounds__(256, 2) void gemm_f16_2p(
    const __half* __restrict__ Ah,
    const __half* __restrict__ Bh, const __half* __restrict__ Bl,
    float* __restrict__ C, int M, int N, int K) {
    extern __shared__ char smem[];
    uint32_t sb = smem_u32(smem);
    int tid = threadIdx.x, wid = tid >> 5, lane = tid & 31;
    int bm = blockIdx.y * 128, bn = blockIdx.x * 128;
    int wm = (wid >> 2) * 64;
    int wn = (wid & 3) * 32;
    const int NK = K / GBK;

    float acc[4][4][4];
#pragma unroll
    for (int a = 0; a < 4; a++)
#pragma unroll
        for (int b = 0; b < 4; b++)
#pragma unroll
            for (int c = 0; c < 4; c++) acc[a][b][c] = 0.f;

    auto load_stage = [&](int kc, uint32_t tb) {
        size_t kcol = (size_t)kc * GBK;
#pragma unroll
        for (int j = 0; j < 2; j++) {
            int idx = tid + j * 256;
            int row = idx >> 2, c = idx & 3;
            uint32_t so = sw_off(row, c);
            size_t ga = (size_t)(bm + row) * K + kcol + c * 8;
            size_t gb = (size_t)(bn + row) * K + kcol + c * 8;
            CP_ASYNC16(tb + so, Ah + ga);
            CP_ASYNC16(tb + GTILEB + so, Bh + gb);
            CP_ASYNC16(tb + 2 * GTILEB + so, Bl + gb);
        }
    };

#pragma unroll
    for (int s = 0; s < GSTAGES - 1; s++) {
        load_stage(s, sb + s * G2STAGEB);
        asm volatile("cp.async.commit_group;" ::: "memory");
    }

    for (int kc = 0; kc < NK; kc++) {
        asm volatile("cp.async.wait_group %0;" :: "n"(GSTAGES - 2) : "memory");
        __syncthreads();
        uint32_t tb = sb + (kc % GSTAGES) * G2STAGEB;

#pragma unroll
        for (int ks = 0; ks < 2; ks++) {
            uint32_t ah[4][4], bh[2][4], bl[2][4];
#pragma unroll
            for (int mt = 0; mt < 4; mt++) {
                int row = wm + mt * 16 + (lane & 15);
                ldsm_x4(ah[mt], tb + sw_off(row, ks * 2 + (lane >> 4)));
            }
#pragma unroll
            for (int pr = 0; pr < 2; pr++) {
                int row = wn + pr * 16 + (lane & 7) + ((lane >> 4) << 3);
                uint32_t off = sw_off(row, ks * 2 + ((lane >> 3) & 1));
                ldsm_x4(bh[pr], tb + GTILEB + off);
                ldsm_x4(bl[pr], tb + 2 * GTILEB + off);
            }
#pragma unroll
            for (int mt = 0; mt < 4; mt++)
#pragma unroll
                for (int nt = 0; nt < 4; nt++) {
                    mma_f16(acc[mt][nt], ah[mt], &bh[nt >> 1][(nt & 1) * 2]);
                    mma_f16(acc[mt][nt], ah[mt], &bl[nt >> 1][(nt & 1) * 2]);
                }
        }
        if (kc + GSTAGES - 1 < NK) {
            int pst = (kc + GSTAGES - 1) % GSTAGES;
            load_stage(kc + GSTAGES - 1, sb + pst * G2STAGEB);
        }
        asm volatile("cp.async.commit_group;" ::: "memory");
    }

#pragma unroll
    for (int mt = 0; mt < 4; mt++) {
        int row0 = bm + wm + mt * 16 + (lane >> 2);
#pragma unroll
        for (int nt = 0; nt < 4; nt++) {
            int col = bn + wn + nt * 8 + (lane & 3) * 2;
            *(float2*)(C + (size_t)row0 * N + col) = make_float2(acc[mt][nt][0], acc[mt][nt][1]);
            *(float2*)(C + (size_t)(row0 + 8) * N + col) = make_float2(acc[mt][nt][2], acc[mt][nt][3]);
        }
    }
}

// ---------------- RoPE table ------------------------------------------------
__global__ void rope_table_kernel() {
    int i = threadIdx.x;
    int t = blockIdx.x;
    double inv = exp(-((double)(2 * i) / 128.0) * log(10000.0));
    double a = (double)t * inv;
    g_cos[t * 64 + i] = (float)cos(a);
    g_sin[t * 64 + i] = (float)sin(a);
}

// --------- fused RMSNorm+RoPE for Q/K + plain hi/lo convert for V -----------
__global__ __launch_bounds__(128) void rmsnorm_rope_qkv(const float* __restrict__ src,
                                                        __half* __restrict__ q16,
                                                        __half* __restrict__ k16h,
                                                        __half* __restrict__ k16l,
                                                        __half* __restrict__ v16h,
                                                        __half* __restrict__ v16l,
                                                        const float* __restrict__ gain) {
    int token = blockIdx.x;
    int hh = blockIdx.y;
    int d = threadIdx.x;

    if (hh >= NH + NKV) {
        int vh_ = hh - NH - NKV;
        float v = src[(size_t)token * NQKV + DMODEL + KVD + vh_ * HD + d];
        size_t idx = ((size_t)token * NKV + vh_) * HD + d;
        __half hv = __float2half_rn(v);
        v16h[idx] = hv;
        v16l[idx] = __float2half_rn(v - __half2float(hv));
        return;
    }

    int s = token & (SEQ - 1);
    bool isQ = hh < NH;
    int coloff = isQ ? hh * HD : DMODEL + (hh - NH) * HD;
    float v = src[(size_t)token * NQKV + coloff + d];

    float ss = v * v;
#pragma unroll
    for (int o = 16; o; o >>= 1) ss += __shfl_xor_sync(0xffffffffu, ss, o);
    __shared__ float ws[4];
    int lane = d & 31, w = d >> 5;
    if (lane == 0) ws[w] = ss;
    __syncthreads();
    float tot = ws[0] + ws[1] + ws[2] + ws[3];
    float inv = rsqrtf(tot * (1.0f / HD) + 1.1920928955078125e-7f);
    v *= inv;

    __shared__ float sv[HD];
    sv[d] = v;
    __syncthreads();

    float out;
    if (d < 64) {
        float c = g_cos[s * 64 + d], si = g_sin[s * 64 + d];
        out = v * c + sv[d + 64] * si;
    } else {
        int i = d - 64;
        float c = g_cos[s * 64 + i], si = g_sin[s * 64 + i];
        out = -sv[i] * si + v * c;
    }
    if (isQ) {
        out *= gain[hh] * 0.08838834764831845f;
        q16[((size_t)token * NH + hh) * HD + d] = __float2half_rn(out);
    } else {
        size_t idx = ((size_t)token * NKV + (hh - NH)) * HD + d;
        __half hv = __float2half_rn(out);
        k16h[idx] = hv;
        k16l[idx] = __float2half_rn(out - __half2float(hv));
    }
}

// ---------------- tensor-core flash attention (causal, GQA, fp16 2-pass) ----
#define FBQ 128
#define FBK 64
#define F_Q 0
#define F_STAGE0 32768
#define F_STAGEB 65536
#define F_KH 0
#define F_KL 16384
#define F_VH 32768
#define F_VL 49152
#define FSMEM_TOTAL (32768 + 2*F_STAGEB)

__device__ __forceinline__ uint32_t f_off(int row, int chunk) {
    return (uint32_t)(row * 256 + ((chunk ^ (row & 7)) << 4));
}

__device__ __forceinline__ void f_load_kv(uint32_t st,
                                          const __half* kh, const __half* kl,
                                          const __half* vh, const __half* vl,
                                          size_t gbase, int tid) {
#pragma unroll
    for (int j = 0; j < 4; j++) {
        int id = tid + j * 256;
        int row = id >> 4, c = id & 15;
        uint32_t so = f_off(row, c);
        size_t g = gbase + (size_t)row * KVD + c * 8;
        CP_ASYNC16(st + F_KH + so, kh + g);
        CP_ASYNC16(st + F_KL + so, kl + g);
        CP_ASYNC16(st + F_VH + so, vh + g);
        CP_ASYNC16(st + F_VL + so, vl + g);
    }
}

__global__ __launch_bounds__(256, 1) void flash_mma(
    const __half* __restrict__ q16,
    const __half* __restrict__ kh, const __half* __restrict__ kl,
    const __half* __restrict__ vh, const __half* __restrict__ vl,
    __half* __restrict__ yh) {
    extern __shared__ char smem[];
    uint32_t sb = smem_u32(smem);
    int tid = threadIdx.x, lane = tid & 31, w = tid >> 5;
    int bh_ = blockIdx.y;
    int b = bh_ >> 4, h = bh_ & 15, hkv = h >> 2;
    int qb = (gridDim.x - 1 - blockIdx.x) * FBQ;
    int q0 = w * 16;

#pragma unroll
    for (int j = 0; j < 8; j++) {
        int id = tid + j * 256;
        int row = id >> 4, c = id & 15;
        uint32_t so = f_off(row, c);
        size_t g = ((size_t)(b * SEQ + qb + row)) * DMODEL + h * HD + c * 8;
        CP_ASYNC16(sb + F_Q + so, q16 + g);
    }
    asm volatile("cp.async.commit_group;" ::: "memory");

    size_t kvhead = (size_t)(b * SEQ) * KVD + hkv * HD;
    int ntiles = qb / FBK + 2;

    f_load_kv(sb + F_STAGE0, kh, kl, vh, vl, kvhead, tid);
    asm volatile("cp.async.commit_group;" ::: "memory");

    asm volatile("cp.async.wait_group 1;" ::: "memory");
    __syncthreads();
    uint32_t qf[8][4];
#pragma unroll
    for (int ds = 0; ds < 8; ds++) {
        uint32_t qoff = f_off(q0 + (lane & 15), ds * 2 + (lane >> 4));
        ldsm_x4(qf[ds], sb + F_Q + qoff);
    }

    float o[16][4];
#pragma unroll
    for (int nt = 0; nt < 16; nt++)
#pragma unroll
        for (int e = 0; e < 4; e++) o[nt][e] = 0.f;
    float m0 = -1e30f, m1 = -1e30f, l0 = 0.f, l1 = 0.f;

    int qmax = qb + q0 + 15;
    int rr0 = qb + q0 + (lane >> 2);
    int rr1 = rr0 + 8;

    for (int t = 0; t < ntiles; t++) {
        if (t + 1 < ntiles)
            f_load_kv(sb + F_STAGE0 + ((t + 1) & 1) * F_STAGEB, kh, kl, vh, vl,
                      kvhead + (size_t)(t + 1) * FBK * KVD, tid);
        asm volatile("cp.async.commit_group;" ::: "memory");
        asm volatile("cp.async.wait_group 1;" ::: "memory");
        __syncthreads();

        int kv = t * FBK;
        if (kv <= qmax) {
            uint32_t st = sb + F_STAGE0 + (t & 1) * F_STAGEB;

            float c[8][4];
#pragma unroll
            for (int nt = 0; nt < 8; nt++)
#pragma unroll
                for (int e = 0; e < 4; e++) c[nt][e] = 0.f;

#pragma unroll
            for (int ds = 0; ds < 8; ds++) {
                uint32_t bh4[4][4], bl4[4][4];
#pragma unroll
                for (int g = 0; g < 4; g++) {
                    int rowk = g * 16 + (lane & 7) + ((lane >> 4) << 3);
                    uint32_t koff = f_off(rowk, ds * 2 + ((lane >> 3) & 1));
                    ldsm_x4(bh4[g], st + F_KH + koff);
                    ldsm_x4(bl4[g], st + F_KL + koff);
                }
#pragma unroll
                for (int g = 0; g < 4; g++)
#pragma unroll
                    for (int sub = 0; sub < 2; sub++) {
                        int nt = g * 2 + sub;
                        mma_f16(c[nt], qf[ds], &bh4[g][sub * 2]);
                        mma_f16(c[nt], qf[ds], &bl4[g][sub * 2]);
                    }
            }

            if (kv + FBK - 1 > qb + q0) {
#pragma unroll
                for (int nt = 0; nt < 8; nt++) {
                    int col = kv + nt * 8 + (lane & 3) * 2;
                    if (col > rr0) c[nt][0] = -1e30f;
                    if (col + 1 > rr0) c[nt][1] = -1e30f;
                    if (col > rr1) c[nt][2] = -1e30f;
                    if (col + 1 > rr1) c[nt][3] = -1e30f;
                }
            }

            float mx0 = -1e30f, mx1 = -1e30f;
#pragma unroll
            for (int nt = 0; nt < 8; nt++) {
                mx0 = fmaxf(mx0, fmaxf(c[nt][0], c[nt][1]));
                mx1 = fmaxf(mx1, fmaxf(c[nt][2], c[nt][3]));
            }
            mx0 = fmaxf(mx0, __shfl_xor_sync(0xffffffffu, mx0, 1));
            mx0 = fmaxf(mx0, __shfl_xor_sync(0xffffffffu, mx0, 2));
            mx1 = fmaxf(mx1, __shfl_xor_sync(0xffffffffu, mx1, 1));
            mx1 = fmaxf(mx1, __shfl_xor_sync(0xffffffffu, mx1, 2));
            float m0n = fmaxf(m0, mx0), m1n = fmaxf(m1, mx1);
            float rs0 = exp2f((m0 - m0n) * LOG2E);
            float rs1 = exp2f((m1 - m1n) * LOG2E);
            float s0 = 0.f, s1 = 0.f;
#pragma unroll
            for (int nt = 0; nt < 8; nt++) {
                c[nt][0] = exp2f((c[nt][0] - m0n) * LOG2E);
                c[nt][1] = exp2f((c[nt][1] - m0n) * LOG2E);
                c[nt][2] = exp2f((c[nt][2] - m1n) * LOG2E);
                c[nt][3] = exp2f((c[nt][3] - m1n) * LOG2E);
                s0 += c[nt][0] + c[nt][1];
                s1 += c[nt][2] + c[nt][3];
            }
            s0 += __shfl_xor_sync(0xffffffffu, s0, 1);
            s0 += __shfl_xor_sync(0xffffffffu, s0, 2);
            s1 += __shfl_xor_sync(0xffffffffu, s1, 1);
            s1 += __shfl_xor_sync(0xffffffffu, s1, 2);
            l0 = l0 * rs0 + s0;
            l1 = l1 * rs1 + s1;
            m0 = m0n; m1 = m1n;
#pragma unroll
            for (int nt = 0; nt < 16; nt++) {
                o[nt][0] *= rs0; o[nt][1] *= rs0;
                o[nt][2] *= rs1; o[nt][3] *= rs1;
            }

#pragma unroll
            for (int kt = 0; kt < 4; kt++) {
                uint32_t ap[4];
#pragma unroll
                for (int half = 0; half < 2; half++) {
                    const float* cc = c[2 * kt + half];
                    ap[half * 2 + 0] = pack_h16x2(cc[0], cc[1]);
                    ap[half * 2 + 1] = pack_h16x2(cc[2], cc[3]);
                }
#pragma unroll
                for (int g = 0; g < 8; g++) {
                    int rowv = kt * 16 + (lane & 15);
                    uint32_t voff = f_off(rowv, g * 2 + (lane >> 4));
                    uint32_t vh4[4], vl4[4];
                    ldsm_x4_t(vh4, st + F_VH + voff);
                    ldsm_x4_t(vl4, st + F_VL + voff);
                    mma_f16(o[2 * g], ap, &vh4[0]);
                    mma_f16(o[2 * g], ap, &vl4[0]);
                    mma_f16(o[2 * g + 1], ap, &vh4[2]);
                    mma_f16(o[2 * g + 1], ap, &vl4[2]);
                }
            }
        }
        __syncthreads();
    }

    float iv0 = 1.f / l0, iv1 = 1.f / l1;
    size_t base0 = ((size_t)(b * SEQ) + rr0) * DMODEL + h * HD;
    size_t base1 = base0 + (size_t)8 * DMODEL;
#pragma unroll
    for (int nt = 0; nt < 16; nt++) {
        int d = nt * 8 + (lane & 3) * 2;
        __half2 h0 = __floats2half2_rn(o[nt][0] * iv0, o[nt][1] * iv0);
        __half2 h1 = __floats2half2_rn(o[nt][2] * iv1, o[nt][3] * iv1);
        *(__half2*)(yh + base0 + d) = h0;
        *(__half2*)(yh + base1 + d) = h1;
    }
}

// ---------------------------------------------------------------------------
extern "C" void kernel_launch(void* const* d_in, const int* in_sizes, int n_in,
                              void* d_out, int out_size) {
    const float* x     = (const float*)d_in[0];
    const float* Wq    = (const float*)d_in[1];
    const float* Wk    = (const float*)d_in[2];
    const float* Wv    = (const float*)d_in[3];
    const float* Wproj = (const float*)d_in[4];
    const float* qgain = (const float*)d_in[5];

    float* qkv;
    cudaGetSymbolAddress((void**)&qkv, g_qkv);
    __half *xh, *yh, *wch, *wph, *wpl;
    __half *q16, *k16h, *k16l, *v16h, *v16l;
    cudaGetSymbolAddress((void**)&xh, g_xh);
    cudaGetSymbolAddress((void**)&yh, g_yh);
    cudaGetSymbolAddress((void**)&wch, g_wch);
    cudaGetSymbolAddress((void**)&wph, g_wph);  cudaGetSymbolAddress((void**)&wpl, g_wpl);
    cudaGetSymbolAddress((void**)&q16, g_q16);
    cudaGetSymbolAddress((void**)&k16h, g_k16h); cudaGetSymbolAddress((void**)&k16l, g_k16l);
    cudaGetSymbolAddress((void**)&v16h, g_v16h); cudaGetSymbolAddress((void**)&v16l, g_v16l);

    cudaFuncSetAttribute(gemm_f16_1p, cudaFuncAttributeMaxDynamicSharedMemorySize, BSMEM_TOTAL);
    cudaFuncSetAttribute(gemm_f16_2p, cudaFuncAttributeMaxDynamicSharedMemorySize, G2SMEM);
    cudaFuncSetAttribute(flash_mma, cudaFuncAttributeMaxDynamicSharedMemorySize, FSMEM_TOTAL);

    rope_table_kernel<<<SEQ, 64>>>();

    {
        int n4 = BS * DMODEL / 4;
        split_x_h<<<(n4 + 255) / 256, 256>>>((const float4*)x, (__half2*)xh, n4);
        int nw = WC4 + WQ4;
        split_weights<<<(nw + 255) / 256, 256>>>((const float4*)Wq, (const float4*)Wk,
                                                 (const float4*)Wv, (const float4*)Wproj,
                                                 (__half2*)wch, (__half2*)wph, (__half2*)wpl);
    }

    // fused QKV projection — single-pass fp16, 256x128 tile
    gemm_f16_1p<<<dim3(NQKV / 128, BS / 256), 256, BSMEM_TOTAL>>>(
        xh, wch, qkv, BS, NQKV, DMODEL);

    rmsnorm_rope_qkv<<<dim3(BS, NH + 2 * NKV), HD>>>(qkv, q16, k16h, k16l, v16h, v16l, qgain);

    flash_mma<<<dim3(SEQ / FBQ, BATCH * NH), 256, FSMEM_TOTAL>>>(q16, k16h, k16l, v16h, v16l, yh);

    // output projection — 2-pass fp16
    gemm_f16_2p<<<dim3(DMODEL / 128, BS / 128), 256, G2SMEM>>>(
        yh, wph, wpl, (float*)d_out, BS, DMODEL, DMODEL);
}

// round 15
// speedup vs baseline: 1.9464x; 1.1215x over previous
#include <cuda_runtime.h>
#include <cuda_bf16.h>
#include <cuda_fp16.h>
#include <math.h>
#include <stdint.h>
#include <string.h>

#define BATCH 2
#define SEQ 2048
#define DMODEL 2048
#define NH 16
#define NKV 4
#define HD 128
#define BS (BATCH*SEQ)
#define KVD (NKV*HD)
#define NQKV (DMODEL + 2*KVD)     // 3072
#define LOG2E 1.4426950408889634f

// ---------------- scratch (__device__ globals; no allocs allowed) ----------
__device__ float g_qkv[(size_t)BS*NQKV];
__device__ float g_cos[SEQ*64];
__device__ float g_sin[SEQ*64];

__device__ __half g_xh[(size_t)BS*DMODEL];
__device__ __half g_yh[(size_t)BS*DMODEL];
__device__ __half g_wch[(size_t)NQKV*DMODEL];           // [Wq;Wk;Wv] single fp16
__device__ __half g_wph[(size_t)DMODEL*DMODEL];         // Wproj single fp16

__device__ __half g_q16[(size_t)BS*DMODEL];
__device__ __half g_k16h[(size_t)BS*KVD];
__device__ __half g_k16l[(size_t)BS*KVD];
__device__ __half g_v16h[(size_t)BS*KVD];
__device__ __half g_v16l[(size_t)BS*KVD];

// ---------------- mma.sync helpers -----------------------------------------
__device__ __forceinline__ uint32_t smem_u32(const void* p) {
    uint32_t a;
    asm("{ .reg .u64 t; cvta.to.shared.u64 t, %1; cvt.u32.u64 %0, t; }" : "=r"(a) : "l"(p));
    return a;
}
__device__ __forceinline__ void ldsm_x4(uint32_t* r, uint32_t addr) {
    asm volatile("ldmatrix.sync.aligned.m8n8.x4.shared.b16 {%0,%1,%2,%3}, [%4];"
                 : "=r"(r[0]), "=r"(r[1]), "=r"(r[2]), "=r"(r[3]) : "r"(addr));
}
__device__ __forceinline__ void ldsm_x4_t(uint32_t* r, uint32_t addr) {
    asm volatile("ldmatrix.sync.aligned.m8n8.x4.trans.shared.b16 {%0,%1,%2,%3}, [%4];"
                 : "=r"(r[0]), "=r"(r[1]), "=r"(r[2]), "=r"(r[3]) : "r"(addr));
}
__device__ __forceinline__ void mma_f16(float* d, const uint32_t* a, const uint32_t* b) {
    asm volatile("mma.sync.aligned.m16n8k16.row.col.f32.f16.f16.f32 "
                 "{%0,%1,%2,%3}, {%4,%5,%6,%7}, {%8,%9}, {%0,%1,%2,%3};"
                 : "+f"(d[0]), "+f"(d[1]), "+f"(d[2]), "+f"(d[3])
                 : "r"(a[0]), "r"(a[1]), "r"(a[2]), "r"(a[3]), "r"(b[0]), "r"(b[1]));
}
__device__ __forceinline__ uint32_t pack_h16x2(float v0, float v1) {
    __half2 h = __floats2half2_rn(v0, v1);
    uint32_t r;
    memcpy(&r, &h, 4);
    return r;
}
#define CP_ASYNC16(s, g) \
    asm volatile("cp.async.cg.shared.global [%0], [%1], 16;" :: "r"(s), "l"(g))

// ---------------- split kernels ---------------------------------------------
__global__ __launch_bounds__(256) void split_x_h(const float4* __restrict__ src,
                                                 __half2* __restrict__ dst, int n4) {
    int i = blockIdx.x * blockDim.x + threadIdx.x;
    if (i >= n4) return;
    float4 v = src[i];
    dst[2 * i + 0] = __floats2half2_rn(v.x, v.y);
    dst[2 * i + 1] = __floats2half2_rn(v.z, v.w);
}

// all weights -> single fp16 (wc = Wq||Wk||Wv, wp = Wproj)
#define WQ4 (DMODEL*DMODEL/4)
#define WK4 (KVD*DMODEL/4)
#define WC4 (WQ4 + 2*WK4)
__global__ __launch_bounds__(256) void split_weights(const float4* __restrict__ wq,
                                                     const float4* __restrict__ wk,
                                                     const float4* __restrict__ wv,
                                                     const float4* __restrict__ wp,
                                                     __half2* __restrict__ ch,
                                                     __half2* __restrict__ ph) {
    int i = blockIdx.x * blockDim.x + threadIdx.x;
    if (i < WC4) {
        float4 v;
        if (i < WQ4) v = wq[i];
        else if (i < WQ4 + WK4) v = wk[i - WQ4];
        else v = wv[i - WQ4 - WK4];
        ch[2 * i + 0] = __floats2half2_rn(v.x, v.y);
        ch[2 * i + 1] = __floats2half2_rn(v.z, v.w);
    } else if (i < WC4 + WQ4) {
        int j = i - WC4;
        float4 v = wp[j];
        ph[2 * j + 0] = __floats2half2_rn(v.x, v.y);
        ph[2 * j + 1] = __floats2half2_rn(v.z, v.w);
    }
}

__device__ __forceinline__ uint32_t sw_off(int row, int chunk) {
    return (uint32_t)(row * 64 + ((chunk ^ (row & 3)) << 4));
}

// ------- single-pass fp16 GEMM, 256x128 CTA tile, 8 warps of 64x64 ---------
#define GSTAGES 3
#define GBK 32
#define BA_SZ (256*GBK*2)           // 16KB A tile
#define BB_SZ (128*GBK*2)           // 8KB B tile
#define BSTAGEB (BA_SZ + BB_SZ)     // 24KB
#define BSMEM_TOTAL (GSTAGES*BSTAGEB)

__global__ __launch_bounds__(256, 1) void gemm_f16_1p(
    const __half* __restrict__ Ah, const __half* __restrict__ Bh,
    float* __restrict__ C, int M, int N, int K) {
    extern __shared__ char smem[];
    uint32_t sb = smem_u32(smem);
    int tid = threadIdx.x, wid = tid >> 5, lane = tid & 31;
    int bm = blockIdx.y * 256, bn = blockIdx.x * 128;
    int wm = (wid >> 1) * 64;
    int wn = (wid & 1) * 64;
    const int NK = K / GBK;

    float acc[4][8][4];
#pragma unroll
    for (int a = 0; a < 4; a++)
#pragma unroll
        for (int b = 0; b < 8; b++)
#pragma unroll
            for (int c = 0; c < 4; c++) acc[a][b][c] = 0.f;

    auto load_stage = [&](int kc, uint32_t tb) {
        size_t kcol = (size_t)kc * GBK;
#pragma unroll
        for (int j = 0; j < 4; j++) {          // A: 256 rows
            int idx = tid + j * 256;
            int row = idx >> 2, c = idx & 3;
            CP_ASYNC16(tb + sw_off(row, c), Ah + (size_t)(bm + row) * K + kcol + c * 8);
        }
#pragma unroll
        for (int j = 0; j < 2; j++) {          // B: 128 rows
            int idx = tid + j * 256;
            int row = idx >> 2, c = idx & 3;
            CP_ASYNC16(tb + BA_SZ + sw_off(row, c), Bh + (size_t)(bn + row) * K + kcol + c * 8);
        }
    };

#pragma unroll
    for (int s = 0; s < GSTAGES - 1; s++) {
        load_stage(s, sb + s * BSTAGEB);
        asm volatile("cp.async.commit_group;" ::: "memory");
    }

    for (int kc = 0; kc < NK; kc++) {
        asm volatile("cp.async.wait_group %0;" :: "n"(GSTAGES - 2) : "memory");
        __syncthreads();
        uint32_t tb = sb + (kc % GSTAGES) * BSTAGEB;

#pragma unroll
        for (int ks = 0; ks < 2; ks++) {
            uint32_t bh[4][4];
#pragma unroll
            for (int pr = 0; pr < 4; pr++) {
                int row = wn + pr * 16 + (lane & 7) + ((lane >> 4) << 3);
                ldsm_x4(bh[pr], tb + BA_SZ + sw_off(row, ks * 2 + ((lane >> 3) & 1)));
            }
#pragma unroll
            for (int mt = 0; mt < 4; mt++) {
                uint32_t ah[4];
                int row = wm + mt * 16 + (lane & 15);
                ldsm_x4(ah, tb + sw_off(row, ks * 2 + (lane >> 4)));
#pragma unroll
                for (int nt = 0; nt < 8; nt++)
                    mma_f16(acc[mt][nt], ah, &bh[nt >> 1][(nt & 1) * 2]);
            }
        }
        if (kc + GSTAGES - 1 < NK) {
            int pst = (kc + GSTAGES - 1) % GSTAGES;
            load_stage(kc + GSTAGES - 1, sb + pst * BSTAGEB);
        }
        asm volatile("cp.async.commit_group;" ::: "memory");
    }

#pragma unroll
    for (int mt = 0; mt < 4; mt++) {
        int row0 = bm + wm + mt * 16 + (lane >> 2);
#pragma unroll
        for (int nt = 0; nt < 8; nt++) {
            int col = bn + wn + nt * 8 + (lane & 3) * 2;
            *(float2*)(C + (size_t)row0 * N + col) = make_float2(acc[mt][nt][0], acc[mt][nt][1]);
            *(float2*)(C + (size_t)(row0 + 8) * N + col) = make_float2(acc[mt][nt][2], acc[mt][nt][3]);
        }
    }
}

// ---------------- RoPE table ------------------------------------------------
__global__ void rope_table_kernel() {
    int i = threadIdx.x;
    int t = blockIdx.x;
    double inv = exp(-((double)(2 * i) / 128.0) * log(10000.0));
    double a = (double)t * inv;
    g_cos[t * 64 + i] = (float)cos(a);
    g_sin[t * 64 + i] = (float)sin(a);
}

// --------- fused RMSNorm+RoPE for Q/K + plain hi/lo convert for V -----------
__global__ __launch_bounds__(128) void rmsnorm_rope_qkv(const float* __restrict__ src,
                                                        __half* __restrict__ q16,
                                                        __half* __restrict__ k16h,
                                                        __half* __restrict__ k16l,
                                                        __half* __restrict__ v16h,
                                                        __half* __restrict__ v16l,
                                                        const float* __restrict__ gain) {
    int token = blockIdx.x;
    int hh = blockIdx.y;
    int d = threadIdx.x;

    if (hh >= NH + NKV) {
        int vh_ = hh - NH - NKV;
        float v = src[(size_t)token * NQKV + DMODEL + KVD + vh_ * HD + d];
        size_t idx = ((size_t)token * NKV + vh_) * HD + d;
        __half hv = __float2half_rn(v);
        v16h[idx] = hv;
        v16l[idx] = __float2half_rn(v - __half2float(hv));
        return;
    }

    int s = token & (SEQ - 1);
    bool isQ = hh < NH;
    int coloff = isQ ? hh * HD : DMODEL + (hh - NH) * HD;
    float v = src[(size_t)token * NQKV + coloff + d];

    float ss = v * v;
#pragma unroll
    for (int o = 16; o; o >>= 1) ss += __shfl_xor_sync(0xffffffffu, ss, o);
    __shared__ float ws[4];
    int lane = d & 31, w = d >> 5;
    if (lane == 0) ws[w] = ss;
    __syncthreads();
    float tot = ws[0] + ws[1] + ws[2] + ws[3];
    float inv = rsqrtf(tot * (1.0f / HD) + 1.1920928955078125e-7f);
    v *= inv;

    __shared__ float sv[HD];
    sv[d] = v;
    __syncthreads();

    float out;
    if (d < 64) {
        float c = g_cos[s * 64 + d], si = g_sin[s * 64 + d];
        out = v * c + sv[d + 64] * si;
    } else {
        int i = d - 64;
        float c = g_cos[s * 64 + i], si = g_sin[s * 64 + i];
        out = -sv[i] * si + v * c;
    }
    if (isQ) {
        out *= gain[hh] * 0.08838834764831845f;
        q16[((size_t)token * NH + hh) * HD + d] = __float2half_rn(out);
    } else {
        size_t idx = ((size_t)token * NKV + (hh - NH)) * HD + d;
        __half hv = __float2half_rn(out);
        k16h[idx] = hv;
        k16l[idx] = __float2half_rn(out - __half2float(hv));
    }
}

// ---------------- tensor-core flash attention (causal, GQA, fp16 2-pass) ----
#define FBQ 128
#define FBK 64
#define F_Q 0
#define F_STAGE0 32768
#define F_STAGEB 65536
#define F_KH 0
#define F_KL 16384
#define F_VH 32768
#define F_VL 49152
#define FSMEM_TOTAL (32768 + 2*F_STAGEB)

__device__ __forceinline__ uint32_t f_off(int row, int chunk) {
    return (uint32_t)(row * 256 + ((chunk ^ (row & 7)) << 4));
}

__device__ __forceinline__ void f_load_kv(uint32_t st,
                                          const __half* kh, const __half* kl,
                                          const __half* vh, const __half* vl,
                                          size_t gbase, int tid) {
#pragma unroll
    for (int j = 0; j < 4; j++) {
        int id = tid + j * 256;
        int row = id >> 4, c = id & 15;
        uint32_t so = f_off(row, c);
        size_t g = gbase + (size_t)row * KVD + c * 8;
        CP_ASYNC16(st + F_KH + so, kh + g);
        CP_ASYNC16(st + F_KL + so, kl + g);
        CP_ASYNC16(st + F_VH + so, vh + g);
        CP_ASYNC16(st + F_VL + so, vl + g);
    }
}

__global__ __launch_bounds__(256, 1) void flash_mma(
    const __half* __restrict__ q16,
    const __half* __restrict__ kh, const __half* __restrict__ kl,
    const __half* __restrict__ vh, const __half* __restrict__ vl,
    __half* __restrict__ yh) {
    extern __shared__ char smem[];
    uint32_t sb = smem_u32(smem);
    int tid = threadIdx.x, lane = tid & 31, w = tid >> 5;
    int bh_ = blockIdx.y;
    int b = bh_ >> 4, h = bh_ & 15, hkv = h >> 2;
    int qb = (gridDim.x - 1 - blockIdx.x) * FBQ;
    int q0 = w * 16;

#pragma unroll
    for (int j = 0; j < 8; j++) {
        int id = tid + j * 256;
        int row = id >> 4, c = id & 15;
        uint32_t so = f_off(row, c);
        size_t g = ((size_t)(b * SEQ + qb + row)) * DMODEL + h * HD + c * 8;
        CP_ASYNC16(sb + F_Q + so, q16 + g);
    }
    asm volatile("cp.async.commit_group;" ::: "memory");

    size_t kvhead = (size_t)(b * SEQ) * KVD + hkv * HD;
    int ntiles = qb / FBK + 2;

    f_load_kv(sb + F_STAGE0, kh, kl, vh, vl, kvhead, tid);
    asm volatile("cp.async.commit_group;" ::: "memory");

    asm volatile("cp.async.wait_group 1;" ::: "memory");
    __syncthreads();
    uint32_t qf[8][4];
#pragma unroll
    for (int ds = 0; ds < 8; ds++) {
        uint32_t qoff = f_off(q0 + (lane & 15), ds * 2 + (lane >> 4));
        ldsm_x4(qf[ds], sb + F_Q + qoff);
    }

    float o[16][4];
#pragma unroll
    for (int nt = 0; nt < 16; nt++)
#pragma unroll
        for (int e = 0; e < 4; e++) o[nt][e] = 0.f;
    float m0 = -1e30f, m1 = -1e30f, l0 = 0.f, l1 = 0.f;

    int qmax = qb + q0 + 15;
    int rr0 = qb + q0 + (lane >> 2);
    int rr1 = rr0 + 8;

    for (int t = 0; t < ntiles; t++) {
        if (t + 1 < ntiles)
            f_load_kv(sb + F_STAGE0 + ((t + 1) & 1) * F_STAGEB, kh, kl, vh, vl,
                      kvhead + (size_t)(t + 1) * FBK * KVD, tid);
        asm volatile("cp.async.commit_group;" ::: "memory");
        asm volatile("cp.async.wait_group 1;" ::: "memory");
        __syncthreads();

        int kv = t * FBK;
        if (kv <= qmax) {
            uint32_t st = sb + F_STAGE0 + (t & 1) * F_STAGEB;

            float c[8][4];
#pragma unroll
            for (int nt = 0; nt < 8; nt++)
#pragma unroll
                for (int e = 0; e < 4; e++) c[nt][e] = 0.f;

#pragma unroll
            for (int ds = 0; ds < 8; ds++) {
                uint32_t bh4[4][4], bl4[4][4];
#pragma unroll
                for (int g = 0; g < 4; g++) {
                    int rowk = g * 16 + (lane & 7) + ((lane >> 4) << 3);
                    uint32_t koff = f_off(rowk, ds * 2 + ((lane >> 3) & 1));
                    ldsm_x4(bh4[g], st + F_KH + koff);
                    ldsm_x4(bl4[g], st + F_KL + koff);
                }
#pragma unroll
                for (int g = 0; g < 4; g++)
#pragma unroll
                    for (int sub = 0; sub < 2; sub++) {
                        int nt = g * 2 + sub;
                        mma_f16(c[nt], qf[ds], &bh4[g][sub * 2]);
                        mma_f16(c[nt], qf[ds], &bl4[g][sub * 2]);
                    }
            }

            if (kv + FBK - 1 > qb + q0) {
#pragma unroll
                for (int nt = 0; nt < 8; nt++) {
                    int col = kv + nt * 8 + (lane & 3) * 2;
                    if (col > rr0) c[nt][0] = -1e30f;
                    if (col + 1 > rr0) c[nt][1] = -1e30f;
                    if (col > rr1) c[nt][2] = -1e30f;
                    if (col + 1 > rr1) c[nt][3] = -1e30f;
                }
            }

            float mx0 = -1e30f, mx1 = -1e30f;
#pragma unroll
            for (int nt = 0; nt < 8; nt++) {
                mx0 = fmaxf(mx0, fmaxf(c[nt][0], c[nt][1]));
                mx1 = fmaxf(mx1, fmaxf(c[nt][2], c[nt][3]));
            }
            mx0 = fmaxf(mx0, __shfl_xor_sync(0xffffffffu, mx0, 1));
            mx0 = fmaxf(mx0, __shfl_xor_sync(0xffffffffu, mx0, 2));
            mx1 = fmaxf(mx1, __shfl_xor_sync(0xffffffffu, mx1, 1));
            mx1 = fmaxf(mx1, __shfl_xor_sync(0xffffffffu, mx1, 2));
            float m0n = fmaxf(m0, mx0), m1n = fmaxf(m1, mx1);
            float rs0 = exp2f((m0 - m0n) * LOG2E);
            float rs1 = exp2f((m1 - m1n) * LOG2E);
            float s0 = 0.f, s1 = 0.f;
#pragma unroll
            for (int nt = 0; nt < 8; nt++) {
                c[nt][0] = exp2f((c[nt][0] - m0n) * LOG2E);
                c[nt][1] = exp2f((c[nt][1] - m0n) * LOG2E);
                c[nt][2] = exp2f((c[nt][2] - m1n) * LOG2E);
                c[nt][3] = exp2f((c[nt][3] - m1n) * LOG2E);
                s0 += c[nt][0] + c[nt][1];
                s1 += c[nt][2] + c[nt][3];
            }
            s0 += __shfl_xor_sync(0xffffffffu, s0, 1);
            s0 += __shfl_xor_sync(0xffffffffu, s0, 2);
            s1 += __shfl_xor_sync(0xffffffffu, s1, 1);
            s1 += __shfl_xor_sync(0xffffffffu, s1, 2);
            l0 = l0 * rs0 + s0;
            l1 = l1 * rs1 + s1;
            m0 = m0n; m1 = m1n;
#pragma unroll
            for (int nt = 0; nt < 16; nt++) {
                o[nt][0] *= rs0; o[nt][1] *= rs0;
                o[nt][2] *= rs1; o[nt][3] *= rs1;
            }

#pragma unroll
            for (int kt = 0; kt < 4; kt++) {
                uint32_t ap[4];
#pragma unroll
                for (int half = 0; half < 2; half++) {
                    const float* cc = c[2 * kt + half];
                    ap[half * 2 + 0] = pack_h16x2(cc[0], cc[1]);
                    ap[half * 2 + 1] = pack_h16x2(cc[2], cc[3]);
                }
#pragma unroll
                for (int g = 0; g < 8; g++) {
                    int rowv = kt * 16 + (lane & 15);
                    uint32_t voff = f_off(rowv, g * 2 + (lane >> 4));
                    uint32_t vh4[4], vl4[4];
                    ldsm_x4_t(vh4, st + F_VH + voff);
                    ldsm_x4_t(vl4, st + F_VL + voff);
                    mma_f16(o[2 * g], ap, &vh4[0]);
                    mma_f16(o[2 * g], ap, &vl4[0]);
                    mma_f16(o[2 * g + 1], ap, &vh4[2]);
                    mma_f16(o[2 * g + 1], ap, &vl4[2]);
                }
            }
        }
        __syncthreads();
    }

    float iv0 = 1.f / l0, iv1 = 1.f / l1;
    size_t base0 = ((size_t)(b * SEQ) + rr0) * DMODEL + h * HD;
    size_t base1 = base0 + (size_t)8 * DMODEL;
#pragma unroll
    for (int nt = 0; nt < 16; nt++) {
        int d = nt * 8 + (lane & 3) * 2;
        __half2 h0 = __floats2half2_rn(o[nt][0] * iv0, o[nt][1] * iv0);
        __half2 h1 = __floats2half2_rn(o[nt][2] * iv1, o[nt][3] * iv1);
        *(__half2*)(yh + base0 + d) = h0;
        *(__half2*)(yh + base1 + d) = h1;
    }
}

// ---------------------------------------------------------------------------
extern "C" void kernel_launch(void* const* d_in, const int* in_sizes, int n_in,
                              void* d_out, int out_size) {
    const float* x     = (const float*)d_in[0];
    const float* Wq    = (const float*)d_in[1];
    const float* Wk    = (const float*)d_in[2];
    const float* Wv    = (const float*)d_in[3];
    const float* Wproj = (const float*)d_in[4];
    const float* qgain = (const float*)d_in[5];

    float* qkv;
    cudaGetSymbolAddress((void**)&qkv, g_qkv);
    __half *xh, *yh, *wch, *wph;
    __half *q16, *k16h, *k16l, *v16h, *v16l;
    cudaGetSymbolAddress((void**)&xh, g_xh);
    cudaGetSymbolAddress((void**)&yh, g_yh);
    cudaGetSymbolAddress((void**)&wch, g_wch);
    cudaGetSymbolAddress((void**)&wph, g_wph);
    cudaGetSymbolAddress((void**)&q16, g_q16);
    cudaGetSymbolAddress((void**)&k16h, g_k16h); cudaGetSymbolAddress((void**)&k16l, g_k16l);
    cudaGetSymbolAddress((void**)&v16h, g_v16h); cudaGetSymbolAddress((void**)&v16l, g_v16l);

    cudaFuncSetAttribute(gemm_f16_1p, cudaFuncAttributeMaxDynamicSharedMemorySize, BSMEM_TOTAL);
    cudaFuncSetAttribute(flash_mma, cudaFuncAttributeMaxDynamicSharedMemorySize, FSMEM_TOTAL);

    rope_table_kernel<<<SEQ, 64>>>();

    {
        int n4 = BS * DMODEL / 4;
        split_x_h<<<(n4 + 255) / 256, 256>>>((const float4*)x, (__half2*)xh, n4);
        int nw = WC4 + WQ4;
        split_weights<<<(nw + 255) / 256, 256>>>((const float4*)Wq, (const float4*)Wk,
                                                 (const float4*)Wv, (const float4*)Wproj,
                                                 (__half2*)wch, (__half2*)wph);
    }

    // fused QKV projection — single-pass fp16, 256x128 tile
    gemm_f16_1p<<<dim3(NQKV / 128, BS / 256), 256, BSMEM_TOTAL>>>(
        xh, wch, qkv, BS, NQKV, DMODEL);

    rmsnorm_rope_qkv<<<dim3(BS, NH + 2 * NKV), HD>>>(qkv, q16, k16h, k16l, v16h, v16l, qgain);

    flash_mma<<<dim3(SEQ / FBQ, BATCH * NH), 256, FSMEM_TOTAL>>>(q16, k16h, k16l, v16h, v16l, yh);

    // output projection — single-pass fp16, 256x128 tile
    gemm_f16_1p<<<dim3(DMODEL / 128, BS / 256), 256, BSMEM_TOTAL>>>(
        yh, wph, (float*)d_out, BS, DMODEL, DMODEL);
}

// round 16
// speedup vs baseline: 2.2593x; 1.1608x over previous
#include <cuda_runtime.h>
#include <cuda_bf16.h>
#include <cuda_fp16.h>
#include <math.h>
#include <stdint.h>
#include <string.h>

#define BATCH 2
#define SEQ 2048
#define DMODEL 2048
#define NH 16
#define NKV 4
#define HD 128
#define BS (BATCH*SEQ)
#define KVD (NKV*HD)
#define NQKV (DMODEL + 2*KVD)     // 3072
#define LOG2E 1.4426950408889634f

// ---------------- scratch (__device__ globals; no allocs allowed) ----------
__device__ float g_qkv[(size_t)BS*NQKV];
__device__ float g_cos[SEQ*64];
__device__ float g_sin[SEQ*64];

__device__ __half g_xh[(size_t)BS*DMODEL];
__device__ __half g_yh[(size_t)BS*DMODEL];
__device__ __half g_wch[(size_t)NQKV*DMODEL];           // [Wq;Wk;Wv] single fp16
__device__ __half g_wph[(size_t)DMODEL*DMODEL];         // Wproj single fp16

__device__ __half g_q16[(size_t)BS*DMODEL];
__device__ __half g_k16[(size_t)BS*KVD];
__device__ __half g_v16[(size_t)BS*KVD];

// ---------------- mma.sync helpers -----------------------------------------
__device__ __forceinline__ uint32_t smem_u32(const void* p) {
    uint32_t a;
    asm("{ .reg .u64 t; cvta.to.shared.u64 t, %1; cvt.u32.u64 %0, t; }" : "=r"(a) : "l"(p));
    return a;
}
__device__ __forceinline__ void ldsm_x4(uint32_t* r, uint32_t addr) {
    asm volatile("ldmatrix.sync.aligned.m8n8.x4.shared.b16 {%0,%1,%2,%3}, [%4];"
                 : "=r"(r[0]), "=r"(r[1]), "=r"(r[2]), "=r"(r[3]) : "r"(addr));
}
__device__ __forceinline__ void ldsm_x4_t(uint32_t* r, uint32_t addr) {
    asm volatile("ldmatrix.sync.aligned.m8n8.x4.trans.shared.b16 {%0,%1,%2,%3}, [%4];"
                 : "=r"(r[0]), "=r"(r[1]), "=r"(r[2]), "=r"(r[3]) : "r"(addr));
}
__device__ __forceinline__ void mma_f16(float* d, const uint32_t* a, const uint32_t* b) {
    asm volatile("mma.sync.aligned.m16n8k16.row.col.f32.f16.f16.f32 "
                 "{%0,%1,%2,%3}, {%4,%5,%6,%7}, {%8,%9}, {%0,%1,%2,%3};"
                 : "+f"(d[0]), "+f"(d[1]), "+f"(d[2]), "+f"(d[3])
                 : "r"(a[0]), "r"(a[1]), "r"(a[2]), "r"(a[3]), "r"(b[0]), "r"(b[1]));
}
__device__ __forceinline__ uint32_t pack_h16x2(float v0, float v1) {
    __half2 h = __floats2half2_rn(v0, v1);
    uint32_t r;
    memcpy(&r, &h, 4);
    return r;
}
#define CP_ASYNC16(s, g) \
    asm volatile("cp.async.cg.shared.global [%0], [%1], 16;" :: "r"(s), "l"(g))

// ---------------- split kernels ---------------------------------------------
__global__ __launch_bounds__(256) void split_x_h(const float4* __restrict__ src,
                                                 __half2* __restrict__ dst, int n4) {
    int i = blockIdx.x * blockDim.x + threadIdx.x;
    if (i >= n4) return;
    float4 v = src[i];
    dst[2 * i + 0] = __floats2half2_rn(v.x, v.y);
    dst[2 * i + 1] = __floats2half2_rn(v.z, v.w);
}

#define WQ4 (DMODEL*DMODEL/4)
#define WK4 (KVD*DMODEL/4)
#define WC4 (WQ4 + 2*WK4)
__global__ __launch_bounds__(256) void split_weights(const float4* __restrict__ wq,
                                                     const float4* __restrict__ wk,
                                                     const float4* __restrict__ wv,
                                                     const float4* __restrict__ wp,
                                                     __half2* __restrict__ ch,
                                                     __half2* __restrict__ ph) {
    int i = blockIdx.x * blockDim.x + threadIdx.x;
    if (i < WC4) {
        float4 v;
        if (i < WQ4) v = wq[i];
        else if (i < WQ4 + WK4) v = wk[i - WQ4];
        else v = wv[i - WQ4 - WK4];
        ch[2 * i + 0] = __floats2half2_rn(v.x, v.y);
        ch[2 * i + 1] = __floats2half2_rn(v.z, v.w);
    } else if (i < WC4 + WQ4) {
        int j = i - WC4;
        float4 v = wp[j];
        ph[2 * j + 0] = __floats2half2_rn(v.x, v.y);
        ph[2 * j + 1] = __floats2half2_rn(v.z, v.w);
    }
}

__device__ __forceinline__ uint32_t sw_off(int row, int chunk) {
    return (uint32_t)(row * 64 + ((chunk ^ (row & 3)) << 4));
}

// ------- single-pass fp16 GEMM, 256x128 CTA tile, 8 warps of 64x64 ---------
#define GSTAGES 3
#define GBK 32
#define BA_SZ (256*GBK*2)
#define BB_SZ (128*GBK*2)
#define BSTAGEB (BA_SZ + BB_SZ)
#define BSMEM_TOTAL (GSTAGES*BSTAGEB)

__global__ __launch_bounds__(256, 1) void gemm_f16_1p(
    const __half* __restrict__ Ah, const __half* __restrict__ Bh,
    float* __restrict__ C, int M, int N, int K) {
    extern __shared__ char smem[];
    uint32_t sb = smem_u32(smem);
    int tid = threadIdx.x, wid = tid >> 5, lane = tid & 31;
    int bm = blockIdx.y * 256, bn = blockIdx.x * 128;
    int wm = (wid >> 1) * 64;
    int wn = (wid & 1) * 64;
    const int NK = K / GBK;

    float acc[4][8][4];
#pragma unroll
    for (int a = 0; a < 4; a++)
#pragma unroll
        for (int b = 0; b < 8; b++)
#pragma unroll
            for (int c = 0; c < 4; c++) acc[a][b][c] = 0.f;

    auto load_stage = [&](int kc, uint32_t tb) {
        size_t kcol = (size_t)kc * GBK;
#pragma unroll
        for (int j = 0; j < 4; j++) {
            int idx = tid + j * 256;
            int row = idx >> 2, c = idx & 3;
            CP_ASYNC16(tb + sw_off(row, c), Ah + (size_t)(bm + row) * K + kcol + c * 8);
        }
#pragma unroll
        for (int j = 0; j < 2; j++) {
            int idx = tid + j * 256;
            int row = idx >> 2, c = idx & 3;
            CP_ASYNC16(tb + BA_SZ + sw_off(row, c), Bh + (size_t)(bn + row) * K + kcol + c * 8);
        }
    };

#pragma unroll
    for (int s = 0; s < GSTAGES - 1; s++) {
        load_stage(s, sb + s * BSTAGEB);
        asm volatile("cp.async.commit_group;" ::: "memory");
    }

    for (int kc = 0; kc < NK; kc++) {
        asm volatile("cp.async.wait_group %0;" :: "n"(GSTAGES - 2) : "memory");
        __syncthreads();
        uint32_t tb = sb + (kc % GSTAGES) * BSTAGEB;

#pragma unroll
        for (int ks = 0; ks < 2; ks++) {
            uint32_t bh[4][4];
#pragma unroll
            for (int pr = 0; pr < 4; pr++) {
                int row = wn + pr * 16 + (lane & 7) + ((lane >> 4) << 3);
                ldsm_x4(bh[pr], tb + BA_SZ + sw_off(row, ks * 2 + ((lane >> 3) & 1)));
            }
#pragma unroll
            for (int mt = 0; mt < 4; mt++) {
                uint32_t ah[4];
                int row = wm + mt * 16 + (lane & 15);
                ldsm_x4(ah, tb + sw_off(row, ks * 2 + (lane >> 4)));
#pragma unroll
                for (int nt = 0; nt < 8; nt++)
                    mma_f16(acc[mt][nt], ah, &bh[nt >> 1][(nt & 1) * 2]);
            }
        }
        if (kc + GSTAGES - 1 < NK) {
            int pst = (kc + GSTAGES - 1) % GSTAGES;
            load_stage(kc + GSTAGES - 1, sb + pst * BSTAGEB);
        }
        asm volatile("cp.async.commit_group;" ::: "memory");
    }

#pragma unroll
    for (int mt = 0; mt < 4; mt++) {
        int row0 = bm + wm + mt * 16 + (lane >> 2);
#pragma unroll
        for (int nt = 0; nt < 8; nt++) {
            int col = bn + wn + nt * 8 + (lane & 3) * 2;
            *(float2*)(C + (size_t)row0 * N + col) = make_float2(acc[mt][nt][0], acc[mt][nt][1]);
            *(float2*)(C + (size_t)(row0 + 8) * N + col) = make_float2(acc[mt][nt][2], acc[mt][nt][3]);
        }
    }
}

// ---------------- RoPE table ------------------------------------------------
__global__ void rope_table_kernel() {
    int i = threadIdx.x;
    int t = blockIdx.x;
    double inv = exp(-((double)(2 * i) / 128.0) * log(10000.0));
    double a = (double)t * inv;
    g_cos[t * 64 + i] = (float)cos(a);
    g_sin[t * 64 + i] = (float)sin(a);
}

// --------- fused RMSNorm+RoPE for Q/K + fp16 convert for V ------------------
__global__ __launch_bounds__(128) void rmsnorm_rope_qkv(const float* __restrict__ src,
                                                        __half* __restrict__ q16,
                                                        __half* __restrict__ k16,
                                                        __half* __restrict__ v16,
                                                        const float* __restrict__ gain) {
    int token = blockIdx.x;
    int hh = blockIdx.y;
    int d = threadIdx.x;

    if (hh >= NH + NKV) {                      // V: plain fp16 convert
        int vh_ = hh - NH - NKV;
        float v = src[(size_t)token * NQKV + DMODEL + KVD + vh_ * HD + d];
        v16[((size_t)token * NKV + vh_) * HD + d] = __float2half_rn(v);
        return;
    }

    int s = token & (SEQ - 1);
    bool isQ = hh < NH;
    int coloff = isQ ? hh * HD : DMODEL + (hh - NH) * HD;
    float v = src[(size_t)token * NQKV + coloff + d];

    float ss = v * v;
#pragma unroll
    for (int o = 16; o; o >>= 1) ss += __shfl_xor_sync(0xffffffffu, ss, o);
    __shared__ float ws[4];
    int lane = d & 31, w = d >> 5;
    if (lane == 0) ws[w] = ss;
    __syncthreads();
    float tot = ws[0] + ws[1] + ws[2] + ws[3];
    float inv = rsqrtf(tot * (1.0f / HD) + 1.1920928955078125e-7f);
    v *= inv;

    __shared__ float sv[HD];
    sv[d] = v;
    __syncthreads();

    float out;
    if (d < 64) {
        float c = g_cos[s * 64 + d], si = g_sin[s * 64 + d];
        out = v * c + sv[d + 64] * si;
    } else {
        int i = d - 64;
        float c = g_cos[s * 64 + i], si = g_sin[s * 64 + i];
        out = -sv[i] * si + v * c;
    }
    if (isQ) {
        out *= gain[hh] * 0.08838834764831845f;
        q16[((size_t)token * NH + hh) * HD + d] = __float2half_rn(out);
    } else {
        k16[((size_t)token * NKV + (hh - NH)) * HD + d] = __float2half_rn(out);
    }
}

// ------ tensor-core flash attention (causal, GQA, single-pass fp16) ---------
#define FBQ 128
#define FBK 64
#define F_Q 0
#define F_STAGE0 32768
#define F_STAGEB 32768            // K 16KB + V 16KB
#define F_K 0
#define F_V 16384
#define FSMEM_TOTAL (32768 + 2*F_STAGEB)   // 96KB

__device__ __forceinline__ uint32_t f_off(int row, int chunk) {
    return (uint32_t)(row * 256 + ((chunk ^ (row & 7)) << 4));
}

__device__ __forceinline__ void f_load_kv(uint32_t st,
                                          const __half* k16, const __half* v16,
                                          size_t gbase, int tid) {
#pragma unroll
    for (int j = 0; j < 4; j++) {
        int id = tid + j * 256;
        int row = id >> 4, c = id & 15;
        uint32_t so = f_off(row, c);
        size_t g = gbase + (size_t)row * KVD + c * 8;
        CP_ASYNC16(st + F_K + so, k16 + g);
        CP_ASYNC16(st + F_V + so, v16 + g);
    }
}

__global__ __launch_bounds__(256, 1) void flash_mma(
    const __half* __restrict__ q16,
    const __half* __restrict__ k16, const __half* __restrict__ v16,
    __half* __restrict__ yh) {
    extern __shared__ char smem[];
    uint32_t sb = smem_u32(smem);
    int tid = threadIdx.x, lane = tid & 31, w = tid >> 5;
    int bh_ = blockIdx.y;
    int b = bh_ >> 4, h = bh_ & 15, hkv = h >> 2;
    int qb = (gridDim.x - 1 - blockIdx.x) * FBQ;   // LPT order
    int q0 = w * 16;

#pragma unroll
    for (int j = 0; j < 8; j++) {
        int id = tid + j * 256;
        int row = id >> 4, c = id & 15;
        uint32_t so = f_off(row, c);
        size_t g = ((size_t)(b * SEQ + qb + row)) * DMODEL + h * HD + c * 8;
        CP_ASYNC16(sb + F_Q + so, q16 + g);
    }
    asm volatile("cp.async.commit_group;" ::: "memory");

    size_t kvhead = (size_t)(b * SEQ) * KVD + hkv * HD;
    int ntiles = qb / FBK + 2;

    f_load_kv(sb + F_STAGE0, k16, v16, kvhead, tid);
    asm volatile("cp.async.commit_group;" ::: "memory");

    asm volatile("cp.async.wait_group 1;" ::: "memory");
    __syncthreads();
    uint32_t qf[8][4];
#pragma unroll
    for (int ds = 0; ds < 8; ds++) {
        uint32_t qoff = f_off(q0 + (lane & 15), ds * 2 + (lane >> 4));
        ldsm_x4(qf[ds], sb + F_Q + qoff);
    }

    float o[16][4];
#pragma unroll
    for (int nt = 0; nt < 16; nt++)
#pragma unroll
        for (int e = 0; e < 4; e++) o[nt][e] = 0.f;
    float m0 = -1e30f, m1 = -1e30f, l0 = 0.f, l1 = 0.f;

    int qmax = qb + q0 + 15;
    int rr0 = qb + q0 + (lane >> 2);
    int rr1 = rr0 + 8;

    for (int t = 0; t < ntiles; t++) {
        if (t + 1 < ntiles)
            f_load_kv(sb + F_STAGE0 + ((t + 1) & 1) * F_STAGEB, k16, v16,
                      kvhead + (size_t)(t + 1) * FBK * KVD, tid);
        asm volatile("cp.async.commit_group;" ::: "memory");
        asm volatile("cp.async.wait_group 1;" ::: "memory");
        __syncthreads();

        int kv = t * FBK;
        if (kv <= qmax) {
            uint32_t st = sb + F_STAGE0 + (t & 1) * F_STAGEB;

            // ---- S = Q K^T (single-pass fp16) ----
            float c[8][4];
#pragma unroll
            for (int nt = 0; nt < 8; nt++)
#pragma unroll
                for (int e = 0; e < 4; e++) c[nt][e] = 0.f;

#pragma unroll
            for (int ds = 0; ds < 8; ds++) {
                uint32_t bh4[4][4];
#pragma unroll
                for (int g = 0; g < 4; g++) {
                    int rowk = g * 16 + (lane & 7) + ((lane >> 4) << 3);
                    uint32_t koff = f_off(rowk, ds * 2 + ((lane >> 3) & 1));
                    ldsm_x4(bh4[g], st + F_K + koff);
                }
#pragma unroll
                for (int g = 0; g < 4; g++)
#pragma unroll
                    for (int sub = 0; sub < 2; sub++)
                        mma_f16(c[g * 2 + sub], qf[ds], &bh4[g][sub * 2]);
            }

            if (kv + FBK - 1 > qb + q0) {
#pragma unroll
                for (int nt = 0; nt < 8; nt++) {
                    int col = kv + nt * 8 + (lane & 3) * 2;
                    if (col > rr0) c[nt][0] = -1e30f;
                    if (col + 1 > rr0) c[nt][1] = -1e30f;
                    if (col > rr1) c[nt][2] = -1e30f;
                    if (col + 1 > rr1) c[nt][3] = -1e30f;
                }
            }

            float mx0 = -1e30f, mx1 = -1e30f;
#pragma unroll
            for (int nt = 0; nt < 8; nt++) {
                mx0 = fmaxf(mx0, fmaxf(c[nt][0], c[nt][1]));
                mx1 = fmaxf(mx1, fmaxf(c[nt][2], c[nt][3]));
            }
            mx0 = fmaxf(mx0, __shfl_xor_sync(0xffffffffu, mx0, 1));
            mx0 = fmaxf(mx0, __shfl_xor_sync(0xffffffffu, mx0, 2));
            mx1 = fmaxf(mx1, __shfl_xor_sync(0xffffffffu, mx1, 1));
            mx1 = fmaxf(mx1, __shfl_xor_sync(0xffffffffu, mx1, 2));
            float m0n = fmaxf(m0, mx0), m1n = fmaxf(m1, mx1);
            float rs0 = exp2f((m0 - m0n) * LOG2E);
            float rs1 = exp2f((m1 - m1n) * LOG2E);
            float s0 = 0.f, s1 = 0.f;
#pragma unroll
            for (int nt = 0; nt < 8; nt++) {
                c[nt][0] = exp2f((c[nt][0] - m0n) * LOG2E);
                c[nt][1] = exp2f((c[nt][1] - m0n) * LOG2E);
                c[nt][2] = exp2f((c[nt][2] - m1n) * LOG2E);
                c[nt][3] = exp2f((c[nt][3] - m1n) * LOG2E);
                s0 += c[nt][0] + c[nt][1];
                s1 += c[nt][2] + c[nt][3];
            }
            s0 += __shfl_xor_sync(0xffffffffu, s0, 1);
            s0 += __shfl_xor_sync(0xffffffffu, s0, 2);
            s1 += __shfl_xor_sync(0xffffffffu, s1, 1);
            s1 += __shfl_xor_sync(0xffffffffu, s1, 2);
            l0 = l0 * rs0 + s0;
            l1 = l1 * rs1 + s1;
            m0 = m0n; m1 = m1n;
#pragma unroll
            for (int nt = 0; nt < 16; nt++) {
                o[nt][0] *= rs0; o[nt][1] *= rs0;
                o[nt][2] *= rs1; o[nt][3] *= rs1;
            }

            // ---- P x V (single-pass fp16) ----
#pragma unroll
            for (int kt = 0; kt < 4; kt++) {
                uint32_t ap[4];
#pragma unroll
                for (int half = 0; half < 2; half++) {
                    const float* cc = c[2 * kt + half];
                    ap[half * 2 + 0] = pack_h16x2(cc[0], cc[1]);
                    ap[half * 2 + 1] = pack_h16x2(cc[2], cc[3]);
                }
#pragma unroll
                for (int g = 0; g < 8; g++) {
                    int rowv = kt * 16 + (lane & 15);
                    uint32_t voff = f_off(rowv, g * 2 + (lane >> 4));
                    uint32_t vh4[4];
                    ldsm_x4_t(vh4, st + F_V + voff);
                    mma_f16(o[2 * g], ap, &vh4[0]);
                    mma_f16(o[2 * g + 1], ap, &vh4[2]);
                }
            }
        }
        __syncthreads();
    }

    float iv0 = 1.f / l0, iv1 = 1.f / l1;
    size_t base0 = ((size_t)(b * SEQ) + rr0) * DMODEL + h * HD;
    size_t base1 = base0 + (size_t)8 * DMODEL;
#pragma unroll
    for (int nt = 0; nt < 16; nt++) {
        int d = nt * 8 + (lane & 3) * 2;
        __half2 h0 = __floats2half2_rn(o[nt][0] * iv0, o[nt][1] * iv0);
        __half2 h1 = __floats2half2_rn(o[nt][2] * iv1, o[nt][3] * iv1);
        *(__half2*)(yh + base0 + d) = h0;
        *(__half2*)(yh + base1 + d) = h1;
    }
}

// ---------------------------------------------------------------------------
extern "C" void kernel_launch(void* const* d_in, const int* in_sizes, int n_in,
                              void* d_out, int out_size) {
    const float* x     = (const float*)d_in[0];
    const float* Wq    = (const float*)d_in[1];
    const float* Wk    = (const float*)d_in[2];
    const float* Wv    = (const float*)d_in[3];
    const float* Wproj = (const float*)d_in[4];
    const float* qgain = (const float*)d_in[5];

    float* qkv;
    cudaGetSymbolAddress((void**)&qkv, g_qkv);
    __half *xh, *yh, *wch, *wph, *q16, *k16, *v16;
    cudaGetSymbolAddress((void**)&xh, g_xh);
    cudaGetSymbolAddress((void**)&yh, g_yh);
    cudaGetSymbolAddress((void**)&wch, g_wch);
    cudaGetSymbolAddress((void**)&wph, g_wph);
    cudaGetSymbolAddress((void**)&q16, g_q16);
    cudaGetSymbolAddress((void**)&k16, g_k16);
    cudaGetSymbolAddress((void**)&v16, g_v16);

    cudaFuncSetAttribute(gemm_f16_1p, cudaFuncAttributeMaxDynamicSharedMemorySize, BSMEM_TOTAL);
    cudaFuncSetAttribute(flash_mma, cudaFuncAttributeMaxDynamicSharedMemorySize, FSMEM_TOTAL);

    rope_table_kernel<<<SEQ, 64>>>();

    {
        int n4 = BS * DMODEL / 4;
        split_x_h<<<(n4 + 255) / 256, 256>>>((const float4*)x, (__half2*)xh, n4);
        int nw = WC4 + WQ4;
        split_weights<<<(nw + 255) / 256, 256>>>((const float4*)Wq, (const float4*)Wk,
                                                 (const float4*)Wv, (const float4*)Wproj,
                                                 (__half2*)wch, (__half2*)wph);
    }

    gemm_f16_1p<<<dim3(NQKV / 128, BS / 256), 256, BSMEM_TOTAL>>>(
        xh, wch, qkv, BS, NQKV, DMODEL);

    rmsnorm_rope_qkv<<<dim3(BS, NH + 2 * NKV), HD>>>(qkv, q16, k16, v16, qgain);

    flash_mma<<<dim3(SEQ / FBQ, BATCH * NH), 256, FSMEM_TOTAL>>>(q16, k16, v16, yh);

    gemm_f16_1p<<<dim3(DMODEL / 128, BS / 256), 256, BSMEM_TOTAL>>>(
        yh, wph, (float*)d_out, BS, DMODEL, DMODEL);
}

// round 17
// speedup vs baseline: 2.2601x; 1.0004x over previous
#include <cuda_runtime.h>
#include <cuda_bf16.h>
#include <cuda_fp16.h>
#include <math.h>
#include <stdint.h>
#include <string.h>

#define BATCH 2
#define SEQ 2048
#define DMODEL 2048
#define NH 16
#define NKV 4
#define HD 128
#define BS (BATCH*SEQ)
#define KVD (NKV*HD)
#define NQKV (DMODEL + 2*KVD)     // 3072
#define LOG2E 1.4426950408889634f

// ---------------- scratch (__device__ globals; no allocs allowed) ----------
__device__ float g_qkv[(size_t)BS*NQKV];
__device__ float g_cos[SEQ*64];
__device__ float g_sin[SEQ*64];

__device__ __half g_xh[(size_t)BS*DMODEL];
__device__ __half g_yh[(size_t)BS*DMODEL];
__device__ __half g_wch[(size_t)NQKV*DMODEL];
__device__ __half g_wph[(size_t)DMODEL*DMODEL];

__device__ __half g_q16[(size_t)BS*DMODEL];
__device__ __half g_k16[(size_t)BS*KVD];
__device__ __half g_v16[(size_t)BS*KVD];

// ---------------- mma.sync helpers -----------------------------------------
__device__ __forceinline__ uint32_t smem_u32(const void* p) {
    uint32_t a;
    asm("{ .reg .u64 t; cvta.to.shared.u64 t, %1; cvt.u32.u64 %0, t; }" : "=r"(a) : "l"(p));
    return a;
}
__device__ __forceinline__ void ldsm_x4(uint32_t* r, uint32_t addr) {
    asm volatile("ldmatrix.sync.aligned.m8n8.x4.shared.b16 {%0,%1,%2,%3}, [%4];"
                 : "=r"(r[0]), "=r"(r[1]), "=r"(r[2]), "=r"(r[3]) : "r"(addr));
}
__device__ __forceinline__ void ldsm_x4_t(uint32_t* r, uint32_t addr) {
    asm volatile("ldmatrix.sync.aligned.m8n8.x4.trans.shared.b16 {%0,%1,%2,%3}, [%4];"
                 : "=r"(r[0]), "=r"(r[1]), "=r"(r[2]), "=r"(r[3]) : "r"(addr));
}
__device__ __forceinline__ void mma_f16(float* d, const uint32_t* a, const uint32_t* b) {
    asm volatile("mma.sync.aligned.m16n8k16.row.col.f32.f16.f16.f32 "
                 "{%0,%1,%2,%3}, {%4,%5,%6,%7}, {%8,%9}, {%0,%1,%2,%3};"
                 : "+f"(d[0]), "+f"(d[1]), "+f"(d[2]), "+f"(d[3])
                 : "r"(a[0]), "r"(a[1]), "r"(a[2]), "r"(a[3]), "r"(b[0]), "r"(b[1]));
}
__device__ __forceinline__ uint32_t pack_h16x2(float v0, float v1) {
    __half2 h = __floats2half2_rn(v0, v1);
    uint32_t r;
    memcpy(&r, &h, 4);
    return r;
}
#define CP_ASYNC16(s, g) \
    asm volatile("cp.async.cg.shared.global [%0], [%1], 16;" :: "r"(s), "l"(g))

// ---------------- fused conversion kernel (x + all weights) -----------------
#define WQ4 (DMODEL*DMODEL/4)
#define WK4 (KVD*DMODEL/4)
#define WC4 (WQ4 + 2*WK4)
#define X4  (BS*DMODEL/4)
__global__ __launch_bounds__(256) void convert_all(const float4* __restrict__ x,
                                                   const float4* __restrict__ wq,
                                                   const float4* __restrict__ wk,
                                                   const float4* __restrict__ wv,
                                                   const float4* __restrict__ wp,
                                                   __half2* __restrict__ xh,
                                                   __half2* __restrict__ ch,
                                                   __half2* __restrict__ ph) {
    int i = blockIdx.x * blockDim.x + threadIdx.x;
    float4 v;
    __half2* dst;
    size_t o;
    if (i < X4) {
        v = x[i]; dst = xh; o = 2 * (size_t)i;
    } else if (i < X4 + WC4) {
        int j = i - X4;
        if (j < WQ4) v = wq[j];
        else if (j < WQ4 + WK4) v = wk[j - WQ4];
        else v = wv[j - WQ4 - WK4];
        dst = ch; o = 2 * (size_t)j;
    } else if (i < X4 + WC4 + WQ4) {
        int j = i - X4 - WC4;
        v = wp[j]; dst = ph; o = 2 * (size_t)j;
    } else return;
    dst[o + 0] = __floats2half2_rn(v.x, v.y);
    dst[o + 1] = __floats2half2_rn(v.z, v.w);
}

__device__ __forceinline__ uint32_t sw_off(int row, int chunk) {
    return (uint32_t)(row * 64 + ((chunk ^ (row & 3)) << 4));
}

// ------- single-pass fp16 GEMM, 256x128 tile, fragment-pipelined ------------
#define GSTAGES 3
#define GBK 32
#define BA_SZ (256*GBK*2)
#define BB_SZ (128*GBK*2)
#define BSTAGEB (BA_SZ + BB_SZ)
#define BSMEM_TOTAL (GSTAGES*BSTAGEB)

__global__ __launch_bounds__(256, 1) void gemm_f16_1p(
    const __half* __restrict__ Ah, const __half* __restrict__ Bh,
    float* __restrict__ C, int M, int N, int K) {
    extern __shared__ char smem[];
    uint32_t sb = smem_u32(smem);
    int tid = threadIdx.x, wid = tid >> 5, lane = tid & 31;
    int bm = blockIdx.y * 256, bn = blockIdx.x * 128;
    int wm = (wid >> 1) * 64;
    int wn = (wid & 1) * 64;
    const int NK = K / GBK;

    float acc[4][8][4];
#pragma unroll
    for (int a = 0; a < 4; a++)
#pragma unroll
        for (int b = 0; b < 8; b++)
#pragma unroll
            for (int c = 0; c < 4; c++) acc[a][b][c] = 0.f;

    auto load_stage = [&](int kc, uint32_t tb) {
        size_t kcol = (size_t)kc * GBK;
#pragma unroll
        for (int j = 0; j < 4; j++) {
            int idx = tid + j * 256;
            int row = idx >> 2, c = idx & 3;
            CP_ASYNC16(tb + sw_off(row, c), Ah + (size_t)(bm + row) * K + kcol + c * 8);
        }
#pragma unroll
        for (int j = 0; j < 2; j++) {
            int idx = tid + j * 256;
            int row = idx >> 2, c = idx & 3;
            CP_ASYNC16(tb + BA_SZ + sw_off(row, c), Bh + (size_t)(bn + row) * K + kcol + c * 8);
        }
    };

#pragma unroll
    for (int s = 0; s < GSTAGES - 1; s++) {
        load_stage(s, sb + s * BSTAGEB);
        asm volatile("cp.async.commit_group;" ::: "memory");
    }

    int arow = wm + (lane & 15);              // A ldsm row base (per mt add 16*mt)
    int brow = wn + (lane & 7) + ((lane >> 4) << 3);
    int acol = (lane >> 4);
    int bcol = ((lane >> 3) & 1);

    for (int kc = 0; kc < NK; kc++) {
        asm volatile("cp.async.wait_group %0;" :: "n"(GSTAGES - 2) : "memory");
        __syncthreads();
        uint32_t tb = sb + (kc % GSTAGES) * BSTAGEB;

        // issue ALL B fragment loads for both ks up front (8 independent LDSM)
        uint32_t bh[2][4][4];
#pragma unroll
        for (int ks = 0; ks < 2; ks++)
#pragma unroll
            for (int pr = 0; pr < 4; pr++)
                ldsm_x4(bh[ks][pr], tb + BA_SZ + sw_off(brow + pr * 16, ks * 2 + bcol));

        // A fragments double-buffered: prefetch next during current MMAs
        uint32_t ah[2][4];
        ldsm_x4(ah[0], tb + sw_off(arow, acol));
#pragma unroll
        for (int it = 0; it < 8; it++) {
            int ks = it >> 2, mt = it & 3;
            int cur = it & 1;
            if (it < 7) {
                int it2 = it + 1;
                ldsm_x4(ah[cur ^ 1], tb + sw_off(arow + (it2 & 3) * 16, (it2 >> 2) * 2 + acol));
            }
#pragma unroll
            for (int nt = 0; nt < 8; nt++)
                mma_f16(acc[mt][nt], ah[cur], &bh[ks][nt >> 1][(nt & 1) * 2]);
        }

        if (kc + GSTAGES - 1 < NK) {
            int pst = (kc + GSTAGES - 1) % GSTAGES;
            load_stage(kc + GSTAGES - 1, sb + pst * BSTAGEB);
        }
        asm volatile("cp.async.commit_group;" ::: "memory");
    }

#pragma unroll
    for (int mt = 0; mt < 4; mt++) {
        int row0 = bm + wm + mt * 16 + (lane >> 2);
#pragma unroll
        for (int nt = 0; nt < 8; nt++) {
            int col = bn + wn + nt * 8 + (lane & 3) * 2;
            *(float2*)(C + (size_t)row0 * N + col) = make_float2(acc[mt][nt][0], acc[mt][nt][1]);
            *(float2*)(C + (size_t)(row0 + 8) * N + col) = make_float2(acc[mt][nt][2], acc[mt][nt][3]);
        }
    }
}

// ---------------- RoPE table ------------------------------------------------
__global__ void rope_table_kernel() {
    int i = threadIdx.x;
    int t = blockIdx.x;
    double inv = exp(-((double)(2 * i) / 128.0) * log(10000.0));
    double a = (double)t * inv;
    g_cos[t * 64 + i] = (float)cos(a);
    g_sin[t * 64 + i] = (float)sin(a);
}

// --------- fused RMSNorm+RoPE for Q/K + fp16 convert for V ------------------
__global__ __launch_bounds__(128) void rmsnorm_rope_qkv(const float* __restrict__ src,
                                                        __half* __restrict__ q16,
                                                        __half* __restrict__ k16,
                                                        __half* __restrict__ v16,
                                                        const float* __restrict__ gain) {
    int token = blockIdx.x;
    int hh = blockIdx.y;
    int d = threadIdx.x;

    if (hh >= NH + NKV) {
        int vh_ = hh - NH - NKV;
        float v = src[(size_t)token * NQKV + DMODEL + KVD + vh_ * HD + d];
        v16[((size_t)token * NKV + vh_) * HD + d] = __float2half_rn(v);
        return;
    }

    int s = token & (SEQ - 1);
    bool isQ = hh < NH;
    int coloff = isQ ? hh * HD : DMODEL + (hh - NH) * HD;
    float v = src[(size_t)token * NQKV + coloff + d];

    float ss = v * v;
#pragma unroll
    for (int o = 16; o; o >>= 1) ss += __shfl_xor_sync(0xffffffffu, ss, o);
    __shared__ float ws[4];
    int lane = d & 31, w = d >> 5;
    if (lane == 0) ws[w] = ss;
    __syncthreads();
    float tot = ws[0] + ws[1] + ws[2] + ws[3];
    float inv = rsqrtf(tot * (1.0f / HD) + 1.1920928955078125e-7f);
    v *= inv;

    __shared__ float sv[HD];
    sv[d] = v;
    __syncthreads();

    float out;
    if (d < 64) {
        float c = g_cos[s * 64 + d], si = g_sin[s * 64 + d];
        out = v * c + sv[d + 64] * si;
    } else {
        int i = d - 64;
        float c = g_cos[s * 64 + i], si = g_sin[s * 64 + i];
        out = -sv[i] * si + v * c;
    }
    if (isQ) {
        out *= gain[hh] * 0.08838834764831845f;
        q16[((size_t)token * NH + hh) * HD + d] = __float2half_rn(out);
    } else {
        k16[((size_t)token * NKV + (hh - NH)) * HD + d] = __float2half_rn(out);
    }
}

// ------ tensor-core flash attention (causal, GQA, single-pass fp16) ---------
#define FBQ 128
#define FBK 64
#define F_Q 0
#define F_STAGE0 32768
#define F_STAGEB 32768
#define F_K 0
#define F_V 16384
#define FSMEM_TOTAL (32768 + 2*F_STAGEB)

__device__ __forceinline__ uint32_t f_off(int row, int chunk) {
    return (uint32_t)(row * 256 + ((chunk ^ (row & 7)) << 4));
}

__device__ __forceinline__ void f_load_kv(uint32_t st,
                                          const __half* k16, const __half* v16,
                                          size_t gbase, int tid) {
#pragma unroll
    for (int j = 0; j < 4; j++) {
        int id = tid + j * 256;
        int row = id >> 4, c = id & 15;
        uint32_t so = f_off(row, c);
        size_t g = gbase + (size_t)row * KVD + c * 8;
        CP_ASYNC16(st + F_K + so, k16 + g);
        CP_ASYNC16(st + F_V + so, v16 + g);
    }
}

__global__ __launch_bounds__(256, 1) void flash_mma(
    const __half* __restrict__ q16,
    const __half* __restrict__ k16, const __half* __restrict__ v16,
    __half* __restrict__ yh) {
    extern __shared__ char smem[];
    uint32_t sb = smem_u32(smem);
    int tid = threadIdx.x, lane = tid & 31, w = tid >> 5;
    int bh_ = blockIdx.y;
    int b = bh_ >> 4, h = bh_ & 15, hkv = h >> 2;
    int qb = (gridDim.x - 1 - blockIdx.x) * FBQ;
    int q0 = w * 16;

#pragma unroll
    for (int j = 0; j < 8; j++) {
        int id = tid + j * 256;
        int row = id >> 4, c = id & 15;
        uint32_t so = f_off(row, c);
        size_t g = ((size_t)(b * SEQ + qb + row)) * DMODEL + h * HD + c * 8;
        CP_ASYNC16(sb + F_Q + so, q16 + g);
    }
    asm volatile("cp.async.commit_group;" ::: "memory");

    size_t kvhead = (size_t)(b * SEQ) * KVD + hkv * HD;
    int ntiles = qb / FBK + 2;

    f_load_kv(sb + F_STAGE0, k16, v16, kvhead, tid);
    asm volatile("cp.async.commit_group;" ::: "memory");

    asm volatile("cp.async.wait_group 1;" ::: "memory");
    __syncthreads();
    uint32_t qf[8][4];
#pragma unroll
    for (int ds = 0; ds < 8; ds++) {
        uint32_t qoff = f_off(q0 + (lane & 15), ds * 2 + (lane >> 4));
        ldsm_x4(qf[ds], sb + F_Q + qoff);
    }

    float o[16][4];
#pragma unroll
    for (int nt = 0; nt < 16; nt++)
#pragma unroll
        for (int e = 0; e < 4; e++) o[nt][e] = 0.f;
    float m0 = -1e30f, m1 = -1e30f, l0 = 0.f, l1 = 0.f;

    int qmax = qb + q0 + 15;
    int rr0 = qb + q0 + (lane >> 2);
    int rr1 = rr0 + 8;

    for (int t = 0; t < ntiles; t++) {
        if (t + 1 < ntiles)
            f_load_kv(sb + F_STAGE0 + ((t + 1) & 1) * F_STAGEB, k16, v16,
                      kvhead + (size_t)(t + 1) * FBK * KVD, tid);
        asm volatile("cp.async.commit_group;" ::: "memory");
        asm volatile("cp.async.wait_group 1;" ::: "memory");
        __syncthreads();

        int kv = t * FBK;
        if (kv <= qmax) {
            uint32_t st = sb + F_STAGE0 + (t & 1) * F_STAGEB;

            float c[8][4];
#pragma unroll
            for (int nt = 0; nt < 8; nt++)
#pragma unroll
                for (int e = 0; e < 4; e++) c[nt][e] = 0.f;

#pragma unroll
            for (int ds = 0; ds < 8; ds++) {
                uint32_t bh4[4][4];
#pragma unroll
                for (int g = 0; g < 4; g++) {
                    int rowk = g * 16 + (lane & 7) + ((lane >> 4) << 3);
                    uint32_t koff = f_off(rowk, ds * 2 + ((lane >> 3) & 1));
                    ldsm_x4(bh4[g], st + F_K + koff);
                }
#pragma unroll
                for (int g = 0; g < 4; g++)
#pragma unroll
                    for (int sub = 0; sub < 2; sub++)
                        mma_f16(c[g * 2 + sub], qf[ds], &bh4[g][sub * 2]);
            }

            if (kv + FBK - 1 > qb + q0) {
#pragma unroll
                for (int nt = 0; nt < 8; nt++) {
                    int col = kv + nt * 8 + (lane & 3) * 2;
                    if (col > rr0) c[nt][0] = -1e30f;
                    if (col + 1 > rr0) c[nt][1] = -1e30f;
                    if (col > rr1) c[nt][2] = -1e30f;
                    if (col + 1 > rr1) c[nt][3] = -1e30f;
                }
            }

            float mx0 = -1e30f, mx1 = -1e30f;
#pragma unroll
            for (int nt = 0; nt < 8; nt++) {
                mx0 = fmaxf(mx0, fmaxf(c[nt][0], c[nt][1]));
                mx1 = fmaxf(mx1, fmaxf(c[nt][2], c[nt][3]));
            }
            mx0 = fmaxf(mx0, __shfl_xor_sync(0xffffffffu, mx0, 1));
            mx0 = fmaxf(mx0, __shfl_xor_sync(0xffffffffu, mx0, 2));
            mx1 = fmaxf(mx1, __shfl_xor_sync(0xffffffffu, mx1, 1));
            mx1 = fmaxf(mx1, __shfl_xor_sync(0xffffffffu, mx1, 2));
            float m0n = fmaxf(m0, mx0), m1n = fmaxf(m1, mx1);
            float rs0 = exp2f((m0 - m0n) * LOG2E);
            float rs1 = exp2f((m1 - m1n) * LOG2E);
            float s0 = 0.f, s1 = 0.f;
#pragma unroll
            for (int nt = 0; nt < 8; nt++) {
                c[nt][0] = exp2f((c[nt][0] - m0n) * LOG2E);
                c[nt][1] = exp2f((c[nt][1] - m0n) * LOG2E);
                c[nt][2] = exp2f((c[nt][2] - m1n) * LOG2E);
                c[nt][3] = exp2f((c[nt][3] - m1n) * LOG2E);
                s0 += c[nt][0] + c[nt][1];
                s1 += c[nt][2] + c[nt][3];
            }
            s0 += __shfl_xor_sync(0xffffffffu, s0, 1);
            s0 += __shfl_xor_sync(0xffffffffu, s0, 2);
            s1 += __shfl_xor_sync(0xffffffffu, s1, 1);
            s1 += __shfl_xor_sync(0xffffffffu, s1, 2);
            l0 = l0 * rs0 + s0;
            l1 = l1 * rs1 + s1;
            m0 = m0n; m1 = m1n;
#pragma unroll
            for (int nt = 0; nt < 16; nt++) {
                o[nt][0] *= rs0; o[nt][1] *= rs0;
                o[nt][2] *= rs1; o[nt][3] *= rs1;
            }

#pragma unroll
            for (int kt = 0; kt < 4; kt++) {
                uint32_t ap[4];
#pragma unroll
                for (int half = 0; half < 2; half++) {
                    const float* cc = c[2 * kt + half];
                    ap[half * 2 + 0] = pack_h16x2(cc[0], cc[1]);
                    ap[half * 2 + 1] = pack_h16x2(cc[2], cc[3]);
                }
#pragma unroll
                for (int g = 0; g < 8; g++) {
                    int rowv = kt * 16 + (lane & 15);
                    uint32_t voff = f_off(rowv, g * 2 + (lane >> 4));
                    uint32_t vh4[4];
                    ldsm_x4_t(vh4, st + F_V + voff);
                    mma_f16(o[2 * g], ap, &vh4[0]);
                    mma_f16(o[2 * g + 1], ap, &vh4[2]);
                }
            }
        }
        __syncthreads();
    }

    float iv0 = 1.f / l0, iv1 = 1.f / l1;
    size_t base0 = ((size_t)(b * SEQ) + rr0) * DMODEL + h * HD;
    size_t base1 = base0 + (size_t)8 * DMODEL;
#pragma unroll
    for (int nt = 0; nt < 16; nt++) {
        int d = nt * 8 + (lane & 3) * 2;
        __half2 h0 = __floats2half2_rn(o[nt][0] * iv0, o[nt][1] * iv0);
        __half2 h1 = __floats2half2_rn(o[nt][2] * iv1, o[nt][3] * iv1);
        *(__half2*)(yh + base0 + d) = h0;
        *(__half2*)(yh + base1 + d) = h1;
    }
}

// ---------------------------------------------------------------------------
extern "C" void kernel_launch(void* const* d_in, const int* in_sizes, int n_in,
                              void* d_out, int out_size) {
    const float* x     = (const float*)d_in[0];
    const float* Wq    = (const float*)d_in[1];
    const float* Wk    = (const float*)d_in[2];
    const float* Wv    = (const float*)d_in[3];
    const float* Wproj = (const float*)d_in[4];
    const float* qgain = (const float*)d_in[5];

    float* qkv;
    cudaGetSymbolAddress((void**)&qkv, g_qkv);
    __half *xh, *yh, *wch, *wph, *q16, *k16, *v16;
    cudaGetSymbolAddress((void**)&xh, g_xh);
    cudaGetSymbolAddress((void**)&yh, g_yh);
    cudaGetSymbolAddress((void**)&wch, g_wch);
    cudaGetSymbolAddress((void**)&wph, g_wph);
    cudaGetSymbolAddress((void**)&q16, g_q16);
    cudaGetSymbolAddress((void**)&k16, g_k16);
    cudaGetSymbolAddress((void**)&v16, g_v16);

    cudaFuncSetAttribute(gemm_f16_1p, cudaFuncAttributeMaxDynamicSharedMemorySize, BSMEM_TOTAL);
    cudaFuncSetAttribute(flash_mma, cudaFuncAttributeMaxDynamicSharedMemorySize, FSMEM_TOTAL);

    rope_table_kernel<<<SEQ, 64>>>();

    {
        int n = X4 + WC4 + WQ4;
        convert_all<<<(n + 255) / 256, 256>>>((const float4*)x,
                                              (const float4*)Wq, (const float4*)Wk,
                                              (const float4*)Wv, (const float4*)Wproj,
                                              (__half2*)xh, (__half2*)wch, (__half2*)wph);
    }

    gemm_f16_1p<<<dim3(NQKV / 128, BS / 256), 256, BSMEM_TOTAL>>>(
        xh, wch, qkv, BS, NQKV, DMODEL);

    rmsnorm_rope_qkv<<<dim3(BS, NH + 2 * NKV), HD>>>(qkv, q16, k16, v16, qgain);

    flash_mma<<<dim3(SEQ / FBQ, BATCH * NH), 256, FSMEM_TOTAL>>>(q16, k16, v16, yh);

    gemm_f16_1p<<<dim3(DMODEL / 128, BS / 256), 256, BSMEM_TOTAL>>>(
        yh, wph, (float*)d_out, BS, DMODEL, DMODEL);
}